// round 1
// baseline (speedup 1.0000x reference)
#include <cuda_runtime.h>
#include <math.h>

// ---------------- problem constants ----------------
#define T_TOK 4096      // B*S tokens
#define HID   2048
#define SEQ   1024
#define BATCH 4
#define NHEAD 32
#define NKVH  4
#define HDIM  128
#define NEXP  32
#define TOPK  8
#define EI    768       // expert intermediate
#define SI    4096      // shared-expert intermediate
#define GQA   8         // NHEAD / NKVH
#define EPSV  1e-6f

// ---------------- scratch (device globals; no allocation allowed) ----------------
__device__ float g_xn [T_TOK*HID];            // rmsnorm output (x, then x2)
__device__ float g_q  [T_TOK*NHEAD*HDIM];     // q; reused as shared-expert intermediate
__device__ float g_k  [T_TOK*NKVH*HDIM];
__device__ float g_v  [T_TOK*NKVH*HDIM];
__device__ float g_att[T_TOK*NHEAD*HDIM];     // attention output
__device__ float g_h  [T_TOK*HID];            // post-attention residual
__device__ float g_act[T_TOK*TOPK*EI];        // expert gate -> activated
__device__ float g_down[T_TOK*TOPK*HID];      // per-pair expert down output
__device__ float g_cos[SEQ*(HDIM/2)];
__device__ float g_sin[SEQ*(HDIM/2)];
__device__ int   g_topi[T_TOK*TOPK];
__device__ float g_topw[T_TOK*TOPK];
__device__ int   g_cnt[NEXP];
__device__ int   g_off[NEXP+1];
__device__ int   g_cur[NEXP];
__device__ int   g_ptok[T_TOK*TOPK];          // expert-sorted pair -> token
__device__ int   g_ppos[T_TOK*TOPK];          // (token,k) -> pair position
__device__ float g_sig[T_TOK];                // shared-expert sigmoid gate

// ---------------- rmsnorm over HID ----------------
__global__ void rmsnorm_k(const float* __restrict__ x, const float* __restrict__ w,
                          float* __restrict__ y)
{
    int row = blockIdx.x;
    const float* xr = x + (long)row*HID;
    float ss = 0.f;
    for (int i = threadIdx.x; i < HID; i += blockDim.x) { float v = xr[i]; ss += v*v; }
    __shared__ float red[32];
    for (int o = 16; o > 0; o >>= 1) ss += __shfl_xor_sync(0xffffffffu, ss, o);
    int warp = threadIdx.x >> 5, lane = threadIdx.x & 31;
    if (lane == 0) red[warp] = ss;
    __syncthreads();
    if (warp == 0) {
        ss = (lane < (blockDim.x >> 5)) ? red[lane] : 0.f;
        for (int o = 16; o > 0; o >>= 1) ss += __shfl_xor_sync(0xffffffffu, ss, o);
        if (lane == 0) red[0] = ss;
    }
    __syncthreads();
    float r = rsqrtf(red[0] / (float)HID + EPSV);
    float* yr = y + (long)row*HID;
    for (int i = threadIdx.x; i < HID; i += blockDim.x) yr[i] = xr[i] * r * w[i];
}

// ---------------- rope tables ----------------
__global__ void rope_tab_k(float* __restrict__ cosT, float* __restrict__ sinT)
{
    int s = blockIdx.x;
    int i = threadIdx.x;                         // 0..63
    float inv = expf(-((float)(2*i) / (float)HDIM) * logf(1000000.0f));
    float ang = (float)s * inv;
    cosT[s*(HDIM/2)+i] = cosf(ang);
    sinT[s*(HDIM/2)+i] = sinf(ang);
}

// ---------------- per-head rmsnorm + NeoX rope (in place) ----------------
__global__ void qknr_k(float* __restrict__ x, const float* __restrict__ nw, int nh,
                       const float* __restrict__ cosT, const float* __restrict__ sinT)
{
    long bh = blockIdx.x;              // token*nh + head
    int t = (int)(bh / nh);
    int s = t & (SEQ-1);
    int d = threadIdx.x;               // 0..127
    float* xp = x + bh*HDIM;
    float v = xp[d];
    float ss = v*v;
    for (int o = 16; o > 0; o >>= 1) ss += __shfl_xor_sync(0xffffffffu, ss, o);
    __shared__ float red[4];
    if ((threadIdx.x & 31) == 0) red[threadIdx.x >> 5] = ss;
    __syncthreads();
    float tot = red[0]+red[1]+red[2]+red[3];
    float r = rsqrtf(tot / (float)HDIM + EPSV);
    float xn = v * r * nw[d];
    __shared__ float xsh[HDIM];
    xsh[d] = xn;
    __syncthreads();
    float c, sn, oth;
    if (d < HDIM/2) { c = cosT[s*(HDIM/2)+d];          sn = sinT[s*(HDIM/2)+d];          oth = -xsh[d+HDIM/2]; }
    else            { c = cosT[s*(HDIM/2)+d-HDIM/2];   sn = sinT[s*(HDIM/2)+d-HDIM/2];   oth =  xsh[d-HDIM/2]; }
    xp[d] = xn*c + oth*sn;
}

// ---------------- flash attention (GQA, causal, fp32) ----------------
// dynamic smem: Qs[64][132] + KT[128][68](/Vs[64][132] union) + Ss[64][65] + stats
#define FLASH_SMEM_BYTES ((64*132 + 128*68 + 64*65 + 3*64) * 4)

__global__ void flash_k(const float* __restrict__ qg, const float* __restrict__ kg,
                        const float* __restrict__ vg, float* __restrict__ og)
{
    extern __shared__ float fsh[];
    float* Qs = fsh;                 // [64][132]
    float* KT = Qs + 64*132;         // [128][68]  (K^T), reused as Vs [64][132]
    float* Vs = KT;
    float* Ss = KT + 128*68;         // [64][65]
    float* ms = Ss + 64*65;
    float* ls = ms + 64;
    float* cs = ls + 64;

    int qt = blockIdx.x, h = blockIdx.y, b = blockIdx.z;
    int kvh = h / GQA;
    int qs0 = qt*64;
    int tid = threadIdx.x;
    float scale = rsqrtf((float)HDIM);

    for (int t = tid; t < 64*HDIM; t += 256) {
        int r = t >> 7, d = t & 127;
        Qs[r*132+d] = qg[((long)(b*SEQ + qs0 + r)*NHEAD + h)*HDIM + d] * scale;
    }
    if (tid < 64) { ms[tid] = -1e30f; ls[tid] = 0.f; }

    int ty = tid >> 4, tx = tid & 15;
    float oacc[4][8];
#pragma unroll
    for (int i = 0; i < 4; i++)
#pragma unroll
        for (int j = 0; j < 8; j++) oacc[i][j] = 0.f;
    __syncthreads();

    for (int jt = 0; jt <= qt; jt++) {
        int ks0 = jt*64;
        for (int t = tid; t < 64*HDIM; t += 256) {
            int r = t >> 7, d = t & 127;
            KT[d*68+r] = kg[((long)(b*SEQ + ks0 + r)*NKVH + kvh)*HDIM + d];
        }
        __syncthreads();

        float sreg[4][4];
#pragma unroll
        for (int i = 0; i < 4; i++)
#pragma unroll
            for (int j = 0; j < 4; j++) sreg[i][j] = 0.f;

        for (int d = 0; d < HDIM; d++) {
            float qv[4], kv[4];
#pragma unroll
            for (int i = 0; i < 4; i++) qv[i] = Qs[(ty*4+i)*132 + d];
#pragma unroll
            for (int j = 0; j < 4; j++) kv[j] = KT[d*68 + tx*4 + j];
#pragma unroll
            for (int i = 0; i < 4; i++)
#pragma unroll
                for (int j = 0; j < 4; j++) sreg[i][j] += qv[i]*kv[j];
        }
#pragma unroll
        for (int i = 0; i < 4; i++) {
            int si = ty*4+i;
#pragma unroll
            for (int j = 0; j < 4; j++) {
                int sj = tx*4+j;
                float sv = sreg[i][j];
                if (jt == qt && sj > si) sv = -1e30f;   // causal mask on diagonal tile
                Ss[si*65+sj] = sv;
            }
        }
        __syncthreads();

        if (tid < 64) {
            float mo = ms[tid];
            float mx = mo;
            for (int j = 0; j < 64; j++) mx = fmaxf(mx, Ss[tid*65+j]);
            float c = expf(mo - mx);
            float ps = 0.f;
            for (int j = 0; j < 64; j++) {
                float p = expf(Ss[tid*65+j] - mx);
                Ss[tid*65+j] = p;
                ps += p;
            }
            ls[tid] = ls[tid]*c + ps;
            ms[tid] = mx;
            cs[tid] = c;
        }
        __syncthreads();

#pragma unroll
        for (int i = 0; i < 4; i++) {
            float c = cs[ty*4+i];
#pragma unroll
            for (int j = 0; j < 8; j++) oacc[i][j] *= c;
        }
        // load V into the union buffer (K reads completed before prior sync)
        for (int t = tid; t < 64*HDIM; t += 256) {
            int r = t >> 7, d = t & 127;
            Vs[r*132+d] = vg[((long)(b*SEQ + ks0 + r)*NKVH + kvh)*HDIM + d];
        }
        __syncthreads();

        for (int j = 0; j < 64; j++) {
            float pv[4];
#pragma unroll
            for (int i = 0; i < 4; i++) pv[i] = Ss[(ty*4+i)*65 + j];
            float vr[8];
#pragma unroll
            for (int c2 = 0; c2 < 8; c2++) vr[c2] = Vs[j*132 + tx*4 + (c2&3) + (c2>>2)*64];
#pragma unroll
            for (int i = 0; i < 4; i++)
#pragma unroll
                for (int c2 = 0; c2 < 8; c2++) oacc[i][c2] += pv[i]*vr[c2];
        }
        __syncthreads();
    }

#pragma unroll
    for (int i = 0; i < 4; i++) {
        int r = ty*4+i;
        float inv = 1.f / ls[r];
#pragma unroll
        for (int c2 = 0; c2 < 8; c2++) {
            int col = tx*4 + (c2&3) + (c2>>2)*64;
            og[((long)(b*SEQ + qs0 + r)*NHEAD + h)*HDIM + col] = oacc[i][c2]*inv;
        }
    }
}

// ---------------- generic 128x128x8 SGEMM ----------------
// EPI: 0=store, 1=resid add (extra=resid), 2=in-place silu(C)*acc, 3=rowscale-add (extra=scale[row])
// AIDX:   A rows indirected through aidx[rbase+row]
// EXPERT: blockIdx.z = expert; row range from offs[]; B += e*strideB; C rows are pair rows
#define BM 128
#define BN 128
#define BKK 8

template<int EPI, bool AIDX, bool EXPERT>
__global__ void __launch_bounds__(256)
sgemm_k(int M, int N, int Kd,
        const float* __restrict__ A, int lda,
        const float* __restrict__ B, int ldb, long strideB,
        float* __restrict__ C, int ldc,
        const int* __restrict__ offs,
        const int* __restrict__ aidx,
        const float* __restrict__ extra)
{
    __shared__ float As[BKK][BM];
    __shared__ float Bs[BKK][BN];

    int rbase = 0, mrows = M;
    const float* Bp = B;
    if (EXPERT) {
        int e = blockIdx.z;
        rbase = offs[e];
        mrows = offs[e+1] - rbase;
        Bp = B + (long)e * strideB;
    }
    int bm0 = blockIdx.y * BM;
    if (bm0 >= mrows) return;
    int bn0 = blockIdx.x * BN;          // N is always a multiple of 128 here

    int tid = threadIdx.x;
    int aRow = tid >> 1, aCol = (tid & 1) * 4;
    int bRow = tid >> 5, bCol = (tid & 31) * 4;

    const float* Arow = nullptr;
    {
        int lr = bm0 + aRow;
        if (lr < mrows) {
            long grow = AIDX ? (long)aidx[rbase + lr] : (long)(rbase + lr);
            Arow = A + grow * (long)lda;
        }
    }

    int tx = tid & 15, ty = tid >> 4;
    int rowoff[8], coloff[8];
#pragma unroll
    for (int i = 0; i < 8; i++) rowoff[i] = ty*4 + (i&3) + (i>>2)*64;
#pragma unroll
    for (int j = 0; j < 8; j++) coloff[j] = tx*4 + (j&3) + (j>>2)*64;

    float acc[8][8];
#pragma unroll
    for (int i = 0; i < 8; i++)
#pragma unroll
        for (int j = 0; j < 8; j++) acc[i][j] = 0.f;

    for (int k0 = 0; k0 < Kd; k0 += BKK) {
        if (Arow) {
            float4 av = *reinterpret_cast<const float4*>(Arow + k0 + aCol);
            As[aCol+0][aRow] = av.x; As[aCol+1][aRow] = av.y;
            As[aCol+2][aRow] = av.z; As[aCol+3][aRow] = av.w;
        } else {
            As[aCol+0][aRow] = 0.f; As[aCol+1][aRow] = 0.f;
            As[aCol+2][aRow] = 0.f; As[aCol+3][aRow] = 0.f;
        }
        {
            float4 bv = *reinterpret_cast<const float4*>(Bp + (long)(k0 + bRow)*ldb + bn0 + bCol);
            Bs[bRow][bCol+0] = bv.x; Bs[bRow][bCol+1] = bv.y;
            Bs[bRow][bCol+2] = bv.z; Bs[bRow][bCol+3] = bv.w;
        }
        __syncthreads();
#pragma unroll
        for (int k = 0; k < BKK; k++) {
            float ra[8], rb[8];
#pragma unroll
            for (int i = 0; i < 8; i++) ra[i] = As[k][rowoff[i]];
#pragma unroll
            for (int j = 0; j < 8; j++) rb[j] = Bs[k][coloff[j]];
#pragma unroll
            for (int i = 0; i < 8; i++)
#pragma unroll
                for (int j = 0; j < 8; j++) acc[i][j] += ra[i]*rb[j];
        }
        __syncthreads();
    }

#pragma unroll
    for (int i = 0; i < 8; i++) {
        int r = bm0 + rowoff[i];
        if (r >= mrows) continue;
        long cr = (long)(rbase + r);
#pragma unroll
        for (int j = 0; j < 8; j++) {
            int c = bn0 + coloff[j];
            float v = acc[i][j];
            if (EPI == 0) {
                C[cr*ldc + c] = v;
            } else if (EPI == 1) {
                C[cr*ldc + c] = extra[cr*ldc + c] + v;
            } else if (EPI == 2) {
                float g = C[cr*ldc + c];
                C[cr*ldc + c] = g / (1.f + expf(-g)) * v;   // silu(gate)*up
            } else if (EPI == 3) {
                C[cr*ldc + c] += v * extra[r];
            }
        }
    }
}

// ---------------- router: logits, softmax, top-8, renorm ----------------
__global__ void router_k(const float* __restrict__ x2, const float* __restrict__ Wr,
                         int* __restrict__ topi, float* __restrict__ topw)
{
    int t = blockIdx.x;
    __shared__ float xs[HID];
    __shared__ float pr[NEXP];
    for (int i = threadIdx.x; i < HID; i += blockDim.x) xs[i] = x2[(long)t*HID + i];
    __syncthreads();
    if (threadIdx.x < NEXP) {
        int e = threadIdx.x;
        float d = 0.f;
        for (int i = 0; i < HID; i++) d += xs[i] * Wr[i*NEXP + e];
        pr[e] = d;
    }
    __syncthreads();
    if (threadIdx.x == 0) {
        float mx = -1e30f;
        for (int e = 0; e < NEXP; e++) mx = fmaxf(mx, pr[e]);
        float p[NEXP]; float sm = 0.f;
        for (int e = 0; e < NEXP; e++) { p[e] = expf(pr[e]-mx); sm += p[e]; }
        for (int e = 0; e < NEXP; e++) p[e] /= sm;
        float tw = 0.f;
        int   idx[TOPK]; float val[TOPK];
        for (int kk = 0; kk < TOPK; kk++) {
            int bi = 0; float bv = -1.f;
            for (int e = 0; e < NEXP; e++) if (p[e] > bv) { bv = p[e]; bi = e; }
            idx[kk] = bi; val[kk] = bv; p[bi] = -2.f; tw += bv;
        }
        for (int kk = 0; kk < TOPK; kk++) {
            topi[t*TOPK+kk] = idx[kk];
            topw[t*TOPK+kk] = val[kk] / tw;
        }
    }
}

// ---------------- routing build ----------------
__global__ void zero32_k(int* cnt) { if (threadIdx.x < NEXP) cnt[threadIdx.x] = 0; }
__global__ void count_k(const int* __restrict__ topi, int* __restrict__ cnt)
{
    int i = blockIdx.x*256 + threadIdx.x;
    if (i < T_TOK*TOPK) atomicAdd(&cnt[topi[i]], 1);
}
__global__ void scan_k(const int* __restrict__ cnt, int* __restrict__ off, int* __restrict__ cur)
{
    if (threadIdx.x == 0) {
        int a = 0;
        for (int e = 0; e < NEXP; e++) { off[e] = a; cur[e] = a; a += cnt[e]; }
        off[NEXP] = a;
    }
}
__global__ void fill_k(const int* __restrict__ topi, int* __restrict__ cur,
                       int* __restrict__ ptok, int* __restrict__ ppos)
{
    int i = blockIdx.x*256 + threadIdx.x;
    if (i < T_TOK*TOPK) {
        int e = topi[i];
        int p = atomicAdd(&cur[e], 1);
        ptok[p] = i / TOPK;
        ppos[i] = p;
    }
}

// ---------------- deterministic per-token MoE reduction: out = h + sum_k w_k * down_k ----------------
__global__ void moe_reduce_k(const float* __restrict__ down, const int* __restrict__ ppos,
                             const float* __restrict__ topw, const float* __restrict__ h,
                             float* __restrict__ out)
{
    int t = blockIdx.x;
    int pos[TOPK]; float w[TOPK];
#pragma unroll
    for (int kk = 0; kk < TOPK; kk++) { pos[kk] = ppos[t*TOPK+kk]; w[kk] = topw[t*TOPK+kk]; }
    for (int c = threadIdx.x; c < HID; c += blockDim.x) {
        float s = h[(long)t*HID + c];
#pragma unroll
        for (int kk = 0; kk < TOPK; kk++) s += down[(long)pos[kk]*HID + c] * w[kk];
        out[(long)t*HID + c] = s;
    }
}

// ---------------- shared-expert sigmoid gate ----------------
__global__ void shgate_k(const float* __restrict__ x2, const float* __restrict__ w,
                         float* __restrict__ sig)
{
    int t = blockIdx.x;
    float s = 0.f;
    for (int i = threadIdx.x; i < HID; i += blockDim.x) s += x2[(long)t*HID + i] * w[i];
    __shared__ float red[32];
    for (int o = 16; o > 0; o >>= 1) s += __shfl_xor_sync(0xffffffffu, s, o);
    int warp = threadIdx.x >> 5, lane = threadIdx.x & 31;
    if (lane == 0) red[warp] = s;
    __syncthreads();
    if (warp == 0) {
        s = (lane < (blockDim.x >> 5)) ? red[lane] : 0.f;
        for (int o = 16; o > 0; o >>= 1) s += __shfl_xor_sync(0xffffffffu, s, o);
        if (lane == 0) sig[t] = 1.f / (1.f + expf(-s));
    }
}

// ---------------- host launch ----------------
extern "C" void kernel_launch(void* const* d_in, const int* in_sizes, int n_in,
                              void* d_out, int out_size)
{
    (void)in_sizes; (void)out_size;
    if (n_in < 17) return;
    const float* hidden = (const float*)d_in[0];
    const float* ln1    = (const float*)d_in[1];
    const float* ln2    = (const float*)d_in[2];
    const float* qnw    = (const float*)d_in[3];
    const float* knw    = (const float*)d_in[4];
    const float* Wq     = (const float*)d_in[5];
    const float* Wk     = (const float*)d_in[6];
    const float* Wv     = (const float*)d_in[7];
    const float* Wo     = (const float*)d_in[8];
    const float* Wr     = (const float*)d_in[9];
    const float* Weg    = (const float*)d_in[10];
    const float* Weu    = (const float*)d_in[11];
    const float* Wed    = (const float*)d_in[12];
    const float* Wsg    = (const float*)d_in[13];
    const float* Wsu    = (const float*)d_in[14];
    const float* Wsd    = (const float*)d_in[15];
    const float* Wshg   = (const float*)d_in[16];
    float* out = (float*)d_out;

    float *xn, *qb, *kb, *vb, *att, *hb, *act, *down, *cosT, *sinT, *topw, *sig;
    int *topi, *cnt, *off, *cur, *ptok, *ppos;
    cudaGetSymbolAddress((void**)&xn,   g_xn);
    cudaGetSymbolAddress((void**)&qb,   g_q);
    cudaGetSymbolAddress((void**)&kb,   g_k);
    cudaGetSymbolAddress((void**)&vb,   g_v);
    cudaGetSymbolAddress((void**)&att,  g_att);
    cudaGetSymbolAddress((void**)&hb,   g_h);
    cudaGetSymbolAddress((void**)&act,  g_act);
    cudaGetSymbolAddress((void**)&down, g_down);
    cudaGetSymbolAddress((void**)&cosT, g_cos);
    cudaGetSymbolAddress((void**)&sinT, g_sin);
    cudaGetSymbolAddress((void**)&topi, g_topi);
    cudaGetSymbolAddress((void**)&topw, g_topw);
    cudaGetSymbolAddress((void**)&cnt,  g_cnt);
    cudaGetSymbolAddress((void**)&off,  g_off);
    cudaGetSymbolAddress((void**)&cur,  g_cur);
    cudaGetSymbolAddress((void**)&ptok, g_ptok);
    cudaGetSymbolAddress((void**)&ppos, g_ppos);
    cudaGetSymbolAddress((void**)&sig,  g_sig);

    cudaFuncSetAttribute(flash_k, cudaFuncAttributeMaxDynamicSharedMemorySize, FLASH_SMEM_BYTES);

    dim3 blk(256);

    // --- attention block ---
    rmsnorm_k<<<T_TOK, 256>>>(hidden, ln1, xn);

    sgemm_k<0,false,false><<<dim3(32,32), blk>>>(T_TOK, NHEAD*HDIM, HID, xn, HID, Wq, NHEAD*HDIM, 0, qb, NHEAD*HDIM, nullptr, nullptr, nullptr);
    sgemm_k<0,false,false><<<dim3(4, 32), blk>>>(T_TOK, NKVH*HDIM,  HID, xn, HID, Wk, NKVH*HDIM,  0, kb, NKVH*HDIM,  nullptr, nullptr, nullptr);
    sgemm_k<0,false,false><<<dim3(4, 32), blk>>>(T_TOK, NKVH*HDIM,  HID, xn, HID, Wv, NKVH*HDIM,  0, vb, NKVH*HDIM,  nullptr, nullptr, nullptr);

    rope_tab_k<<<SEQ, HDIM/2>>>(cosT, sinT);
    qknr_k<<<T_TOK*NHEAD, HDIM>>>(qb, qnw, NHEAD, cosT, sinT);
    qknr_k<<<T_TOK*NKVH,  HDIM>>>(kb, knw, NKVH, cosT, sinT);

    flash_k<<<dim3(SEQ/64, NHEAD, BATCH), 256, FLASH_SMEM_BYTES>>>(qb, kb, vb, att);

    // h = hidden + att @ Wo
    sgemm_k<1,false,false><<<dim3(16,32), blk>>>(T_TOK, HID, NHEAD*HDIM, att, NHEAD*HDIM, Wo, HID, 0, hb, HID, nullptr, nullptr, hidden);

    // --- MoE block ---
    rmsnorm_k<<<T_TOK, 256>>>(hb, ln2, xn);

    router_k<<<T_TOK, 128>>>(xn, Wr, topi, topw);
    zero32_k<<<1, 32>>>(cnt);
    count_k<<<(T_TOK*TOPK+255)/256, 256>>>(topi, cnt);
    scan_k<<<1, 32>>>(cnt, off, cur);
    fill_k<<<(T_TOK*TOPK+255)/256, 256>>>(topi, cur, ptok, ppos);

    // gate: act = x2[ptok] @ Weg[e]
    sgemm_k<0,true,true><<<dim3(EI/128, 32, NEXP), blk>>>(0, EI, HID, xn, HID, Weg, EI, (long)HID*EI, act, EI, off, ptok, nullptr);
    // up:   act = silu(act) * (x2[ptok] @ Weu[e])
    sgemm_k<2,true,true><<<dim3(EI/128, 32, NEXP), blk>>>(0, EI, HID, xn, HID, Weu, EI, (long)HID*EI, act, EI, off, ptok, nullptr);
    // down: down = act @ Wed[e]   (per-pair rows)
    sgemm_k<0,false,true><<<dim3(HID/128, 32, NEXP), blk>>>(0, HID, EI, act, EI, Wed, HID, (long)EI*HID, down, HID, off, nullptr, nullptr);

    // out = h + sum_k w_k * down_k   (deterministic)
    moe_reduce_k<<<T_TOK, 256>>>(down, ppos, topw, hb, out);

    // --- shared expert (reuses g_q as [T, SI] intermediate) ---
    sgemm_k<0,false,false><<<dim3(SI/128, 32), blk>>>(T_TOK, SI, HID, xn, HID, Wsg, SI, 0, qb, SI, nullptr, nullptr, nullptr);
    sgemm_k<2,false,false><<<dim3(SI/128, 32), blk>>>(T_TOK, SI, HID, xn, HID, Wsu, SI, 0, qb, SI, nullptr, nullptr, nullptr);
    shgate_k<<<T_TOK, 256>>>(xn, Wshg, sig);
    // out += (shared_act @ Wsd) * sigmoid_gate[row]
    sgemm_k<3,false,false><<<dim3(HID/128, 32), blk>>>(T_TOK, HID, SI, qb, SI, Wsd, HID, 0, out, HID, nullptr, nullptr, sig);
}

// round 4
// speedup vs baseline: 2.0749x; 2.0749x over previous
#include <cuda_runtime.h>
#include <math.h>
#include <stdint.h>

// ---------------- problem constants ----------------
#define T_TOK 4096
#define HID   2048
#define SEQ   1024
#define BATCH 4
#define NHEAD 32
#define NKVH  4
#define HDIM  128
#define NEXP  32
#define TOPK  8
#define EI    768
#define SI    4096
#define GQA   8
#define EPSV  1e-6f

// ---------------- scratch ----------------
__device__ float g_xn [T_TOK*HID];
__device__ float g_q  [T_TOK*NHEAD*HDIM];     // q; reused as shared-expert intermediate
__device__ float g_k  [T_TOK*NKVH*HDIM];
__device__ float g_v  [T_TOK*NKVH*HDIM];
__device__ float g_att[T_TOK*NHEAD*HDIM];
__device__ float g_h  [T_TOK*HID];
__device__ float g_act[T_TOK*TOPK*EI];
__device__ float g_down[T_TOK*TOPK*HID];
__device__ float g_cos[SEQ*(HDIM/2)];
__device__ float g_sin[SEQ*(HDIM/2)];
__device__ int   g_topi[T_TOK*TOPK];
__device__ float g_topw[T_TOK*TOPK];
__device__ int   g_cnt[NEXP];
__device__ int   g_off[NEXP+1];
__device__ int   g_cur[NEXP];
__device__ int   g_ptok[T_TOK*TOPK];
__device__ int   g_ppos[T_TOK*TOPK];
__device__ float g_sig[T_TOK];

// ---------------- rmsnorm over HID ----------------
__global__ void rmsnorm_k(const float* __restrict__ x, const float* __restrict__ w,
                          float* __restrict__ y)
{
    int row = blockIdx.x;
    const float* xr = x + (long)row*HID;
    float ss = 0.f;
    for (int i = threadIdx.x; i < HID; i += blockDim.x) { float v = xr[i]; ss += v*v; }
    __shared__ float red[32];
    for (int o = 16; o > 0; o >>= 1) ss += __shfl_xor_sync(0xffffffffu, ss, o);
    int warp = threadIdx.x >> 5, lane = threadIdx.x & 31;
    if (lane == 0) red[warp] = ss;
    __syncthreads();
    if (warp == 0) {
        ss = (lane < (blockDim.x >> 5)) ? red[lane] : 0.f;
        for (int o = 16; o > 0; o >>= 1) ss += __shfl_xor_sync(0xffffffffu, ss, o);
        if (lane == 0) red[0] = ss;
    }
    __syncthreads();
    float r = rsqrtf(red[0] / (float)HID + EPSV);
    float* yr = y + (long)row*HID;
    for (int i = threadIdx.x; i < HID; i += blockDim.x) yr[i] = xr[i] * r * w[i];
}

// ---------------- rope tables ----------------
__global__ void rope_tab_k(float* __restrict__ cosT, float* __restrict__ sinT)
{
    int s = blockIdx.x;
    int i = threadIdx.x;
    float inv = expf(-((float)(2*i) / (float)HDIM) * logf(1000000.0f));
    float ang = (float)s * inv;
    cosT[s*(HDIM/2)+i] = cosf(ang);
    sinT[s*(HDIM/2)+i] = sinf(ang);
}

// ---------------- per-head rmsnorm + rope ----------------
__global__ void qknr_k(float* __restrict__ x, const float* __restrict__ nw, int nh,
                       const float* __restrict__ cosT, const float* __restrict__ sinT)
{
    long bh = blockIdx.x;
    int t = (int)(bh / nh);
    int s = t & (SEQ-1);
    int d = threadIdx.x;
    float* xp = x + bh*HDIM;
    float v = xp[d];
    float ss = v*v;
    for (int o = 16; o > 0; o >>= 1) ss += __shfl_xor_sync(0xffffffffu, ss, o);
    __shared__ float red[4];
    if ((threadIdx.x & 31) == 0) red[threadIdx.x >> 5] = ss;
    __syncthreads();
    float tot = red[0]+red[1]+red[2]+red[3];
    float r = rsqrtf(tot / (float)HDIM + EPSV);
    float xn = v * r * nw[d];
    __shared__ float xsh[HDIM];
    xsh[d] = xn;
    __syncthreads();
    float c, sn, oth;
    if (d < HDIM/2) { c = cosT[s*(HDIM/2)+d];          sn = sinT[s*(HDIM/2)+d];          oth = -xsh[d+HDIM/2]; }
    else            { c = cosT[s*(HDIM/2)+d-HDIM/2];   sn = sinT[s*(HDIM/2)+d-HDIM/2];   oth =  xsh[d-HDIM/2]; }
    xp[d] = xn*c + oth*sn;
}

// ---------------- flash attention (fp32) ----------------
#define FLASH_SMEM_BYTES ((64*132 + 128*68 + 64*65 + 3*64) * 4)
__global__ void flash_k(const float* __restrict__ qg, const float* __restrict__ kg,
                        const float* __restrict__ vg, float* __restrict__ og)
{
    extern __shared__ float fsh[];
    float* Qs = fsh;
    float* KT = Qs + 64*132;
    float* Vs = KT;
    float* Ss = KT + 128*68;
    float* ms = Ss + 64*65;
    float* ls = ms + 64;
    float* cs = ls + 64;

    int qt = blockIdx.x, h = blockIdx.y, b = blockIdx.z;
    int kvh = h / GQA;
    int qs0 = qt*64;
    int tid = threadIdx.x;
    float scale = rsqrtf((float)HDIM);

    for (int t = tid; t < 64*HDIM; t += 256) {
        int r = t >> 7, d = t & 127;
        Qs[r*132+d] = qg[((long)(b*SEQ + qs0 + r)*NHEAD + h)*HDIM + d] * scale;
    }
    if (tid < 64) { ms[tid] = -1e30f; ls[tid] = 0.f; }

    int ty = tid >> 4, tx = tid & 15;
    float oacc[4][8];
#pragma unroll
    for (int i = 0; i < 4; i++)
#pragma unroll
        for (int j = 0; j < 8; j++) oacc[i][j] = 0.f;
    __syncthreads();

    for (int jt = 0; jt <= qt; jt++) {
        int ks0 = jt*64;
        for (int t = tid; t < 64*HDIM; t += 256) {
            int r = t >> 7, d = t & 127;
            KT[d*68+r] = kg[((long)(b*SEQ + ks0 + r)*NKVH + kvh)*HDIM + d];
        }
        __syncthreads();

        float sreg[4][4];
#pragma unroll
        for (int i = 0; i < 4; i++)
#pragma unroll
            for (int j = 0; j < 4; j++) sreg[i][j] = 0.f;

        for (int d = 0; d < HDIM; d++) {
            float qv[4], kv[4];
#pragma unroll
            for (int i = 0; i < 4; i++) qv[i] = Qs[(ty*4+i)*132 + d];
#pragma unroll
            for (int j = 0; j < 4; j++) kv[j] = KT[d*68 + tx*4 + j];
#pragma unroll
            for (int i = 0; i < 4; i++)
#pragma unroll
                for (int j = 0; j < 4; j++) sreg[i][j] += qv[i]*kv[j];
        }
#pragma unroll
        for (int i = 0; i < 4; i++) {
            int si = ty*4+i;
#pragma unroll
            for (int j = 0; j < 4; j++) {
                int sj = tx*4+j;
                float sv = sreg[i][j];
                if (jt == qt && sj > si) sv = -1e30f;
                Ss[si*65+sj] = sv;
            }
        }
        __syncthreads();

        if (tid < 64) {
            float mo = ms[tid];
            float mx = mo;
            for (int j = 0; j < 64; j++) mx = fmaxf(mx, Ss[tid*65+j]);
            float c = expf(mo - mx);
            float ps = 0.f;
            for (int j = 0; j < 64; j++) {
                float p = expf(Ss[tid*65+j] - mx);
                Ss[tid*65+j] = p;
                ps += p;
            }
            ls[tid] = ls[tid]*c + ps;
            ms[tid] = mx;
            cs[tid] = c;
        }
        __syncthreads();

#pragma unroll
        for (int i = 0; i < 4; i++) {
            float c = cs[ty*4+i];
#pragma unroll
            for (int j = 0; j < 8; j++) oacc[i][j] *= c;
        }
        for (int t = tid; t < 64*HDIM; t += 256) {
            int r = t >> 7, d = t & 127;
            Vs[r*132+d] = vg[((long)(b*SEQ + ks0 + r)*NKVH + kvh)*HDIM + d];
        }
        __syncthreads();

        for (int j = 0; j < 64; j++) {
            float pv[4];
#pragma unroll
            for (int i = 0; i < 4; i++) pv[i] = Ss[(ty*4+i)*65 + j];
            float vr[8];
#pragma unroll
            for (int c2 = 0; c2 < 8; c2++) vr[c2] = Vs[j*132 + tx*4 + (c2&3) + (c2>>2)*64];
#pragma unroll
            for (int i = 0; i < 4; i++)
#pragma unroll
                for (int c2 = 0; c2 < 8; c2++) oacc[i][c2] += pv[i]*vr[c2];
        }
        __syncthreads();
    }

#pragma unroll
    for (int i = 0; i < 4; i++) {
        int r = ty*4+i;
        float inv = 1.f / ls[r];
#pragma unroll
        for (int c2 = 0; c2 < 8; c2++) {
            int col = tx*4 + (c2&3) + (c2>>2)*64;
            og[((long)(b*SEQ + qs0 + r)*NHEAD + h)*HDIM + col] = oacc[i][c2]*inv;
        }
    }
}

// ---------------- tf32 mma.sync GEMM: C[M,N] = A[M,K] @ B[K,N] ----------------
// B consumed directly in its native [K,N] layout (transposed while staging to smem).
// EPI: 0=store, 1=resid add(extra), 2=in-place silu(C)*acc, 3=rowscale-add(extra[row])
__device__ __forceinline__ void mma_tf32(float* c, float a0, float a1, float a2, float a3,
                                         float b0, float b1)
{
    uint32_t ua0 = __float_as_uint(a0), ua1 = __float_as_uint(a1);
    uint32_t ua2 = __float_as_uint(a2), ua3 = __float_as_uint(a3);
    uint32_t ub0 = __float_as_uint(b0), ub1 = __float_as_uint(b1);
    asm volatile("mma.sync.aligned.m16n8k8.row.col.f32.tf32.tf32.f32 "
        "{%0,%1,%2,%3}, {%4,%5,%6,%7}, {%8,%9}, {%0,%1,%2,%3};"
        : "+f"(c[0]), "+f"(c[1]), "+f"(c[2]), "+f"(c[3])
        : "r"(ua0), "r"(ua1), "r"(ua2), "r"(ua3), "r"(ub0), "r"(ub1));
}
__device__ __forceinline__ float tf32r(float x)
{
    uint32_t u;
    asm("cvt.rna.tf32.f32 %0, %1;" : "=r"(u) : "f"(x));
    return __uint_as_float(u);
}

#define APAD 40
#define BPAD 34

template<int EPI, bool AIDX, bool EXPERT>
__global__ void __launch_bounds__(256)
mmgemm_k(int M, int N, int Kd,
         const float* __restrict__ A, int lda,
         const float* __restrict__ B, int ldb, long strideB,
         float* __restrict__ C, int ldc,
         const int* __restrict__ offs, const int* __restrict__ aidx,
         const float* __restrict__ extra)
{
    __shared__ float As[128][APAD];   // [m][k] tile
    __shared__ float Bs[128][BPAD];   // [n][k] tile (transposed from global [K,N])

    int rbase = 0, mrows = M;
    const float* Bp = B;
    if (EXPERT) {
        int e = blockIdx.z;
        rbase = offs[e];
        mrows = offs[e+1] - rbase;
        Bp = B + (long)e * strideB;
    }
    int bm0 = blockIdx.y * 128;
    if (bm0 >= mrows) return;
    int bn0 = blockIdx.x * 128;

    int tid = threadIdx.x;
    int wid = tid >> 5, lane = tid & 31;
    int g = lane >> 2, tg = lane & 3;
    int warp_m = wid & 1, warp_n = wid >> 1;    // 2 x 4 warp grid

    // A staging: thread covers rows r0+32i, cols cA..cA+3 of the 32-wide k-chunk
    int rA0 = tid >> 3;
    int cA  = (tid & 7) * 4;
    const float* ap[4];
#pragma unroll
    for (int i = 0; i < 4; i++) {
        int lr = bm0 + rA0 + 32*i;
        if (lr < mrows) {
            long gr = AIDX ? (long)aidx[rbase + lr] : (long)(rbase + lr);
            ap[i] = A + gr*(long)lda + cA;
        } else ap[i] = nullptr;
    }
    // B staging: thread reads row kB of B, cols nB+32i .. +3; stores transposed
    int kB = tid >> 3;
    int nB = (tid & 7) * 4;
    const float* bp = Bp + (long)kB*ldb + bn0 + nB;

    float acc[4][4][4];
#pragma unroll
    for (int mt = 0; mt < 4; mt++)
#pragma unroll
        for (int nt = 0; nt < 4; nt++)
#pragma unroll
            for (int r = 0; r < 4; r++) acc[mt][nt][r] = 0.f;

    int nc = Kd >> 5;
    for (int kt = 0; kt < nc; kt++) {
        long ko = (long)(kt << 5);
        // stage A (cvt to tf32 at store)
#pragma unroll
        for (int i = 0; i < 4; i++) {
            float4 v = ap[i] ? *reinterpret_cast<const float4*>(ap[i] + ko)
                             : make_float4(0.f,0.f,0.f,0.f);
            int r = rA0 + 32*i;
            As[r][cA+0] = tf32r(v.x); As[r][cA+1] = tf32r(v.y);
            As[r][cA+2] = tf32r(v.z); As[r][cA+3] = tf32r(v.w);
        }
        // stage B transposed
#pragma unroll
        for (int i = 0; i < 4; i++) {
            float4 u = *reinterpret_cast<const float4*>(bp + ko*ldb + 32*i);
            int n = nB + 32*i;
            Bs[n+0][kB] = tf32r(u.x); Bs[n+1][kB] = tf32r(u.y);
            Bs[n+2][kB] = tf32r(u.z); Bs[n+3][kB] = tf32r(u.w);
        }
        __syncthreads();

#pragma unroll
        for (int ks = 0; ks < 4; ks++) {
            int kb = ks*8;
            // B fragment: b0 = (k=kb+tg, n), b1 = (k=kb+tg+4, n)
            float bb0[4], bb1[4];
#pragma unroll
            for (int nt = 0; nt < 4; nt++) {
                int n = warp_n*32 + nt*8 + g;
                bb0[nt] = Bs[n][kb + tg];
                bb1[nt] = Bs[n][kb + tg + 4];
            }
#pragma unroll
            for (int mt = 0; mt < 4; mt++) {
                int rm = warp_m*64 + mt*16;
                // A fragment: a0=(g, tg), a1=(g+8, tg), a2=(g, tg+4), a3=(g+8, tg+4)
                float a0 = As[rm + g    ][kb + tg];
                float a1 = As[rm + g + 8][kb + tg];
                float a2 = As[rm + g    ][kb + tg + 4];
                float a3 = As[rm + g + 8][kb + tg + 4];
#pragma unroll
                for (int nt = 0; nt < 4; nt++)
                    mma_tf32(acc[mt][nt], a0, a1, a2, a3, bb0[nt], bb1[nt]);
            }
        }
        __syncthreads();
    }

    // epilogue: c0=(g,2tg), c1=(g,2tg+1), c2=(g+8,2tg), c3=(g+8,2tg+1)
#pragma unroll
    for (int mt = 0; mt < 4; mt++) {
        int lr1 = warp_m*64 + mt*16 + g;
        int lr2 = lr1 + 8;
#pragma unroll
        for (int nt = 0; nt < 4; nt++) {
            int col = bn0 + warp_n*32 + nt*8 + 2*tg;
#pragma unroll
            for (int half = 0; half < 2; half++) {
                int lr = half ? lr2 : lr1;
                int grow = bm0 + lr;
                if (grow >= mrows) continue;
                long cr = rbase + grow;
                float v0 = acc[mt][nt][half*2+0];
                float v1 = acc[mt][nt][half*2+1];
                long o0 = cr*(long)ldc + col;
                if (EPI == 0) {
                    C[o0] = v0; C[o0+1] = v1;
                } else if (EPI == 1) {
                    C[o0]   = extra[o0]   + v0;
                    C[o0+1] = extra[o0+1] + v1;
                } else if (EPI == 2) {
                    float g0 = C[o0], g1 = C[o0+1];
                    C[o0]   = g0 / (1.f + expf(-g0)) * v0;
                    C[o0+1] = g1 / (1.f + expf(-g1)) * v1;
                } else if (EPI == 3) {
                    float s = extra[grow];
                    C[o0]   += v0 * s;
                    C[o0+1] += v1 * s;
                }
            }
        }
    }
}

// ---------------- router ----------------
__global__ void router_k(const float* __restrict__ x2, const float* __restrict__ Wr,
                         int* __restrict__ topi, float* __restrict__ topw)
{
    int t = blockIdx.x;
    __shared__ float xs[HID];
    __shared__ float pr[NEXP];
    for (int i = threadIdx.x; i < HID; i += blockDim.x) xs[i] = x2[(long)t*HID + i];
    __syncthreads();
    if (threadIdx.x < NEXP) {
        int e = threadIdx.x;
        float d = 0.f;
        for (int i = 0; i < HID; i++) d += xs[i] * Wr[i*NEXP + e];
        pr[e] = d;
    }
    __syncthreads();
    if (threadIdx.x == 0) {
        float mx = -1e30f;
        for (int e = 0; e < NEXP; e++) mx = fmaxf(mx, pr[e]);
        float p[NEXP]; float sm2 = 0.f;
        for (int e = 0; e < NEXP; e++) { p[e] = expf(pr[e]-mx); sm2 += p[e]; }
        for (int e = 0; e < NEXP; e++) p[e] /= sm2;
        float tw = 0.f;
        int   idx[TOPK]; float val[TOPK];
        for (int kk = 0; kk < TOPK; kk++) {
            int bi = 0; float bv = -1.f;
            for (int e = 0; e < NEXP; e++) if (p[e] > bv) { bv = p[e]; bi = e; }
            idx[kk] = bi; val[kk] = bv; p[bi] = -2.f; tw += bv;
        }
        for (int kk = 0; kk < TOPK; kk++) {
            topi[t*TOPK+kk] = idx[kk];
            topw[t*TOPK+kk] = val[kk] / tw;
        }
    }
}

// ---------------- routing build ----------------
__global__ void zero32_k(int* cnt) { if (threadIdx.x < NEXP) cnt[threadIdx.x] = 0; }
__global__ void count_k(const int* __restrict__ topi, int* __restrict__ cnt)
{
    int i = blockIdx.x*256 + threadIdx.x;
    if (i < T_TOK*TOPK) atomicAdd(&cnt[topi[i]], 1);
}
__global__ void scan_k(const int* __restrict__ cnt, int* __restrict__ off, int* __restrict__ cur)
{
    if (threadIdx.x == 0) {
        int a = 0;
        for (int e = 0; e < NEXP; e++) { off[e] = a; cur[e] = a; a += cnt[e]; }
        off[NEXP] = a;
    }
}
__global__ void fill_k(const int* __restrict__ topi, int* __restrict__ cur,
                       int* __restrict__ ptok, int* __restrict__ ppos)
{
    int i = blockIdx.x*256 + threadIdx.x;
    if (i < T_TOK*TOPK) {
        int e = topi[i];
        int p = atomicAdd(&cur[e], 1);
        ptok[p] = i / TOPK;
        ppos[i] = p;
    }
}

// ---------------- MoE reduction ----------------
__global__ void moe_reduce_k(const float* __restrict__ down, const int* __restrict__ ppos,
                             const float* __restrict__ topw, const float* __restrict__ h,
                             float* __restrict__ out)
{
    int t = blockIdx.x;
    int pos[TOPK]; float w[TOPK];
#pragma unroll
    for (int kk = 0; kk < TOPK; kk++) { pos[kk] = ppos[t*TOPK+kk]; w[kk] = topw[t*TOPK+kk]; }
    for (int c = threadIdx.x; c < HID; c += blockDim.x) {
        float s = h[(long)t*HID + c];
#pragma unroll
        for (int kk = 0; kk < TOPK; kk++) s += down[(long)pos[kk]*HID + c] * w[kk];
        out[(long)t*HID + c] = s;
    }
}

// ---------------- shared-expert sigmoid gate ----------------
__global__ void shgate_k(const float* __restrict__ x2, const float* __restrict__ w,
                         float* __restrict__ sig)
{
    int t = blockIdx.x;
    float s = 0.f;
    for (int i = threadIdx.x; i < HID; i += blockDim.x) s += x2[(long)t*HID + i] * w[i];
    __shared__ float red[32];
    for (int o = 16; o > 0; o >>= 1) s += __shfl_xor_sync(0xffffffffu, s, o);
    int warp = threadIdx.x >> 5, lane = threadIdx.x & 31;
    if (lane == 0) red[warp] = s;
    __syncthreads();
    if (warp == 0) {
        s = (lane < (blockDim.x >> 5)) ? red[lane] : 0.f;
        for (int o = 16; o > 0; o >>= 1) s += __shfl_xor_sync(0xffffffffu, s, o);
        if (lane == 0) sig[t] = 1.f / (1.f + expf(-s));
    }
}

// ---------------- host launch ----------------
extern "C" void kernel_launch(void* const* d_in, const int* in_sizes, int n_in,
                              void* d_out, int out_size)
{
    (void)in_sizes; (void)out_size;
    if (n_in < 17) return;
    const float* hidden = (const float*)d_in[0];
    const float* ln1    = (const float*)d_in[1];
    const float* ln2    = (const float*)d_in[2];
    const float* qnw    = (const float*)d_in[3];
    const float* knw    = (const float*)d_in[4];
    const float* Wq     = (const float*)d_in[5];
    const float* Wk     = (const float*)d_in[6];
    const float* Wv     = (const float*)d_in[7];
    const float* Wo     = (const float*)d_in[8];
    const float* Wr     = (const float*)d_in[9];
    const float* Weg    = (const float*)d_in[10];
    const float* Weu    = (const float*)d_in[11];
    const float* Wed    = (const float*)d_in[12];
    const float* Wsg    = (const float*)d_in[13];
    const float* Wsu    = (const float*)d_in[14];
    const float* Wsd    = (const float*)d_in[15];
    const float* Wshg   = (const float*)d_in[16];
    float* out = (float*)d_out;

    float *xn, *qb, *kb, *vb, *att, *hb, *act, *down, *cosT, *sinT, *topw, *sig;
    int *topi, *cnt, *off, *cur, *ptok, *ppos;
    cudaGetSymbolAddress((void**)&xn,   g_xn);
    cudaGetSymbolAddress((void**)&qb,   g_q);
    cudaGetSymbolAddress((void**)&kb,   g_k);
    cudaGetSymbolAddress((void**)&vb,   g_v);
    cudaGetSymbolAddress((void**)&att,  g_att);
    cudaGetSymbolAddress((void**)&hb,   g_h);
    cudaGetSymbolAddress((void**)&act,  g_act);
    cudaGetSymbolAddress((void**)&down, g_down);
    cudaGetSymbolAddress((void**)&cosT, g_cos);
    cudaGetSymbolAddress((void**)&sinT, g_sin);
    cudaGetSymbolAddress((void**)&topi, g_topi);
    cudaGetSymbolAddress((void**)&topw, g_topw);
    cudaGetSymbolAddress((void**)&cnt,  g_cnt);
    cudaGetSymbolAddress((void**)&off,  g_off);
    cudaGetSymbolAddress((void**)&cur,  g_cur);
    cudaGetSymbolAddress((void**)&ptok, g_ptok);
    cudaGetSymbolAddress((void**)&ppos, g_ppos);
    cudaGetSymbolAddress((void**)&sig,  g_sig);

    cudaFuncSetAttribute(flash_k, cudaFuncAttributeMaxDynamicSharedMemorySize, FLASH_SMEM_BYTES);

    // --- attention block ---
    rmsnorm_k<<<T_TOK, 256>>>(hidden, ln1, xn);

    mmgemm_k<0,false,false><<<dim3(32, 32), 256>>>(T_TOK, NHEAD*HDIM, HID, xn, HID, Wq, NHEAD*HDIM, 0, qb, NHEAD*HDIM, nullptr, nullptr, nullptr);
    mmgemm_k<0,false,false><<<dim3( 4, 32), 256>>>(T_TOK, NKVH*HDIM,  HID, xn, HID, Wk, NKVH*HDIM,  0, kb, NKVH*HDIM,  nullptr, nullptr, nullptr);
    mmgemm_k<0,false,false><<<dim3( 4, 32), 256>>>(T_TOK, NKVH*HDIM,  HID, xn, HID, Wv, NKVH*HDIM,  0, vb, NKVH*HDIM,  nullptr, nullptr, nullptr);

    rope_tab_k<<<SEQ, HDIM/2>>>(cosT, sinT);
    qknr_k<<<T_TOK*NHEAD, HDIM>>>(qb, qnw, NHEAD, cosT, sinT);
    qknr_k<<<T_TOK*NKVH,  HDIM>>>(kb, knw, NKVH, cosT, sinT);

    flash_k<<<dim3(SEQ/64, NHEAD, BATCH), 256, FLASH_SMEM_BYTES>>>(qb, kb, vb, att);

    // h = hidden + att @ Wo
    mmgemm_k<1,false,false><<<dim3(16, 32), 256>>>(T_TOK, HID, NHEAD*HDIM, att, NHEAD*HDIM, Wo, HID, 0, hb, HID, nullptr, nullptr, hidden);

    // --- MoE block ---
    rmsnorm_k<<<T_TOK, 256>>>(hb, ln2, xn);

    router_k<<<T_TOK, 128>>>(xn, Wr, topi, topw);
    zero32_k<<<1, 32>>>(cnt);
    count_k<<<(T_TOK*TOPK+255)/256, 256>>>(topi, cnt);
    scan_k<<<1, 32>>>(cnt, off, cur);
    fill_k<<<(T_TOK*TOPK+255)/256, 256>>>(topi, cur, ptok, ppos);

    // experts: gate, up(silu*), down
    mmgemm_k<0,true,true><<<dim3(EI/128, 32, NEXP), 256>>>(0, EI, HID, xn, HID, Weg, EI, (long)HID*EI, act, EI, off, ptok, nullptr);
    mmgemm_k<2,true,true><<<dim3(EI/128, 32, NEXP), 256>>>(0, EI, HID, xn, HID, Weu, EI, (long)HID*EI, act, EI, off, ptok, nullptr);
    mmgemm_k<0,false,true><<<dim3(HID/128, 32, NEXP), 256>>>(0, HID, EI, act, EI, Wed, HID, (long)EI*HID, down, HID, off, nullptr, nullptr);

    moe_reduce_k<<<T_TOK, 256>>>(down, ppos, topw, hb, out);

    // --- shared expert (reuses g_q as [T, SI] intermediate) ---
    mmgemm_k<0,false,false><<<dim3(SI/128, 32), 256>>>(T_TOK, SI, HID, xn, HID, Wsg, SI, 0, qb, SI, nullptr, nullptr, nullptr);
    mmgemm_k<2,false,false><<<dim3(SI/128, 32), 256>>>(T_TOK, SI, HID, xn, HID, Wsu, SI, 0, qb, SI, nullptr, nullptr, nullptr);
    shgate_k<<<T_TOK, 256>>>(xn, Wshg, sig);
    mmgemm_k<3,false,false><<<dim3(HID/128, 32), 256>>>(T_TOK, HID, SI, qb, SI, Wsd, HID, 0, out, HID, nullptr, nullptr, sig);
}

// round 5
// speedup vs baseline: 2.9087x; 1.4018x over previous
#include <cuda_runtime.h>
#include <math.h>
#include <stdint.h>

// ---------------- problem constants ----------------
#define T_TOK 4096
#define HID   2048
#define SEQ   1024
#define BATCH 4
#define NHEAD 32
#define NKVH  4
#define HDIM  128
#define NEXP  32
#define TOPK  8
#define EI    768
#define SI    4096
#define GQA   8
#define EPSV  1e-6f
#define QKVN  (NHEAD*HDIM + 2*NKVH*HDIM)   // 5120

// ---------------- scratch ----------------
__device__ float g_xn  [T_TOK*HID];
__device__ float g_xnr [T_TOK*HID];           // tf32-rounded rmsnorm output (GEMM A)
__device__ float g_qkv [T_TOK*QKVN];          // packed q|k|v
__device__ float g_sh  [T_TOK*SI];            // shared-expert intermediate
__device__ float g_att [T_TOK*NHEAD*HDIM];
__device__ float g_h   [T_TOK*HID];
__device__ float g_act [T_TOK*TOPK*EI];
__device__ float g_down[T_TOK*TOPK*HID];
__device__ float g_cos[SEQ*(HDIM/2)];
__device__ float g_sin[SEQ*(HDIM/2)];
__device__ int   g_topi[T_TOK*TOPK];
__device__ float g_topw[T_TOK*TOPK];
__device__ int   g_cnt[NEXP];
__device__ int   g_off[NEXP+1];
__device__ int   g_cur[NEXP];
__device__ int   g_ptok[T_TOK*TOPK];
__device__ int   g_ppos[T_TOK*TOPK];
__device__ float g_sig[T_TOK];
// tf32-rounded weight copies
__device__ float g_Wqkv[HID*QKVN];
__device__ float g_WoC [NHEAD*HDIM*HID];
__device__ float g_WegC[NEXP*HID*EI];
__device__ float g_WeuC[NEXP*HID*EI];
__device__ float g_WedC[NEXP*EI*HID];
__device__ float g_WsgC[HID*SI];
__device__ float g_WsuC[HID*SI];
__device__ float g_WsdC[SI*HID];

// ---------------- helpers ----------------
__device__ __forceinline__ float tf32r(float x)
{
    uint32_t u;
    asm("cvt.rna.tf32.f32 %0, %1;" : "=r"(u) : "f"(x));
    return __uint_as_float(u);
}
__device__ __forceinline__ uint32_t smem_u32(const void* p){
    uint32_t a;
    asm("{ .reg .u64 t; cvta.to.shared.u64 t, %1; cvt.u32.u64 %0, t; }" : "=r"(a) : "l"(p));
    return a;
}
__device__ __forceinline__ void cp_async16(uint32_t saddr, const void* gaddr, uint32_t sz){
    asm volatile("cp.async.cg.shared.global [%0], [%1], 16, %2;"
        :: "r"(saddr), "l"(gaddr), "r"(sz) : "memory");
}
__device__ __forceinline__ void cp_commit(){
    asm volatile("cp.async.commit_group;" ::: "memory");
}
template<int N>
__device__ __forceinline__ void cp_wait(){
    asm volatile("cp.async.wait_group %0;" :: "n"(N) : "memory");
}
__device__ __forceinline__ void mma_tf32(float* c, float a0, float a1, float a2, float a3,
                                         float b0, float b1)
{
    uint32_t ua0 = __float_as_uint(a0), ua1 = __float_as_uint(a1);
    uint32_t ua2 = __float_as_uint(a2), ua3 = __float_as_uint(a3);
    uint32_t ub0 = __float_as_uint(b0), ub1 = __float_as_uint(b1);
    asm volatile("mma.sync.aligned.m16n8k8.row.col.f32.tf32.tf32.f32 "
        "{%0,%1,%2,%3}, {%4,%5,%6,%7}, {%8,%9}, {%0,%1,%2,%3};"
        : "+f"(c[0]), "+f"(c[1]), "+f"(c[2]), "+f"(c[3])
        : "r"(ua0), "r"(ua1), "r"(ua2), "r"(ua3), "r"(ub0), "r"(ub1));
}

// ---------------- weight conversion (tf32 round, elementwise) ----------------
__global__ void cvt_k(const float* __restrict__ src, float* __restrict__ dst, long n4)
{
    long i = (long)blockIdx.x*blockDim.x + threadIdx.x;
    long stride = (long)gridDim.x*blockDim.x;
    for (; i < n4; i += stride) {
        float4 v = reinterpret_cast<const float4*>(src)[i];
        v.x = tf32r(v.x); v.y = tf32r(v.y); v.z = tf32r(v.z); v.w = tf32r(v.w);
        reinterpret_cast<float4*>(dst)[i] = v;
    }
}
// pack Wq|Wk|Wv (each [HID, n]) into [HID, 5120] with tf32 rounding
__global__ void cvt_qkv_k(const float* __restrict__ Wq, const float* __restrict__ Wk,
                          const float* __restrict__ Wv, float* __restrict__ dst)
{
    long n4 = (long)HID*QKVN/4;
    long i = (long)blockIdx.x*blockDim.x + threadIdx.x;
    long stride = (long)gridDim.x*blockDim.x;
    for (; i < n4; i += stride) {
        long e = i*4;
        int k = (int)(e / QKVN);
        int c = (int)(e % QKVN);
        float4 v;
        if (c < NHEAD*HDIM)          v = *reinterpret_cast<const float4*>(Wq + (long)k*(NHEAD*HDIM) + c);
        else if (c < NHEAD*HDIM+NKVH*HDIM) v = *reinterpret_cast<const float4*>(Wk + (long)k*(NKVH*HDIM) + (c - NHEAD*HDIM));
        else                          v = *reinterpret_cast<const float4*>(Wv + (long)k*(NKVH*HDIM) + (c - NHEAD*HDIM - NKVH*HDIM));
        v.x = tf32r(v.x); v.y = tf32r(v.y); v.z = tf32r(v.z); v.w = tf32r(v.w);
        reinterpret_cast<float4*>(dst)[i] = v;
    }
}

// ---------------- rmsnorm over HID (writes full + tf32-rounded) ----------------
__global__ void rmsnorm_k(const float* __restrict__ x, const float* __restrict__ w,
                          float* __restrict__ y, float* __restrict__ yr)
{
    int row = blockIdx.x;
    const float* xr = x + (long)row*HID;
    float ss = 0.f;
    for (int i = threadIdx.x; i < HID; i += blockDim.x) { float v = xr[i]; ss += v*v; }
    __shared__ float red[32];
    for (int o = 16; o > 0; o >>= 1) ss += __shfl_xor_sync(0xffffffffu, ss, o);
    int warp = threadIdx.x >> 5, lane = threadIdx.x & 31;
    if (lane == 0) red[warp] = ss;
    __syncthreads();
    if (warp == 0) {
        ss = (lane < (blockDim.x >> 5)) ? red[lane] : 0.f;
        for (int o = 16; o > 0; o >>= 1) ss += __shfl_xor_sync(0xffffffffu, ss, o);
        if (lane == 0) red[0] = ss;
    }
    __syncthreads();
    float r = rsqrtf(red[0] / (float)HID + EPSV);
    for (int i = threadIdx.x; i < HID; i += blockDim.x) {
        float v = xr[i] * r * w[i];
        y [(long)row*HID + i] = v;
        yr[(long)row*HID + i] = tf32r(v);
    }
}

// ---------------- rope tables ----------------
__global__ void rope_tab_k(float* __restrict__ cosT, float* __restrict__ sinT)
{
    int s = blockIdx.x;
    int i = threadIdx.x;
    float inv = expf(-((float)(2*i) / (float)HDIM) * logf(1000000.0f));
    float ang = (float)s * inv;
    cosT[s*(HDIM/2)+i] = cosf(ang);
    sinT[s*(HDIM/2)+i] = sinf(ang);
}

// ---------------- per-head rmsnorm + rope on packed qkv ----------------
__global__ void qknr_k(float* __restrict__ qkv, const float* __restrict__ nw, int nh, int colOff,
                       const float* __restrict__ cosT, const float* __restrict__ sinT)
{
    long bh = blockIdx.x;
    int t = (int)(bh / nh);
    int head = (int)(bh % nh);
    int s = t & (SEQ-1);
    int d = threadIdx.x;
    float* xp = qkv + (long)t*QKVN + colOff + head*HDIM;
    float v = xp[d];
    float ss = v*v;
    for (int o = 16; o > 0; o >>= 1) ss += __shfl_xor_sync(0xffffffffu, ss, o);
    __shared__ float red[4];
    if ((threadIdx.x & 31) == 0) red[threadIdx.x >> 5] = ss;
    __syncthreads();
    float tot = red[0]+red[1]+red[2]+red[3];
    float r = rsqrtf(tot / (float)HDIM + EPSV);
    float xn = v * r * nw[d];
    __shared__ float xsh[HDIM];
    xsh[d] = xn;
    __syncthreads();
    float c, sn, oth;
    if (d < HDIM/2) { c = cosT[s*(HDIM/2)+d];          sn = sinT[s*(HDIM/2)+d];          oth = -xsh[d+HDIM/2]; }
    else            { c = cosT[s*(HDIM/2)+d-HDIM/2];   sn = sinT[s*(HDIM/2)+d-HDIM/2];   oth =  xsh[d-HDIM/2]; }
    xp[d] = xn*c + oth*sn;
}

// ---------------- flash attention (fp32), packed qkv input, rounded output ----------------
#define FLASH_SMEM_BYTES ((64*132 + 128*68 + 64*65 + 3*64) * 4)
__global__ void flash_k(const float* __restrict__ qkv, float* __restrict__ og)
{
    extern __shared__ float fsh[];
    float* Qs = fsh;
    float* KT = Qs + 64*132;
    float* Vs = KT;
    float* Ss = KT + 128*68;
    float* ms = Ss + 64*65;
    float* ls = ms + 64;
    float* cs = ls + 64;

    int qt = blockIdx.x, h = blockIdx.y, b = blockIdx.z;
    int kvh = h / GQA;
    int qs0 = qt*64;
    int tid = threadIdx.x;
    float scale = rsqrtf((float)HDIM);

    for (int t = tid; t < 64*HDIM; t += 256) {
        int r = t >> 7, d = t & 127;
        Qs[r*132+d] = qkv[(long)(b*SEQ + qs0 + r)*QKVN + h*HDIM + d] * scale;
    }
    if (tid < 64) { ms[tid] = -1e30f; ls[tid] = 0.f; }

    int ty = tid >> 4, tx = tid & 15;
    float oacc[4][8];
#pragma unroll
    for (int i = 0; i < 4; i++)
#pragma unroll
        for (int j = 0; j < 8; j++) oacc[i][j] = 0.f;
    __syncthreads();

    for (int jt = 0; jt <= qt; jt++) {
        int ks0 = jt*64;
        for (int t = tid; t < 64*HDIM; t += 256) {
            int r = t >> 7, d = t & 127;
            KT[d*68+r] = qkv[(long)(b*SEQ + ks0 + r)*QKVN + NHEAD*HDIM + kvh*HDIM + d];
        }
        __syncthreads();

        float sreg[4][4];
#pragma unroll
        for (int i = 0; i < 4; i++)
#pragma unroll
            for (int j = 0; j < 4; j++) sreg[i][j] = 0.f;

        for (int d = 0; d < HDIM; d++) {
            float qv[4], kv[4];
#pragma unroll
            for (int i = 0; i < 4; i++) qv[i] = Qs[(ty*4+i)*132 + d];
#pragma unroll
            for (int j = 0; j < 4; j++) kv[j] = KT[d*68 + tx*4 + j];
#pragma unroll
            for (int i = 0; i < 4; i++)
#pragma unroll
                for (int j = 0; j < 4; j++) sreg[i][j] += qv[i]*kv[j];
        }
#pragma unroll
        for (int i = 0; i < 4; i++) {
            int si = ty*4+i;
#pragma unroll
            for (int j = 0; j < 4; j++) {
                int sj = tx*4+j;
                float sv = sreg[i][j];
                if (jt == qt && sj > si) sv = -1e30f;
                Ss[si*65+sj] = sv;
            }
        }
        __syncthreads();

        if (tid < 64) {
            float mo = ms[tid];
            float mx = mo;
            for (int j = 0; j < 64; j++) mx = fmaxf(mx, Ss[tid*65+j]);
            float c = expf(mo - mx);
            float ps = 0.f;
            for (int j = 0; j < 64; j++) {
                float p = expf(Ss[tid*65+j] - mx);
                Ss[tid*65+j] = p;
                ps += p;
            }
            ls[tid] = ls[tid]*c + ps;
            ms[tid] = mx;
            cs[tid] = c;
        }
        __syncthreads();

#pragma unroll
        for (int i = 0; i < 4; i++) {
            float c = cs[ty*4+i];
#pragma unroll
            for (int j = 0; j < 8; j++) oacc[i][j] *= c;
        }
        for (int t = tid; t < 64*HDIM; t += 256) {
            int r = t >> 7, d = t & 127;
            Vs[r*132+d] = qkv[(long)(b*SEQ + ks0 + r)*QKVN + NHEAD*HDIM + NKVH*HDIM + kvh*HDIM + d];
        }
        __syncthreads();

        for (int j = 0; j < 64; j++) {
            float pv[4];
#pragma unroll
            for (int i = 0; i < 4; i++) pv[i] = Ss[(ty*4+i)*65 + j];
            float vr[8];
#pragma unroll
            for (int c2 = 0; c2 < 8; c2++) vr[c2] = Vs[j*132 + tx*4 + (c2&3) + (c2>>2)*64];
#pragma unroll
            for (int i = 0; i < 4; i++)
#pragma unroll
                for (int c2 = 0; c2 < 8; c2++) oacc[i][c2] += pv[i]*vr[c2];
        }
        __syncthreads();
    }

#pragma unroll
    for (int i = 0; i < 4; i++) {
        int r = ty*4+i;
        float inv = 1.f / ls[r];
#pragma unroll
        for (int c2 = 0; c2 < 8; c2++) {
            int col = tx*4 + (c2&3) + (c2>>2)*64;
            og[((long)(b*SEQ + qs0 + r)*NHEAD + h)*HDIM + col] = tf32r(oacc[i][c2]*inv);
        }
    }
}

// ---------------- tf32 mma.sync GEMM with cp.async double buffering ----------------
// C[M,N] = A[M,K] @ B[K,N]; A and B pre-rounded to tf32 representable values.
// CTA tile 128x128x32; 4 warps (2x2), warp tile 64x64.
// EPI: 0=store, 1=resid add(extra), 2=in-place tf32r(silu(C)*acc), 3=rowscale-add(extra[row])
#define APITCH 36
#define BPITCH 136
#define ABUF_F (128*APITCH)
#define BBUF_F (32*BPITCH)
#define MM2_SMEM_BYTES (2*(ABUF_F + BBUF_F)*4)

template<int EPI, bool AIDX, bool EXPERT>
__global__ void __launch_bounds__(128)
mm2_k(int M, int N, int Kd,
      const float* __restrict__ A, int lda,
      const float* __restrict__ B, int ldb, long strideB,
      float* __restrict__ C, int ldc,
      const int* __restrict__ offs, const int* __restrict__ aidx,
      const float* __restrict__ extra)
{
    extern __shared__ float sm[];
    int rbase = 0, mrows = M;
    const float* Bp = B;
    if (EXPERT) {
        int e = blockIdx.z;
        rbase = offs[e];
        mrows = offs[e+1] - rbase;
        Bp = B + (long)e * strideB;
    }
    int bm0 = blockIdx.y * 128;
    if (bm0 >= mrows) return;
    int bn0 = blockIdx.x * 128;

    uint32_t sb = smem_u32(sm);
    uint32_t aS[2] = { sb, sb + (uint32_t)ABUF_F*4 };
    uint32_t bS[2] = { sb + (uint32_t)2*ABUF_F*4, sb + (uint32_t)(2*ABUF_F + BBUF_F)*4 };
    float* aF[2] = { sm, sm + ABUF_F };
    float* bF[2] = { sm + 2*ABUF_F, sm + 2*ABUF_F + BBUF_F };

    int tid = threadIdx.x, lane = tid & 31, wid = tid >> 5;
    int g = lane >> 2, tg = lane & 3;
    int warp_m = wid & 1, warp_n = wid >> 1;   // 2x2 warps

    // ---- staging descriptors ----
    // A: 1024 x 16B chunks; thread handles rows rA+16i, 16B at col cA*4
    int rA = tid >> 3, cA = tid & 7;
    const char* apg[8];
    uint32_t asz[8], asmo[8];
#pragma unroll
    for (int i = 0; i < 8; i++) {
        int lr = bm0 + rA + 16*i;
        if (lr < mrows) {
            long gr = AIDX ? (long)aidx[rbase + lr] : (long)(rbase + lr);
            apg[i] = (const char*)(A + gr*(long)lda + cA*4);
            asz[i] = 16;
        } else { apg[i] = (const char*)A; asz[i] = 0; }
        asmo[i] = (uint32_t)((rA + 16*i)*APITCH + cA*4) * 4;
    }
    // B: 1024 x 16B chunks; thread handles k-rows (tid>>5)+4i, 16B at col cB*4
    int cB = tid & 31;
    const char* bpg[8];
    uint32_t bsmo[8];
#pragma unroll
    for (int i = 0; i < 8; i++) {
        int kr = (tid >> 5) + 4*i;
        bpg[i] = (const char*)(Bp + (long)kr*ldb + bn0 + cB*4);
        bsmo[i] = (uint32_t)(kr*BPITCH + cB*4) * 4;
    }
    long bstep = (long)32*ldb*4;   // bytes per k-chunk for B

    float acc[4][8][4];
#pragma unroll
    for (int mt = 0; mt < 4; mt++)
#pragma unroll
        for (int nt = 0; nt < 8; nt++)
#pragma unroll
            for (int r = 0; r < 4; r++) acc[mt][nt][r] = 0.f;

    int nc = Kd >> 5;

    // prologue: stage chunk 0 into buffer 0
#pragma unroll
    for (int i = 0; i < 8; i++) cp_async16(aS[0] + asmo[i], apg[i], asz[i]);
#pragma unroll
    for (int i = 0; i < 8; i++) cp_async16(bS[0] + bsmo[i], bpg[i], 16);
    cp_commit();

    for (int c = 0; c < nc; c++) {
        int p = c & 1;
        if (c + 1 < nc) {
            int q = p ^ 1;
            long ka = (long)(c+1)*128;        // A byte advance (32 floats)
            long kb2 = (long)(c+1)*bstep;
#pragma unroll
            for (int i = 0; i < 8; i++) cp_async16(aS[q] + asmo[i], apg[i] + ka, asz[i]);
#pragma unroll
            for (int i = 0; i < 8; i++) cp_async16(bS[q] + bsmo[i], bpg[i] + kb2, 16);
            cp_commit();
            cp_wait<1>();
        } else {
            cp_wait<0>();
        }
        __syncthreads();

        const float* Asf = aF[p];
        const float* Bsf = bF[p];
#pragma unroll
        for (int ks = 0; ks < 4; ks++) {
            int kb = ks*8;
            float a0[4], a1[4], a2[4], a3[4];
#pragma unroll
            for (int mt = 0; mt < 4; mt++) {
                int ra = warp_m*64 + mt*16 + g;
                a0[mt] = Asf[ra*APITCH + kb + tg];
                a1[mt] = Asf[(ra+8)*APITCH + kb + tg];
                a2[mt] = Asf[ra*APITCH + kb + tg + 4];
                a3[mt] = Asf[(ra+8)*APITCH + kb + tg + 4];
            }
            float b0[8], b1[8];
#pragma unroll
            for (int nt = 0; nt < 8; nt++) {
                int n = warp_n*64 + nt*8 + g;
                b0[nt] = Bsf[(kb+tg)*BPITCH + n];
                b1[nt] = Bsf[(kb+tg+4)*BPITCH + n];
            }
#pragma unroll
            for (int mt = 0; mt < 4; mt++)
#pragma unroll
                for (int nt = 0; nt < 8; nt++)
                    mma_tf32(acc[mt][nt], a0[mt], a1[mt], a2[mt], a3[mt], b0[nt], b1[nt]);
        }
        __syncthreads();
    }

    // epilogue: c0=(g,2tg), c1=(g,2tg+1), c2=(g+8,2tg), c3=(g+8,2tg+1)
#pragma unroll
    for (int mt = 0; mt < 4; mt++) {
#pragma unroll
        for (int nt = 0; nt < 8; nt++) {
            int col = bn0 + warp_n*64 + nt*8 + 2*tg;
#pragma unroll
            for (int half = 0; half < 2; half++) {
                int lr = warp_m*64 + mt*16 + g + half*8;
                int grow = bm0 + lr;
                if (grow >= mrows) continue;
                long cr = rbase + grow;
                float v0 = acc[mt][nt][half*2+0];
                float v1 = acc[mt][nt][half*2+1];
                long o0 = cr*(long)ldc + col;
                if (EPI == 0) {
                    C[o0] = v0; C[o0+1] = v1;
                } else if (EPI == 1) {
                    C[o0]   = extra[o0]   + v0;
                    C[o0+1] = extra[o0+1] + v1;
                } else if (EPI == 2) {
                    float g0 = C[o0], g1 = C[o0+1];
                    C[o0]   = tf32r(g0 / (1.f + expf(-g0)) * v0);
                    C[o0+1] = tf32r(g1 / (1.f + expf(-g1)) * v1);
                } else if (EPI == 3) {
                    float s = extra[grow];
                    C[o0]   += v0 * s;
                    C[o0+1] += v1 * s;
                }
            }
        }
    }
}

// ---------------- router ----------------
__global__ void router_k(const float* __restrict__ x2, const float* __restrict__ Wr,
                         int* __restrict__ topi, float* __restrict__ topw)
{
    int t = blockIdx.x;
    __shared__ float xs[HID];
    __shared__ float pr[NEXP];
    for (int i = threadIdx.x; i < HID; i += blockDim.x) xs[i] = x2[(long)t*HID + i];
    __syncthreads();
    if (threadIdx.x < NEXP) {
        int e = threadIdx.x;
        float d = 0.f;
        for (int i = 0; i < HID; i++) d += xs[i] * Wr[i*NEXP + e];
        pr[e] = d;
    }
    __syncthreads();
    if (threadIdx.x == 0) {
        float mx = -1e30f;
        for (int e = 0; e < NEXP; e++) mx = fmaxf(mx, pr[e]);
        float p[NEXP]; float sm2 = 0.f;
        for (int e = 0; e < NEXP; e++) { p[e] = expf(pr[e]-mx); sm2 += p[e]; }
        for (int e = 0; e < NEXP; e++) p[e] /= sm2;
        float tw = 0.f;
        int   idx[TOPK]; float val[TOPK];
        for (int kk = 0; kk < TOPK; kk++) {
            int bi = 0; float bv = -1.f;
            for (int e = 0; e < NEXP; e++) if (p[e] > bv) { bv = p[e]; bi = e; }
            idx[kk] = bi; val[kk] = bv; p[bi] = -2.f; tw += bv;
        }
        for (int kk = 0; kk < TOPK; kk++) {
            topi[t*TOPK+kk] = idx[kk];
            topw[t*TOPK+kk] = val[kk] / tw;
        }
    }
}

// ---------------- routing build ----------------
__global__ void zero32_k(int* cnt) { if (threadIdx.x < NEXP) cnt[threadIdx.x] = 0; }
__global__ void count_k(const int* __restrict__ topi, int* __restrict__ cnt)
{
    int i = blockIdx.x*256 + threadIdx.x;
    if (i < T_TOK*TOPK) atomicAdd(&cnt[topi[i]], 1);
}
__global__ void scan_k(const int* __restrict__ cnt, int* __restrict__ off, int* __restrict__ cur)
{
    if (threadIdx.x == 0) {
        int a = 0;
        for (int e = 0; e < NEXP; e++) { off[e] = a; cur[e] = a; a += cnt[e]; }
        off[NEXP] = a;
    }
}
__global__ void fill_k(const int* __restrict__ topi, int* __restrict__ cur,
                       int* __restrict__ ptok, int* __restrict__ ppos)
{
    int i = blockIdx.x*256 + threadIdx.x;
    if (i < T_TOK*TOPK) {
        int e = topi[i];
        int p = atomicAdd(&cur[e], 1);
        ptok[p] = i / TOPK;
        ppos[i] = p;
    }
}

// ---------------- MoE reduction ----------------
__global__ void moe_reduce_k(const float* __restrict__ down, const int* __restrict__ ppos,
                             const float* __restrict__ topw, const float* __restrict__ h,
                             float* __restrict__ out)
{
    int t = blockIdx.x;
    int pos[TOPK]; float w[TOPK];
#pragma unroll
    for (int kk = 0; kk < TOPK; kk++) { pos[kk] = ppos[t*TOPK+kk]; w[kk] = topw[t*TOPK+kk]; }
    for (int c = threadIdx.x; c < HID; c += blockDim.x) {
        float s = h[(long)t*HID + c];
#pragma unroll
        for (int kk = 0; kk < TOPK; kk++) s += down[(long)pos[kk]*HID + c] * w[kk];
        out[(long)t*HID + c] = s;
    }
}

// ---------------- shared-expert sigmoid gate ----------------
__global__ void shgate_k(const float* __restrict__ x2, const float* __restrict__ w,
                         float* __restrict__ sig)
{
    int t = blockIdx.x;
    float s = 0.f;
    for (int i = threadIdx.x; i < HID; i += blockDim.x) s += x2[(long)t*HID + i] * w[i];
    __shared__ float red[32];
    for (int o = 16; o > 0; o >>= 1) s += __shfl_xor_sync(0xffffffffu, s, o);
    int warp = threadIdx.x >> 5, lane = threadIdx.x & 31;
    if (lane == 0) red[warp] = s;
    __syncthreads();
    if (warp == 0) {
        s = (lane < (blockDim.x >> 5)) ? red[lane] : 0.f;
        for (int o = 16; o > 0; o >>= 1) s += __shfl_xor_sync(0xffffffffu, s, o);
        if (lane == 0) sig[t] = 1.f / (1.f + expf(-s));
    }
}

// ---------------- host launch ----------------
extern "C" void kernel_launch(void* const* d_in, const int* in_sizes, int n_in,
                              void* d_out, int out_size)
{
    (void)in_sizes; (void)out_size;
    if (n_in < 17) return;
    const float* hidden = (const float*)d_in[0];
    const float* ln1    = (const float*)d_in[1];
    const float* ln2    = (const float*)d_in[2];
    const float* qnw    = (const float*)d_in[3];
    const float* knw    = (const float*)d_in[4];
    const float* Wq     = (const float*)d_in[5];
    const float* Wk     = (const float*)d_in[6];
    const float* Wv     = (const float*)d_in[7];
    const float* Wo     = (const float*)d_in[8];
    const float* Wr     = (const float*)d_in[9];
    const float* Weg    = (const float*)d_in[10];
    const float* Weu    = (const float*)d_in[11];
    const float* Wed    = (const float*)d_in[12];
    const float* Wsg    = (const float*)d_in[13];
    const float* Wsu    = (const float*)d_in[14];
    const float* Wsd    = (const float*)d_in[15];
    const float* Wshg   = (const float*)d_in[16];
    float* out = (float*)d_out;

    float *xn, *xnr, *qkv, *shb, *att, *hb, *act, *down, *cosT, *sinT, *topw, *sig;
    int *topi, *cnt, *off, *cur, *ptok, *ppos;
    float *Wqkv, *WoC, *WegC, *WeuC, *WedC, *WsgC, *WsuC, *WsdC;
    cudaGetSymbolAddress((void**)&xn,   g_xn);
    cudaGetSymbolAddress((void**)&xnr,  g_xnr);
    cudaGetSymbolAddress((void**)&qkv,  g_qkv);
    cudaGetSymbolAddress((void**)&shb,  g_sh);
    cudaGetSymbolAddress((void**)&att,  g_att);
    cudaGetSymbolAddress((void**)&hb,   g_h);
    cudaGetSymbolAddress((void**)&act,  g_act);
    cudaGetSymbolAddress((void**)&down, g_down);
    cudaGetSymbolAddress((void**)&cosT, g_cos);
    cudaGetSymbolAddress((void**)&sinT, g_sin);
    cudaGetSymbolAddress((void**)&topi, g_topi);
    cudaGetSymbolAddress((void**)&topw, g_topw);
    cudaGetSymbolAddress((void**)&cnt,  g_cnt);
    cudaGetSymbolAddress((void**)&off,  g_off);
    cudaGetSymbolAddress((void**)&cur,  g_cur);
    cudaGetSymbolAddress((void**)&ptok, g_ptok);
    cudaGetSymbolAddress((void**)&ppos, g_ppos);
    cudaGetSymbolAddress((void**)&sig,  g_sig);
    cudaGetSymbolAddress((void**)&Wqkv, g_Wqkv);
    cudaGetSymbolAddress((void**)&WoC,  g_WoC);
    cudaGetSymbolAddress((void**)&WegC, g_WegC);
    cudaGetSymbolAddress((void**)&WeuC, g_WeuC);
    cudaGetSymbolAddress((void**)&WedC, g_WedC);
    cudaGetSymbolAddress((void**)&WsgC, g_WsgC);
    cudaGetSymbolAddress((void**)&WsuC, g_WsuC);
    cudaGetSymbolAddress((void**)&WsdC, g_WsdC);

    cudaFuncSetAttribute(flash_k, cudaFuncAttributeMaxDynamicSharedMemorySize, FLASH_SMEM_BYTES);
    cudaFuncSetAttribute(mm2_k<0,false,false>, cudaFuncAttributeMaxDynamicSharedMemorySize, MM2_SMEM_BYTES);
    cudaFuncSetAttribute(mm2_k<1,false,false>, cudaFuncAttributeMaxDynamicSharedMemorySize, MM2_SMEM_BYTES);
    cudaFuncSetAttribute(mm2_k<2,false,false>, cudaFuncAttributeMaxDynamicSharedMemorySize, MM2_SMEM_BYTES);
    cudaFuncSetAttribute(mm2_k<3,false,false>, cudaFuncAttributeMaxDynamicSharedMemorySize, MM2_SMEM_BYTES);
    cudaFuncSetAttribute(mm2_k<0,true,true>,   cudaFuncAttributeMaxDynamicSharedMemorySize, MM2_SMEM_BYTES);
    cudaFuncSetAttribute(mm2_k<2,true,true>,   cudaFuncAttributeMaxDynamicSharedMemorySize, MM2_SMEM_BYTES);
    cudaFuncSetAttribute(mm2_k<0,false,true>,  cudaFuncAttributeMaxDynamicSharedMemorySize, MM2_SMEM_BYTES);

    // --- weight conversion (tf32 rounding), once per launch ---
    cvt_qkv_k<<<2048, 256>>>(Wq, Wk, Wv, Wqkv);
    cvt_k<<<2048, 256>>>(Wo,  WoC,  (long)NHEAD*HDIM*HID/4);
    cvt_k<<<4096, 256>>>(Weg, WegC, (long)NEXP*HID*EI/4);
    cvt_k<<<4096, 256>>>(Weu, WeuC, (long)NEXP*HID*EI/4);
    cvt_k<<<4096, 256>>>(Wed, WedC, (long)NEXP*EI*HID/4);
    cvt_k<<<2048, 256>>>(Wsg, WsgC, (long)HID*SI/4);
    cvt_k<<<2048, 256>>>(Wsu, WsuC, (long)HID*SI/4);
    cvt_k<<<2048, 256>>>(Wsd, WsdC, (long)SI*HID/4);

    // --- attention block ---
    rmsnorm_k<<<T_TOK, 256>>>(hidden, ln1, xn, xnr);

    // fused QKV GEMM: [T,2048] @ [2048,5120]
    mm2_k<0,false,false><<<dim3(QKVN/128, 32), 128, MM2_SMEM_BYTES>>>(T_TOK, QKVN, HID, xnr, HID, Wqkv, QKVN, 0, qkv, QKVN, nullptr, nullptr, nullptr);

    rope_tab_k<<<SEQ, HDIM/2>>>(cosT, sinT);
    qknr_k<<<T_TOK*NHEAD, HDIM>>>(qkv, qnw, NHEAD, 0, cosT, sinT);
    qknr_k<<<T_TOK*NKVH,  HDIM>>>(qkv, knw, NKVH, NHEAD*HDIM, cosT, sinT);

    flash_k<<<dim3(SEQ/64, NHEAD, BATCH), 256, FLASH_SMEM_BYTES>>>(qkv, att);

    // h = hidden + att @ Wo
    mm2_k<1,false,false><<<dim3(16, 32), 128, MM2_SMEM_BYTES>>>(T_TOK, HID, NHEAD*HDIM, att, NHEAD*HDIM, WoC, HID, 0, hb, HID, nullptr, nullptr, hidden);

    // --- MoE block ---
    rmsnorm_k<<<T_TOK, 256>>>(hb, ln2, xn, xnr);

    router_k<<<T_TOK, 128>>>(xn, Wr, topi, topw);
    zero32_k<<<1, 32>>>(cnt);
    count_k<<<(T_TOK*TOPK+255)/256, 256>>>(topi, cnt);
    scan_k<<<1, 32>>>(cnt, off, cur);
    fill_k<<<(T_TOK*TOPK+255)/256, 256>>>(topi, cur, ptok, ppos);

    // experts: gate, up(silu*), down
    mm2_k<0,true,true><<<dim3(EI/128, 32, NEXP), 128, MM2_SMEM_BYTES>>>(0, EI, HID, xnr, HID, WegC, EI, (long)HID*EI, act, EI, off, ptok, nullptr);
    mm2_k<2,true,true><<<dim3(EI/128, 32, NEXP), 128, MM2_SMEM_BYTES>>>(0, EI, HID, xnr, HID, WeuC, EI, (long)HID*EI, act, EI, off, ptok, nullptr);
    mm2_k<0,false,true><<<dim3(HID/128, 32, NEXP), 128, MM2_SMEM_BYTES>>>(0, HID, EI, act, EI, WedC, HID, (long)EI*HID, down, HID, off, nullptr, nullptr);

    moe_reduce_k<<<T_TOK, 256>>>(down, ppos, topw, hb, out);

    // --- shared expert ---
    mm2_k<0,false,false><<<dim3(SI/128, 32), 128, MM2_SMEM_BYTES>>>(T_TOK, SI, HID, xnr, HID, WsgC, SI, 0, shb, SI, nullptr, nullptr, nullptr);
    mm2_k<2,false,false><<<dim3(SI/128, 32), 128, MM2_SMEM_BYTES>>>(T_TOK, SI, HID, xnr, HID, WsuC, SI, 0, shb, SI, nullptr, nullptr, nullptr);
    shgate_k<<<T_TOK, 256>>>(xn, Wshg, sig);
    mm2_k<3,false,false><<<dim3(HID/128, 32), 128, MM2_SMEM_BYTES>>>(T_TOK, HID, SI, shb, SI, WsdC, HID, 0, out, HID, nullptr, nullptr, sig);
}

// round 6
// speedup vs baseline: 3.3928x; 1.1664x over previous
#include <cuda_runtime.h>
#include <math.h>
#include <stdint.h>

// ---------------- problem constants ----------------
#define T_TOK 4096
#define HID   2048
#define SEQ   1024
#define BATCH 4
#define NHEAD 32
#define NKVH  4
#define HDIM  128
#define NEXP  32
#define TOPK  8
#define EI    768
#define SI    4096
#define GQA   8
#define EPSV  1e-6f
#define QKVN  (NHEAD*HDIM + 2*NKVH*HDIM)   // 5120

// ---------------- scratch ----------------
__device__ float g_xn  [T_TOK*HID];
__device__ float g_xnr [T_TOK*HID];           // tf32-rounded rmsnorm output (GEMM A)
__device__ float g_qkv [T_TOK*QKVN];          // packed q|k|v
__device__ float g_sh  [T_TOK*SI];            // shared-expert intermediate
__device__ float g_att [T_TOK*NHEAD*HDIM];
__device__ float g_h   [T_TOK*HID];
__device__ float g_act [T_TOK*TOPK*EI];
__device__ float g_down[T_TOK*TOPK*HID];
__device__ float g_cos[SEQ*(HDIM/2)];
__device__ float g_sin[SEQ*(HDIM/2)];
__device__ int   g_topi[T_TOK*TOPK];
__device__ float g_topw[T_TOK*TOPK];
__device__ int   g_cnt[NEXP];
__device__ int   g_off[NEXP+1];
__device__ int   g_cur[NEXP];
__device__ int   g_ptok[T_TOK*TOPK];
__device__ int   g_ppos[T_TOK*TOPK];
__device__ float g_sig[T_TOK];
// tf32-rounded weight copies
__device__ float g_Wqkv[HID*QKVN];
__device__ float g_WoC [NHEAD*HDIM*HID];
__device__ float g_WegC[NEXP*HID*EI];
__device__ float g_WeuC[NEXP*HID*EI];
__device__ float g_WedC[NEXP*EI*HID];
__device__ float g_WsgC[HID*SI];
__device__ float g_WsuC[HID*SI];
__device__ float g_WsdC[SI*HID];

// ---------------- helpers ----------------
__device__ __forceinline__ float tf32r(float x)
{
    uint32_t u;
    asm("cvt.rna.tf32.f32 %0, %1;" : "=r"(u) : "f"(x));
    return __uint_as_float(u);
}
__device__ __forceinline__ uint32_t smem_u32(const void* p){
    uint32_t a;
    asm("{ .reg .u64 t; cvta.to.shared.u64 t, %1; cvt.u32.u64 %0, t; }" : "=r"(a) : "l"(p));
    return a;
}
__device__ __forceinline__ void cp_async16(uint32_t saddr, const void* gaddr, uint32_t sz){
    asm volatile("cp.async.cg.shared.global [%0], [%1], 16, %2;"
        :: "r"(saddr), "l"(gaddr), "r"(sz) : "memory");
}
__device__ __forceinline__ void cp_commit(){
    asm volatile("cp.async.commit_group;" ::: "memory");
}
template<int N>
__device__ __forceinline__ void cp_wait(){
    asm volatile("cp.async.wait_group %0;" :: "n"(N) : "memory");
}
__device__ __forceinline__ void mma_tf32(float* c, float a0, float a1, float a2, float a3,
                                         float b0, float b1)
{
    uint32_t ua0 = __float_as_uint(a0), ua1 = __float_as_uint(a1);
    uint32_t ua2 = __float_as_uint(a2), ua3 = __float_as_uint(a3);
    uint32_t ub0 = __float_as_uint(b0), ub1 = __float_as_uint(b1);
    asm volatile("mma.sync.aligned.m16n8k8.row.col.f32.tf32.tf32.f32 "
        "{%0,%1,%2,%3}, {%4,%5,%6,%7}, {%8,%9}, {%0,%1,%2,%3};"
        : "+f"(c[0]), "+f"(c[1]), "+f"(c[2]), "+f"(c[3])
        : "r"(ua0), "r"(ua1), "r"(ua2), "r"(ua3), "r"(ub0), "r"(ub1));
}

// ---------------- weight conversion (tf32 round, elementwise) ----------------
__global__ void cvt_k(const float* __restrict__ src, float* __restrict__ dst, long n4)
{
    long i = (long)blockIdx.x*blockDim.x + threadIdx.x;
    long stride = (long)gridDim.x*blockDim.x;
    for (; i < n4; i += stride) {
        float4 v = reinterpret_cast<const float4*>(src)[i];
        v.x = tf32r(v.x); v.y = tf32r(v.y); v.z = tf32r(v.z); v.w = tf32r(v.w);
        reinterpret_cast<float4*>(dst)[i] = v;
    }
}
// pack Wq|Wk|Wv (each [HID, n]) into [HID, 5120] with tf32 rounding
__global__ void cvt_qkv_k(const float* __restrict__ Wq, const float* __restrict__ Wk,
                          const float* __restrict__ Wv, float* __restrict__ dst)
{
    long n4 = (long)HID*QKVN/4;
    long i = (long)blockIdx.x*blockDim.x + threadIdx.x;
    long stride = (long)gridDim.x*blockDim.x;
    for (; i < n4; i += stride) {
        long e = i*4;
        int k = (int)(e / QKVN);
        int c = (int)(e % QKVN);
        float4 v;
        if (c < NHEAD*HDIM)          v = *reinterpret_cast<const float4*>(Wq + (long)k*(NHEAD*HDIM) + c);
        else if (c < NHEAD*HDIM+NKVH*HDIM) v = *reinterpret_cast<const float4*>(Wk + (long)k*(NKVH*HDIM) + (c - NHEAD*HDIM));
        else                          v = *reinterpret_cast<const float4*>(Wv + (long)k*(NKVH*HDIM) + (c - NHEAD*HDIM - NKVH*HDIM));
        v.x = tf32r(v.x); v.y = tf32r(v.y); v.z = tf32r(v.z); v.w = tf32r(v.w);
        reinterpret_cast<float4*>(dst)[i] = v;
    }
}

// ---------------- rmsnorm over HID (writes full + tf32-rounded) ----------------
__global__ void rmsnorm_k(const float* __restrict__ x, const float* __restrict__ w,
                          float* __restrict__ y, float* __restrict__ yr)
{
    int row = blockIdx.x;
    const float* xr = x + (long)row*HID;
    float ss = 0.f;
    for (int i = threadIdx.x; i < HID; i += blockDim.x) { float v = xr[i]; ss += v*v; }
    __shared__ float red[32];
    for (int o = 16; o > 0; o >>= 1) ss += __shfl_xor_sync(0xffffffffu, ss, o);
    int warp = threadIdx.x >> 5, lane = threadIdx.x & 31;
    if (lane == 0) red[warp] = ss;
    __syncthreads();
    if (warp == 0) {
        ss = (lane < (blockDim.x >> 5)) ? red[lane] : 0.f;
        for (int o = 16; o > 0; o >>= 1) ss += __shfl_xor_sync(0xffffffffu, ss, o);
        if (lane == 0) red[0] = ss;
    }
    __syncthreads();
    float r = rsqrtf(red[0] / (float)HID + EPSV);
    for (int i = threadIdx.x; i < HID; i += blockDim.x) {
        float v = xr[i] * r * w[i];
        y [(long)row*HID + i] = v;
        yr[(long)row*HID + i] = tf32r(v);
    }
}

// ---------------- rope tables ----------------
__global__ void rope_tab_k(float* __restrict__ cosT, float* __restrict__ sinT)
{
    int s = blockIdx.x;
    int i = threadIdx.x;
    float inv = expf(-((float)(2*i) / (float)HDIM) * logf(1000000.0f));
    float ang = (float)s * inv;
    cosT[s*(HDIM/2)+i] = cosf(ang);
    sinT[s*(HDIM/2)+i] = sinf(ang);
}

// ---------------- per-head rmsnorm + rope on packed qkv ----------------
__global__ void qknr_k(float* __restrict__ qkv, const float* __restrict__ nw, int nh, int colOff,
                       int doRound,
                       const float* __restrict__ cosT, const float* __restrict__ sinT)
{
    long bh = blockIdx.x;
    int t = (int)(bh / nh);
    int head = (int)(bh % nh);
    int s = t & (SEQ-1);
    int d = threadIdx.x;
    float* xp = qkv + (long)t*QKVN + colOff + head*HDIM;
    float v = xp[d];
    float ss = v*v;
    for (int o = 16; o > 0; o >>= 1) ss += __shfl_xor_sync(0xffffffffu, ss, o);
    __shared__ float red[4];
    if ((threadIdx.x & 31) == 0) red[threadIdx.x >> 5] = ss;
    __syncthreads();
    float tot = red[0]+red[1]+red[2]+red[3];
    float r = rsqrtf(tot / (float)HDIM + EPSV);
    float xn = v * r * nw[d];
    __shared__ float xsh[HDIM];
    xsh[d] = xn;
    __syncthreads();
    float c, sn, oth;
    if (d < HDIM/2) { c = cosT[s*(HDIM/2)+d];          sn = sinT[s*(HDIM/2)+d];          oth = -xsh[d+HDIM/2]; }
    else            { c = cosT[s*(HDIM/2)+d-HDIM/2];   sn = sinT[s*(HDIM/2)+d-HDIM/2];   oth =  xsh[d-HDIM/2]; }
    float val = xn*c + oth*sn;
    xp[d] = doRound ? tf32r(val) : val;
}

// ---------------- round V slice in place (tf32) ----------------
__global__ void vround_k(float* __restrict__ qkv)
{
    long t = blockIdx.x;
    float4* p = reinterpret_cast<float4*>(qkv + t*QKVN + NHEAD*HDIM + NKVH*HDIM);
    for (int i = threadIdx.x; i < NKVH*HDIM/4; i += blockDim.x) {
        float4 v = p[i];
        v.x = tf32r(v.x); v.y = tf32r(v.y); v.z = tf32r(v.z); v.w = tf32r(v.w);
        p[i] = v;
    }
}

// ---------------- tensor-core flash attention (tf32 mma, online softmax) ----------------
// 64x64 tiles, 4 warps x 16 q-rows; Q frags in regs; K/V via cp.async; P through smem.
// smem floats: Ks[64][132]=8448, Vs[64][136]=8704, Ps[64][68]=4352  -> 86016 B
#define FLASH2_SMEM_BYTES ((8448 + 8704 + 4352)*4)

__global__ void __launch_bounds__(128)
flash_tc_k(const float* __restrict__ qkv, float* __restrict__ og)
{
    extern __shared__ float fs[];
    float* Ks = fs;
    float* Vs = fs + 8448;
    float* Ps = fs + 17152;
    uint32_t sb = smem_u32(fs);
    uint32_t KsU = sb;
    uint32_t VsU = sb + 8448u*4;

    int qt = blockIdx.x, h = blockIdx.y, b = blockIdx.z;
    int kvh = h / GQA;
    int qs0 = qt*64;
    int tid = threadIdx.x, w = tid >> 5, lane = tid & 31;
    int g = lane >> 2, tg = lane & 3;
    float scale = rsqrtf((float)HDIM);

    // Q fragments in registers (scaled + tf32-rounded)
    float qa[16][4];
    {
        const float* q0 = qkv + (long)(b*SEQ + qs0 + w*16 + g)*QKVN + h*HDIM;
        const float* q8 = q0 + 8L*QKVN;
#pragma unroll
        for (int ks = 0; ks < 16; ks++) {
            int kb = ks*8;
            qa[ks][0] = tf32r(q0[kb+tg]*scale);
            qa[ks][1] = tf32r(q8[kb+tg]*scale);
            qa[ks][2] = tf32r(q0[kb+tg+4]*scale);
            qa[ks][3] = tf32r(q8[kb+tg+4]*scale);
        }
    }

    float m0 = -1e30f, m1 = -1e30f, l0 = 0.f, l1 = 0.f;
    float oac[16][4];
#pragma unroll
    for (int nt = 0; nt < 16; nt++)
#pragma unroll
        for (int r = 0; r < 4; r++) oac[nt][r] = 0.f;

    long kbase = (long)(b*SEQ)*QKVN + NHEAD*HDIM + kvh*HDIM;
    long vbase = kbase + (long)NKVH*HDIM;
    int pr0 = (w*16+g)*68, pr1 = (w*16+g+8)*68;

    for (int jt = 0; jt <= qt; jt++) {
        __syncthreads();                       // smem buffers free for reuse
        {
            long kr = kbase + (long)(jt*64)*QKVN;
#pragma unroll
            for (int i = 0; i < 16; i++) {
                int idx = i*128 + tid;
                int r = idx >> 5, c = idx & 31;
                cp_async16(KsU + (uint32_t)(r*132 + c*4)*4, qkv + kr + (long)r*QKVN + c*4, 16);
            }
            cp_commit();
            long vr = vbase + (long)(jt*64)*QKVN;
#pragma unroll
            for (int i = 0; i < 16; i++) {
                int idx = i*128 + tid;
                int r = idx >> 5, c = idx & 31;
                cp_async16(VsU + (uint32_t)(r*136 + c*4)*4, qkv + vr + (long)r*QKVN + c*4, 16);
            }
            cp_commit();
        }
        cp_wait<1>(); __syncthreads();          // K ready (V in flight)

        // S = Q K^T
        float sacc[8][4];
#pragma unroll
        for (int nt = 0; nt < 8; nt++)
#pragma unroll
            for (int r = 0; r < 4; r++) sacc[nt][r] = 0.f;
#pragma unroll
        for (int ks = 0; ks < 16; ks++) {
            int kb = ks*8;
#pragma unroll
            for (int nt = 0; nt < 8; nt++) {
                float b0 = Ks[(nt*8+g)*132 + kb+tg];
                float b1 = Ks[(nt*8+g)*132 + kb+tg+4];
                mma_tf32(sacc[nt], qa[ks][0], qa[ks][1], qa[ks][2], qa[ks][3], b0, b1);
            }
        }
        // causal mask (diagonal tile only)
        int row0 = qs0 + w*16 + g, row1 = row0 + 8;
        if (jt == qt) {
            int cb = jt*64;
#pragma unroll
            for (int nt = 0; nt < 8; nt++) {
                int c0 = cb + nt*8 + 2*tg;
                if (c0   > row0) sacc[nt][0] = -1e30f;
                if (c0+1 > row0) sacc[nt][1] = -1e30f;
                if (c0   > row1) sacc[nt][2] = -1e30f;
                if (c0+1 > row1) sacc[nt][3] = -1e30f;
            }
        }
        // online softmax
        float mx0 = m0, mx1 = m1;
#pragma unroll
        for (int nt = 0; nt < 8; nt++) {
            mx0 = fmaxf(mx0, fmaxf(sacc[nt][0], sacc[nt][1]));
            mx1 = fmaxf(mx1, fmaxf(sacc[nt][2], sacc[nt][3]));
        }
        mx0 = fmaxf(mx0, __shfl_xor_sync(0xffffffffu, mx0, 1));
        mx0 = fmaxf(mx0, __shfl_xor_sync(0xffffffffu, mx0, 2));
        mx1 = fmaxf(mx1, __shfl_xor_sync(0xffffffffu, mx1, 1));
        mx1 = fmaxf(mx1, __shfl_xor_sync(0xffffffffu, mx1, 2));
        float c0 = expf(m0 - mx0), c1 = expf(m1 - mx1);
        float s0 = 0.f, s1 = 0.f;
#pragma unroll
        for (int nt = 0; nt < 8; nt++) {
            sacc[nt][0] = expf(sacc[nt][0] - mx0);
            sacc[nt][1] = expf(sacc[nt][1] - mx0);
            sacc[nt][2] = expf(sacc[nt][2] - mx1);
            sacc[nt][3] = expf(sacc[nt][3] - mx1);
            s0 += sacc[nt][0] + sacc[nt][1];
            s1 += sacc[nt][2] + sacc[nt][3];
        }
        s0 += __shfl_xor_sync(0xffffffffu, s0, 1);
        s0 += __shfl_xor_sync(0xffffffffu, s0, 2);
        s1 += __shfl_xor_sync(0xffffffffu, s1, 1);
        s1 += __shfl_xor_sync(0xffffffffu, s1, 2);
        l0 = l0*c0 + s0;  l1 = l1*c1 + s1;  m0 = mx0;  m1 = mx1;
#pragma unroll
        for (int nt = 0; nt < 16; nt++) {
            oac[nt][0] *= c0; oac[nt][1] *= c0;
            oac[nt][2] *= c1; oac[nt][3] *= c1;
        }
        // write P (tf32-rounded)
#pragma unroll
        for (int nt = 0; nt < 8; nt++) {
            int pc = nt*8 + 2*tg;
            Ps[pr0+pc]   = tf32r(sacc[nt][0]);
            Ps[pr0+pc+1] = tf32r(sacc[nt][1]);
            Ps[pr1+pc]   = tf32r(sacc[nt][2]);
            Ps[pr1+pc+1] = tf32r(sacc[nt][3]);
        }
        cp_wait<0>(); __syncthreads();          // V ready + Ps visible

        // O += P V
#pragma unroll
        for (int ks = 0; ks < 8; ks++) {
            int kb = ks*8;
            float a0 = Ps[pr0 + kb+tg];
            float a1 = Ps[pr1 + kb+tg];
            float a2 = Ps[pr0 + kb+tg+4];
            float a3 = Ps[pr1 + kb+tg+4];
#pragma unroll
            for (int nt = 0; nt < 16; nt++) {
                float b0 = Vs[(kb+tg)*136 + nt*8+g];
                float b1 = Vs[(kb+tg+4)*136 + nt*8+g];
                mma_tf32(oac[nt], a0, a1, a2, a3, b0, b1);
            }
        }
    }

    float i0 = 1.f/l0, i1 = 1.f/l1;
    long o0 = ((long)(b*SEQ + qs0 + w*16 + g)*NHEAD + h)*HDIM;
    long o8 = o0 + 8L*NHEAD*HDIM;
#pragma unroll
    for (int nt = 0; nt < 16; nt++) {
        int c = nt*8 + 2*tg;
        og[o0+c]   = tf32r(oac[nt][0]*i0);
        og[o0+c+1] = tf32r(oac[nt][1]*i0);
        og[o8+c]   = tf32r(oac[nt][2]*i1);
        og[o8+c+1] = tf32r(oac[nt][3]*i1);
    }
}

// ---------------- tf32 mma.sync GEMM with cp.async double buffering ----------------
#define APITCH 36
#define BPITCH 136
#define ABUF_F (128*APITCH)
#define BBUF_F (32*BPITCH)
#define MM2_SMEM_BYTES (2*(ABUF_F + BBUF_F)*4)

template<int EPI, bool AIDX, bool EXPERT>
__global__ void __launch_bounds__(128)
mm2_k(int M, int N, int Kd,
      const float* __restrict__ A, int lda,
      const float* __restrict__ B, int ldb, long strideB,
      float* __restrict__ C, int ldc,
      const int* __restrict__ offs, const int* __restrict__ aidx,
      const float* __restrict__ extra)
{
    extern __shared__ float sm[];
    int rbase = 0, mrows = M;
    const float* Bp = B;
    if (EXPERT) {
        int e = blockIdx.z;
        rbase = offs[e];
        mrows = offs[e+1] - rbase;
        Bp = B + (long)e * strideB;
    }
    int bm0 = blockIdx.y * 128;
    if (bm0 >= mrows) return;
    int bn0 = blockIdx.x * 128;

    uint32_t sb = smem_u32(sm);
    uint32_t aS[2] = { sb, sb + (uint32_t)ABUF_F*4 };
    uint32_t bS[2] = { sb + (uint32_t)2*ABUF_F*4, sb + (uint32_t)(2*ABUF_F + BBUF_F)*4 };
    float* aF[2] = { sm, sm + ABUF_F };
    float* bF[2] = { sm + 2*ABUF_F, sm + 2*ABUF_F + BBUF_F };

    int tid = threadIdx.x, lane = tid & 31, wid = tid >> 5;
    int g = lane >> 2, tg = lane & 3;
    int warp_m = wid & 1, warp_n = wid >> 1;

    int rA = tid >> 3, cA = tid & 7;
    const char* apg[8];
    uint32_t asz[8], asmo[8];
#pragma unroll
    for (int i = 0; i < 8; i++) {
        int lr = bm0 + rA + 16*i;
        if (lr < mrows) {
            long gr = AIDX ? (long)aidx[rbase + lr] : (long)(rbase + lr);
            apg[i] = (const char*)(A + gr*(long)lda + cA*4);
            asz[i] = 16;
        } else { apg[i] = (const char*)A; asz[i] = 0; }
        asmo[i] = (uint32_t)((rA + 16*i)*APITCH + cA*4) * 4;
    }
    int cB = tid & 31;
    const char* bpg[8];
    uint32_t bsmo[8];
#pragma unroll
    for (int i = 0; i < 8; i++) {
        int kr = (tid >> 5) + 4*i;
        bpg[i] = (const char*)(Bp + (long)kr*ldb + bn0 + cB*4);
        bsmo[i] = (uint32_t)(kr*BPITCH + cB*4) * 4;
    }
    long bstep = (long)32*ldb*4;

    float acc[4][8][4];
#pragma unroll
    for (int mt = 0; mt < 4; mt++)
#pragma unroll
        for (int nt = 0; nt < 8; nt++)
#pragma unroll
            for (int r = 0; r < 4; r++) acc[mt][nt][r] = 0.f;

    int nc = Kd >> 5;
#pragma unroll
    for (int i = 0; i < 8; i++) cp_async16(aS[0] + asmo[i], apg[i], asz[i]);
#pragma unroll
    for (int i = 0; i < 8; i++) cp_async16(bS[0] + bsmo[i], bpg[i], 16);
    cp_commit();

    for (int c = 0; c < nc; c++) {
        int p = c & 1;
        if (c + 1 < nc) {
            int q = p ^ 1;
            long ka = (long)(c+1)*128;
            long kb2 = (long)(c+1)*bstep;
#pragma unroll
            for (int i = 0; i < 8; i++) cp_async16(aS[q] + asmo[i], apg[i] + ka, asz[i]);
#pragma unroll
            for (int i = 0; i < 8; i++) cp_async16(bS[q] + bsmo[i], bpg[i] + kb2, 16);
            cp_commit();
            cp_wait<1>();
        } else {
            cp_wait<0>();
        }
        __syncthreads();

        const float* Asf = aF[p];
        const float* Bsf = bF[p];
#pragma unroll
        for (int ks = 0; ks < 4; ks++) {
            int kb = ks*8;
            float a0[4], a1[4], a2[4], a3[4];
#pragma unroll
            for (int mt = 0; mt < 4; mt++) {
                int ra = warp_m*64 + mt*16 + g;
                a0[mt] = Asf[ra*APITCH + kb + tg];
                a1[mt] = Asf[(ra+8)*APITCH + kb + tg];
                a2[mt] = Asf[ra*APITCH + kb + tg + 4];
                a3[mt] = Asf[(ra+8)*APITCH + kb + tg + 4];
            }
            float b0[8], b1[8];
#pragma unroll
            for (int nt = 0; nt < 8; nt++) {
                int n = warp_n*64 + nt*8 + g;
                b0[nt] = Bsf[(kb+tg)*BPITCH + n];
                b1[nt] = Bsf[(kb+tg+4)*BPITCH + n];
            }
#pragma unroll
            for (int mt = 0; mt < 4; mt++)
#pragma unroll
                for (int nt = 0; nt < 8; nt++)
                    mma_tf32(acc[mt][nt], a0[mt], a1[mt], a2[mt], a3[mt], b0[nt], b1[nt]);
        }
        __syncthreads();
    }

#pragma unroll
    for (int mt = 0; mt < 4; mt++) {
#pragma unroll
        for (int nt = 0; nt < 8; nt++) {
            int col = bn0 + warp_n*64 + nt*8 + 2*tg;
#pragma unroll
            for (int half = 0; half < 2; half++) {
                int lr = warp_m*64 + mt*16 + g + half*8;
                int grow = bm0 + lr;
                if (grow >= mrows) continue;
                long cr = rbase + grow;
                float v0 = acc[mt][nt][half*2+0];
                float v1 = acc[mt][nt][half*2+1];
                long o0 = cr*(long)ldc + col;
                if (EPI == 0) {
                    C[o0] = v0; C[o0+1] = v1;
                } else if (EPI == 1) {
                    C[o0]   = extra[o0]   + v0;
                    C[o0+1] = extra[o0+1] + v1;
                } else if (EPI == 2) {
                    float g0 = C[o0], g1 = C[o0+1];
                    C[o0]   = tf32r(g0 / (1.f + expf(-g0)) * v0);
                    C[o0+1] = tf32r(g1 / (1.f + expf(-g1)) * v1);
                } else if (EPI == 3) {
                    float s = extra[grow];
                    C[o0]   += v0 * s;
                    C[o0+1] += v1 * s;
                }
            }
        }
    }
}

// ---------------- router ----------------
__global__ void router_k(const float* __restrict__ x2, const float* __restrict__ Wr,
                         int* __restrict__ topi, float* __restrict__ topw)
{
    int t = blockIdx.x;
    __shared__ float xs[HID];
    __shared__ float pr[NEXP];
    for (int i = threadIdx.x; i < HID; i += blockDim.x) xs[i] = x2[(long)t*HID + i];
    __syncthreads();
    if (threadIdx.x < NEXP) {
        int e = threadIdx.x;
        float d = 0.f;
        for (int i = 0; i < HID; i++) d += xs[i] * Wr[i*NEXP + e];
        pr[e] = d;
    }
    __syncthreads();
    if (threadIdx.x == 0) {
        float mx = -1e30f;
        for (int e = 0; e < NEXP; e++) mx = fmaxf(mx, pr[e]);
        float p[NEXP]; float sm2 = 0.f;
        for (int e = 0; e < NEXP; e++) { p[e] = expf(pr[e]-mx); sm2 += p[e]; }
        for (int e = 0; e < NEXP; e++) p[e] /= sm2;
        float tw = 0.f;
        int   idx[TOPK]; float val[TOPK];
        for (int kk = 0; kk < TOPK; kk++) {
            int bi = 0; float bv = -1.f;
            for (int e = 0; e < NEXP; e++) if (p[e] > bv) { bv = p[e]; bi = e; }
            idx[kk] = bi; val[kk] = bv; p[bi] = -2.f; tw += bv;
        }
        for (int kk = 0; kk < TOPK; kk++) {
            topi[t*TOPK+kk] = idx[kk];
            topw[t*TOPK+kk] = val[kk] / tw;
        }
    }
}

// ---------------- routing build ----------------
__global__ void zero32_k(int* cnt) { if (threadIdx.x < NEXP) cnt[threadIdx.x] = 0; }
__global__ void count_k(const int* __restrict__ topi, int* __restrict__ cnt)
{
    int i = blockIdx.x*256 + threadIdx.x;
    if (i < T_TOK*TOPK) atomicAdd(&cnt[topi[i]], 1);
}
__global__ void scan_k(const int* __restrict__ cnt, int* __restrict__ off, int* __restrict__ cur)
{
    if (threadIdx.x == 0) {
        int a = 0;
        for (int e = 0; e < NEXP; e++) { off[e] = a; cur[e] = a; a += cnt[e]; }
        off[NEXP] = a;
    }
}
__global__ void fill_k(const int* __restrict__ topi, int* __restrict__ cur,
                       int* __restrict__ ptok, int* __restrict__ ppos)
{
    int i = blockIdx.x*256 + threadIdx.x;
    if (i < T_TOK*TOPK) {
        int e = topi[i];
        int p = atomicAdd(&cur[e], 1);
        ptok[p] = i / TOPK;
        ppos[i] = p;
    }
}

// ---------------- MoE reduction ----------------
__global__ void moe_reduce_k(const float* __restrict__ down, const int* __restrict__ ppos,
                             const float* __restrict__ topw, const float* __restrict__ h,
                             float* __restrict__ out)
{
    int t = blockIdx.x;
    int pos[TOPK]; float w[TOPK];
#pragma unroll
    for (int kk = 0; kk < TOPK; kk++) { pos[kk] = ppos[t*TOPK+kk]; w[kk] = topw[t*TOPK+kk]; }
    for (int c = threadIdx.x; c < HID; c += blockDim.x) {
        float s = h[(long)t*HID + c];
#pragma unroll
        for (int kk = 0; kk < TOPK; kk++) s += down[(long)pos[kk]*HID + c] * w[kk];
        out[(long)t*HID + c] = s;
    }
}

// ---------------- shared-expert sigmoid gate ----------------
__global__ void shgate_k(const float* __restrict__ x2, const float* __restrict__ w,
                         float* __restrict__ sig)
{
    int t = blockIdx.x;
    float s = 0.f;
    for (int i = threadIdx.x; i < HID; i += blockDim.x) s += x2[(long)t*HID + i] * w[i];
    __shared__ float red[32];
    for (int o = 16; o > 0; o >>= 1) s += __shfl_xor_sync(0xffffffffu, s, o);
    int warp = threadIdx.x >> 5, lane = threadIdx.x & 31;
    if (lane == 0) red[warp] = s;
    __syncthreads();
    if (warp == 0) {
        s = (lane < (blockDim.x >> 5)) ? red[lane] : 0.f;
        for (int o = 16; o > 0; o >>= 1) s += __shfl_xor_sync(0xffffffffu, s, o);
        if (lane == 0) sig[t] = 1.f / (1.f + expf(-s));
    }
}

// ---------------- host launch ----------------
extern "C" void kernel_launch(void* const* d_in, const int* in_sizes, int n_in,
                              void* d_out, int out_size)
{
    (void)in_sizes; (void)out_size;
    if (n_in < 17) return;
    const float* hidden = (const float*)d_in[0];
    const float* ln1    = (const float*)d_in[1];
    const float* ln2    = (const float*)d_in[2];
    const float* qnw    = (const float*)d_in[3];
    const float* knw    = (const float*)d_in[4];
    const float* Wq     = (const float*)d_in[5];
    const float* Wk     = (const float*)d_in[6];
    const float* Wv     = (const float*)d_in[7];
    const float* Wo     = (const float*)d_in[8];
    const float* Wr     = (const float*)d_in[9];
    const float* Weg    = (const float*)d_in[10];
    const float* Weu    = (const float*)d_in[11];
    const float* Wed    = (const float*)d_in[12];
    const float* Wsg    = (const float*)d_in[13];
    const float* Wsu    = (const float*)d_in[14];
    const float* Wsd    = (const float*)d_in[15];
    const float* Wshg   = (const float*)d_in[16];
    float* out = (float*)d_out;

    float *xn, *xnr, *qkv, *shb, *att, *hb, *act, *down, *cosT, *sinT, *topw, *sig;
    int *topi, *cnt, *off, *cur, *ptok, *ppos;
    float *Wqkv, *WoC, *WegC, *WeuC, *WedC, *WsgC, *WsuC, *WsdC;
    cudaGetSymbolAddress((void**)&xn,   g_xn);
    cudaGetSymbolAddress((void**)&xnr,  g_xnr);
    cudaGetSymbolAddress((void**)&qkv,  g_qkv);
    cudaGetSymbolAddress((void**)&shb,  g_sh);
    cudaGetSymbolAddress((void**)&att,  g_att);
    cudaGetSymbolAddress((void**)&hb,   g_h);
    cudaGetSymbolAddress((void**)&act,  g_act);
    cudaGetSymbolAddress((void**)&down, g_down);
    cudaGetSymbolAddress((void**)&cosT, g_cos);
    cudaGetSymbolAddress((void**)&sinT, g_sin);
    cudaGetSymbolAddress((void**)&topi, g_topi);
    cudaGetSymbolAddress((void**)&topw, g_topw);
    cudaGetSymbolAddress((void**)&cnt,  g_cnt);
    cudaGetSymbolAddress((void**)&off,  g_off);
    cudaGetSymbolAddress((void**)&cur,  g_cur);
    cudaGetSymbolAddress((void**)&ptok, g_ptok);
    cudaGetSymbolAddress((void**)&ppos, g_ppos);
    cudaGetSymbolAddress((void**)&sig,  g_sig);
    cudaGetSymbolAddress((void**)&Wqkv, g_Wqkv);
    cudaGetSymbolAddress((void**)&WoC,  g_WoC);
    cudaGetSymbolAddress((void**)&WegC, g_WegC);
    cudaGetSymbolAddress((void**)&WeuC, g_WeuC);
    cudaGetSymbolAddress((void**)&WedC, g_WedC);
    cudaGetSymbolAddress((void**)&WsgC, g_WsgC);
    cudaGetSymbolAddress((void**)&WsuC, g_WsuC);
    cudaGetSymbolAddress((void**)&WsdC, g_WsdC);

    cudaFuncSetAttribute(flash_tc_k, cudaFuncAttributeMaxDynamicSharedMemorySize, FLASH2_SMEM_BYTES);
    cudaFuncSetAttribute(mm2_k<0,false,false>, cudaFuncAttributeMaxDynamicSharedMemorySize, MM2_SMEM_BYTES);
    cudaFuncSetAttribute(mm2_k<1,false,false>, cudaFuncAttributeMaxDynamicSharedMemorySize, MM2_SMEM_BYTES);
    cudaFuncSetAttribute(mm2_k<2,false,false>, cudaFuncAttributeMaxDynamicSharedMemorySize, MM2_SMEM_BYTES);
    cudaFuncSetAttribute(mm2_k<3,false,false>, cudaFuncAttributeMaxDynamicSharedMemorySize, MM2_SMEM_BYTES);
    cudaFuncSetAttribute(mm2_k<0,true,true>,   cudaFuncAttributeMaxDynamicSharedMemorySize, MM2_SMEM_BYTES);
    cudaFuncSetAttribute(mm2_k<2,true,true>,   cudaFuncAttributeMaxDynamicSharedMemorySize, MM2_SMEM_BYTES);
    cudaFuncSetAttribute(mm2_k<0,false,true>,  cudaFuncAttributeMaxDynamicSharedMemorySize, MM2_SMEM_BYTES);

    // --- weight conversion (tf32 rounding), once per launch ---
    cvt_qkv_k<<<2048, 256>>>(Wq, Wk, Wv, Wqkv);
    cvt_k<<<2048, 256>>>(Wo,  WoC,  (long)NHEAD*HDIM*HID/4);
    cvt_k<<<4096, 256>>>(Weg, WegC, (long)NEXP*HID*EI/4);
    cvt_k<<<4096, 256>>>(Weu, WeuC, (long)NEXP*HID*EI/4);
    cvt_k<<<4096, 256>>>(Wed, WedC, (long)NEXP*EI*HID/4);
    cvt_k<<<2048, 256>>>(Wsg, WsgC, (long)HID*SI/4);
    cvt_k<<<2048, 256>>>(Wsu, WsuC, (long)HID*SI/4);
    cvt_k<<<2048, 256>>>(Wsd, WsdC, (long)SI*HID/4);

    // --- attention block ---
    rmsnorm_k<<<T_TOK, 256>>>(hidden, ln1, xn, xnr);

    mm2_k<0,false,false><<<dim3(QKVN/128, 32), 128, MM2_SMEM_BYTES>>>(T_TOK, QKVN, HID, xnr, HID, Wqkv, QKVN, 0, qkv, QKVN, nullptr, nullptr, nullptr);

    rope_tab_k<<<SEQ, HDIM/2>>>(cosT, sinT);
    qknr_k<<<T_TOK*NHEAD, HDIM>>>(qkv, qnw, NHEAD, 0, 0, cosT, sinT);
    qknr_k<<<T_TOK*NKVH,  HDIM>>>(qkv, knw, NKVH, NHEAD*HDIM, 1, cosT, sinT);
    vround_k<<<T_TOK, 128>>>(qkv);

    flash_tc_k<<<dim3(SEQ/64, NHEAD, BATCH), 128, FLASH2_SMEM_BYTES>>>(qkv, att);

    // h = hidden + att @ Wo
    mm2_k<1,false,false><<<dim3(16, 32), 128, MM2_SMEM_BYTES>>>(T_TOK, HID, NHEAD*HDIM, att, NHEAD*HDIM, WoC, HID, 0, hb, HID, nullptr, nullptr, hidden);

    // --- MoE block ---
    rmsnorm_k<<<T_TOK, 256>>>(hb, ln2, xn, xnr);

    router_k<<<T_TOK, 128>>>(xn, Wr, topi, topw);
    zero32_k<<<1, 32>>>(cnt);
    count_k<<<(T_TOK*TOPK+255)/256, 256>>>(topi, cnt);
    scan_k<<<1, 32>>>(cnt, off, cur);
    fill_k<<<(T_TOK*TOPK+255)/256, 256>>>(topi, cur, ptok, ppos);

    // experts: gate, up(silu*), down
    mm2_k<0,true,true><<<dim3(EI/128, 32, NEXP), 128, MM2_SMEM_BYTES>>>(0, EI, HID, xnr, HID, WegC, EI, (long)HID*EI, act, EI, off, ptok, nullptr);
    mm2_k<2,true,true><<<dim3(EI/128, 32, NEXP), 128, MM2_SMEM_BYTES>>>(0, EI, HID, xnr, HID, WeuC, EI, (long)HID*EI, act, EI, off, ptok, nullptr);
    mm2_k<0,false,true><<<dim3(HID/128, 32, NEXP), 128, MM2_SMEM_BYTES>>>(0, HID, EI, act, EI, WedC, HID, (long)EI*HID, down, HID, off, nullptr, nullptr);

    moe_reduce_k<<<T_TOK, 256>>>(down, ppos, topw, hb, out);

    // --- shared expert ---
    mm2_k<0,false,false><<<dim3(SI/128, 32), 128, MM2_SMEM_BYTES>>>(T_TOK, SI, HID, xnr, HID, WsgC, SI, 0, shb, SI, nullptr, nullptr, nullptr);
    mm2_k<2,false,false><<<dim3(SI/128, 32), 128, MM2_SMEM_BYTES>>>(T_TOK, SI, HID, xnr, HID, WsuC, SI, 0, shb, SI, nullptr, nullptr, nullptr);
    shgate_k<<<T_TOK, 256>>>(xn, Wshg, sig);
    mm2_k<3,false,false><<<dim3(HID/128, 32), 128, MM2_SMEM_BYTES>>>(T_TOK, HID, SI, shb, SI, WsdC, HID, 0, out, HID, nullptr, nullptr, sig);
}

// round 7
// speedup vs baseline: 3.7264x; 1.0983x over previous
#include <cuda_runtime.h>
#include <cuda_fp16.h>
#include <math.h>
#include <stdint.h>

// ---------------- problem constants ----------------
#define T_TOK 4096
#define HID   2048
#define SEQ   1024
#define BATCH 4
#define NHEAD 32
#define NKVH  4
#define HDIM  128
#define NEXP  32
#define TOPK  8
#define EI    768
#define SI    4096
#define GQA   8
#define EPSV  1e-6f
#define QKVN  (NHEAD*HDIM + 2*NKVH*HDIM)   // 5120

// ---------------- scratch (fp32) ----------------
__device__ float g_xn  [T_TOK*HID];
__device__ float g_qkv [T_TOK*QKVN];
__device__ float g_h   [T_TOK*HID];
__device__ float g_actg[T_TOK*TOPK*EI];       // expert gate output (pre-silu)
__device__ float g_shg [T_TOK*SI];            // shared gate output
__device__ float g_down[T_TOK*TOPK*HID];
__device__ float g_cos[SEQ*(HDIM/2)];
__device__ float g_sin[SEQ*(HDIM/2)];
__device__ int   g_topi[T_TOK*TOPK];
__device__ float g_topw[T_TOK*TOPK];
__device__ int   g_cnt[NEXP];
__device__ int   g_off[NEXP+1];
__device__ int   g_cur[NEXP];
__device__ int   g_ptok[T_TOK*TOPK];
__device__ int   g_ppos[T_TOK*TOPK];
__device__ float g_sig[T_TOK];
// ---------------- scratch (fp16) ----------------
__device__ __half g_xh  [T_TOK*HID];          // fp16 rmsnorm output (GEMM A)
__device__ __half g_atth[T_TOK*NHEAD*HDIM];   // fp16 attention output
__device__ __half g_acth[T_TOK*TOPK*EI];      // fp16 activated expert intermediate
__device__ __half g_shh [T_TOK*SI];           // fp16 activated shared intermediate
// fp16 transposed weights [N][K]
__device__ __half g_Wqkv[QKVN*HID];
__device__ __half g_WoT [HID*NHEAD*HDIM];
__device__ __half g_WegT[(long)NEXP*EI*HID];
__device__ __half g_WeuT[(long)NEXP*EI*HID];
__device__ __half g_WedT[(long)NEXP*HID*EI];
__device__ __half g_WsgT[SI*HID];
__device__ __half g_WsuT[SI*HID];
__device__ __half g_WsdT[HID*SI];

// ---------------- helpers ----------------
__device__ __forceinline__ float tf32r(float x)
{
    uint32_t u;
    asm("cvt.rna.tf32.f32 %0, %1;" : "=r"(u) : "f"(x));
    return __uint_as_float(u);
}
__device__ __forceinline__ uint32_t smem_u32(const void* p){
    uint32_t a;
    asm("{ .reg .u64 t; cvta.to.shared.u64 t, %1; cvt.u32.u64 %0, t; }" : "=r"(a) : "l"(p));
    return a;
}
__device__ __forceinline__ void cp_async16(uint32_t saddr, const void* gaddr, uint32_t sz){
    asm volatile("cp.async.cg.shared.global [%0], [%1], 16, %2;"
        :: "r"(saddr), "l"(gaddr), "r"(sz) : "memory");
}
__device__ __forceinline__ void cp_commit(){
    asm volatile("cp.async.commit_group;" ::: "memory");
}
template<int N>
__device__ __forceinline__ void cp_wait(){
    asm volatile("cp.async.wait_group %0;" :: "n"(N) : "memory");
}
__device__ __forceinline__ void mma_tf32(float* c, float a0, float a1, float a2, float a3,
                                         float b0, float b1)
{
    uint32_t ua0 = __float_as_uint(a0), ua1 = __float_as_uint(a1);
    uint32_t ua2 = __float_as_uint(a2), ua3 = __float_as_uint(a3);
    uint32_t ub0 = __float_as_uint(b0), ub1 = __float_as_uint(b1);
    asm volatile("mma.sync.aligned.m16n8k8.row.col.f32.tf32.tf32.f32 "
        "{%0,%1,%2,%3}, {%4,%5,%6,%7}, {%8,%9}, {%0,%1,%2,%3};"
        : "+f"(c[0]), "+f"(c[1]), "+f"(c[2]), "+f"(c[3])
        : "r"(ua0), "r"(ua1), "r"(ua2), "r"(ua3), "r"(ub0), "r"(ub1));
}
__device__ __forceinline__ void mma_f16(float* c, uint32_t a0, uint32_t a1, uint32_t a2, uint32_t a3,
                                        uint32_t b0, uint32_t b1)
{
    asm volatile("mma.sync.aligned.m16n8k16.row.col.f32.f16.f16.f32 "
        "{%0,%1,%2,%3}, {%4,%5,%6,%7}, {%8,%9}, {%0,%1,%2,%3};"
        : "+f"(c[0]), "+f"(c[1]), "+f"(c[2]), "+f"(c[3])
        : "r"(a0), "r"(a1), "r"(a2), "r"(a3), "r"(b0), "r"(b1));
}

// ---------------- weight transpose + fp16 convert: src[K][N] -> dst[N][K] ----------------
__global__ void tcvt_k(const float* __restrict__ src, __half* __restrict__ dst, int K, int N)
{
    __shared__ float t[32][33];
    long z = blockIdx.z;
    src += z * (long)K * N;
    dst += z * (long)K * N;
    int n0 = blockIdx.x*32, k0 = blockIdx.y*32;
    int tx = threadIdx.x, ty = threadIdx.y;
#pragma unroll
    for (int i = 0; i < 32; i += 8)
        t[tx][ty+i] = src[(long)(k0+ty+i)*N + n0+tx];   // t[n][k]
    __syncthreads();
#pragma unroll
    for (int i = 0; i < 32; i += 8)
        dst[(long)(n0+ty+i)*K + k0+tx] = __float2half(t[ty+i][tx]);
}

// ---------------- rmsnorm over HID (writes fp32 + fp16) ----------------
__global__ void rmsnorm_k(const float* __restrict__ x, const float* __restrict__ w,
                          float* __restrict__ y, __half* __restrict__ yh)
{
    int row = blockIdx.x;
    const float* xr = x + (long)row*HID;
    float ss = 0.f;
    for (int i = threadIdx.x; i < HID; i += blockDim.x) { float v = xr[i]; ss += v*v; }
    __shared__ float red[32];
    for (int o = 16; o > 0; o >>= 1) ss += __shfl_xor_sync(0xffffffffu, ss, o);
    int warp = threadIdx.x >> 5, lane = threadIdx.x & 31;
    if (lane == 0) red[warp] = ss;
    __syncthreads();
    if (warp == 0) {
        ss = (lane < (blockDim.x >> 5)) ? red[lane] : 0.f;
        for (int o = 16; o > 0; o >>= 1) ss += __shfl_xor_sync(0xffffffffu, ss, o);
        if (lane == 0) red[0] = ss;
    }
    __syncthreads();
    float r = rsqrtf(red[0] / (float)HID + EPSV);
    for (int i = threadIdx.x; i < HID; i += blockDim.x) {
        float v = xr[i] * r * w[i];
        y [(long)row*HID + i] = v;
        yh[(long)row*HID + i] = __float2half(v);
    }
}

// ---------------- rope tables ----------------
__global__ void rope_tab_k(float* __restrict__ cosT, float* __restrict__ sinT)
{
    int s = blockIdx.x;
    int i = threadIdx.x;
    float inv = expf(-((float)(2*i) / (float)HDIM) * logf(1000000.0f));
    float ang = (float)s * inv;
    cosT[s*(HDIM/2)+i] = cosf(ang);
    sinT[s*(HDIM/2)+i] = sinf(ang);
}

// ---------------- per-head rmsnorm + rope on packed qkv ----------------
__global__ void qknr_k(float* __restrict__ qkv, const float* __restrict__ nw, int nh, int colOff,
                       int doRound,
                       const float* __restrict__ cosT, const float* __restrict__ sinT)
{
    long bh = blockIdx.x;
    int t = (int)(bh / nh);
    int head = (int)(bh % nh);
    int s = t & (SEQ-1);
    int d = threadIdx.x;
    float* xp = qkv + (long)t*QKVN + colOff + head*HDIM;
    float v = xp[d];
    float ss = v*v;
    for (int o = 16; o > 0; o >>= 1) ss += __shfl_xor_sync(0xffffffffu, ss, o);
    __shared__ float red[4];
    if ((threadIdx.x & 31) == 0) red[threadIdx.x >> 5] = ss;
    __syncthreads();
    float tot = red[0]+red[1]+red[2]+red[3];
    float r = rsqrtf(tot / (float)HDIM + EPSV);
    float xn = v * r * nw[d];
    __shared__ float xsh[HDIM];
    xsh[d] = xn;
    __syncthreads();
    float c, sn, oth;
    if (d < HDIM/2) { c = cosT[s*(HDIM/2)+d];          sn = sinT[s*(HDIM/2)+d];          oth = -xsh[d+HDIM/2]; }
    else            { c = cosT[s*(HDIM/2)+d-HDIM/2];   sn = sinT[s*(HDIM/2)+d-HDIM/2];   oth =  xsh[d-HDIM/2]; }
    float val = xn*c + oth*sn;
    xp[d] = doRound ? tf32r(val) : val;
}

// ---------------- round V slice in place (tf32) ----------------
__global__ void vround_k(float* __restrict__ qkv)
{
    long t = blockIdx.x;
    float4* p = reinterpret_cast<float4*>(qkv + t*QKVN + NHEAD*HDIM + NKVH*HDIM);
    for (int i = threadIdx.x; i < NKVH*HDIM/4; i += blockDim.x) {
        float4 v = p[i];
        v.x = tf32r(v.x); v.y = tf32r(v.y); v.z = tf32r(v.z); v.w = tf32r(v.w);
        p[i] = v;
    }
}

// ---------------- tensor-core flash attention (tf32 mma, online softmax), fp16 output ----------------
#define FLASH2_SMEM_BYTES ((8448 + 8704 + 4352)*4)

__global__ void __launch_bounds__(128)
flash_tc_k(const float* __restrict__ qkv, __half* __restrict__ og)
{
    extern __shared__ float fs[];
    float* Ks = fs;
    float* Vs = fs + 8448;
    float* Ps = fs + 17152;
    uint32_t sb = smem_u32(fs);
    uint32_t KsU = sb;
    uint32_t VsU = sb + 8448u*4;

    int qt = blockIdx.x, h = blockIdx.y, b = blockIdx.z;
    int kvh = h / GQA;
    int qs0 = qt*64;
    int tid = threadIdx.x, w = tid >> 5, lane = tid & 31;
    int g = lane >> 2, tg = lane & 3;
    float scale = rsqrtf((float)HDIM);

    float qa[16][4];
    {
        const float* q0 = qkv + (long)(b*SEQ + qs0 + w*16 + g)*QKVN + h*HDIM;
        const float* q8 = q0 + 8L*QKVN;
#pragma unroll
        for (int ks = 0; ks < 16; ks++) {
            int kb = ks*8;
            qa[ks][0] = tf32r(q0[kb+tg]*scale);
            qa[ks][1] = tf32r(q8[kb+tg]*scale);
            qa[ks][2] = tf32r(q0[kb+tg+4]*scale);
            qa[ks][3] = tf32r(q8[kb+tg+4]*scale);
        }
    }

    float m0 = -1e30f, m1 = -1e30f, l0 = 0.f, l1 = 0.f;
    float oac[16][4];
#pragma unroll
    for (int nt = 0; nt < 16; nt++)
#pragma unroll
        for (int r = 0; r < 4; r++) oac[nt][r] = 0.f;

    long kbase = (long)(b*SEQ)*QKVN + NHEAD*HDIM + kvh*HDIM;
    long vbase = kbase + (long)NKVH*HDIM;
    int pr0 = (w*16+g)*68, pr1 = (w*16+g+8)*68;

    for (int jt = 0; jt <= qt; jt++) {
        __syncthreads();
        {
            long kr = kbase + (long)(jt*64)*QKVN;
#pragma unroll
            for (int i = 0; i < 16; i++) {
                int idx = i*128 + tid;
                int r = idx >> 5, c = idx & 31;
                cp_async16(KsU + (uint32_t)(r*132 + c*4)*4, qkv + kr + (long)r*QKVN + c*4, 16);
            }
            cp_commit();
            long vr = vbase + (long)(jt*64)*QKVN;
#pragma unroll
            for (int i = 0; i < 16; i++) {
                int idx = i*128 + tid;
                int r = idx >> 5, c = idx & 31;
                cp_async16(VsU + (uint32_t)(r*136 + c*4)*4, qkv + vr + (long)r*QKVN + c*4, 16);
            }
            cp_commit();
        }
        cp_wait<1>(); __syncthreads();

        float sacc[8][4];
#pragma unroll
        for (int nt = 0; nt < 8; nt++)
#pragma unroll
            for (int r = 0; r < 4; r++) sacc[nt][r] = 0.f;
#pragma unroll
        for (int ks = 0; ks < 16; ks++) {
            int kb = ks*8;
#pragma unroll
            for (int nt = 0; nt < 8; nt++) {
                float b0 = Ks[(nt*8+g)*132 + kb+tg];
                float b1 = Ks[(nt*8+g)*132 + kb+tg+4];
                mma_tf32(sacc[nt], qa[ks][0], qa[ks][1], qa[ks][2], qa[ks][3], b0, b1);
            }
        }
        int row0 = qs0 + w*16 + g, row1 = row0 + 8;
        if (jt == qt) {
            int cb = jt*64;
#pragma unroll
            for (int nt = 0; nt < 8; nt++) {
                int c0 = cb + nt*8 + 2*tg;
                if (c0   > row0) sacc[nt][0] = -1e30f;
                if (c0+1 > row0) sacc[nt][1] = -1e30f;
                if (c0   > row1) sacc[nt][2] = -1e30f;
                if (c0+1 > row1) sacc[nt][3] = -1e30f;
            }
        }
        float mx0 = m0, mx1 = m1;
#pragma unroll
        for (int nt = 0; nt < 8; nt++) {
            mx0 = fmaxf(mx0, fmaxf(sacc[nt][0], sacc[nt][1]));
            mx1 = fmaxf(mx1, fmaxf(sacc[nt][2], sacc[nt][3]));
        }
        mx0 = fmaxf(mx0, __shfl_xor_sync(0xffffffffu, mx0, 1));
        mx0 = fmaxf(mx0, __shfl_xor_sync(0xffffffffu, mx0, 2));
        mx1 = fmaxf(mx1, __shfl_xor_sync(0xffffffffu, mx1, 1));
        mx1 = fmaxf(mx1, __shfl_xor_sync(0xffffffffu, mx1, 2));
        float c0 = expf(m0 - mx0), c1 = expf(m1 - mx1);
        float s0 = 0.f, s1 = 0.f;
#pragma unroll
        for (int nt = 0; nt < 8; nt++) {
            sacc[nt][0] = expf(sacc[nt][0] - mx0);
            sacc[nt][1] = expf(sacc[nt][1] - mx0);
            sacc[nt][2] = expf(sacc[nt][2] - mx1);
            sacc[nt][3] = expf(sacc[nt][3] - mx1);
            s0 += sacc[nt][0] + sacc[nt][1];
            s1 += sacc[nt][2] + sacc[nt][3];
        }
        s0 += __shfl_xor_sync(0xffffffffu, s0, 1);
        s0 += __shfl_xor_sync(0xffffffffu, s0, 2);
        s1 += __shfl_xor_sync(0xffffffffu, s1, 1);
        s1 += __shfl_xor_sync(0xffffffffu, s1, 2);
        l0 = l0*c0 + s0;  l1 = l1*c1 + s1;  m0 = mx0;  m1 = mx1;
#pragma unroll
        for (int nt = 0; nt < 16; nt++) {
            oac[nt][0] *= c0; oac[nt][1] *= c0;
            oac[nt][2] *= c1; oac[nt][3] *= c1;
        }
#pragma unroll
        for (int nt = 0; nt < 8; nt++) {
            int pc = nt*8 + 2*tg;
            Ps[pr0+pc]   = tf32r(sacc[nt][0]);
            Ps[pr0+pc+1] = tf32r(sacc[nt][1]);
            Ps[pr1+pc]   = tf32r(sacc[nt][2]);
            Ps[pr1+pc+1] = tf32r(sacc[nt][3]);
        }
        cp_wait<0>(); __syncthreads();

#pragma unroll
        for (int ks = 0; ks < 8; ks++) {
            int kb = ks*8;
            float a0 = Ps[pr0 + kb+tg];
            float a1 = Ps[pr1 + kb+tg];
            float a2 = Ps[pr0 + kb+tg+4];
            float a3 = Ps[pr1 + kb+tg+4];
#pragma unroll
            for (int nt = 0; nt < 16; nt++) {
                float b0 = Vs[(kb+tg)*136 + nt*8+g];
                float b1 = Vs[(kb+tg+4)*136 + nt*8+g];
                mma_tf32(oac[nt], a0, a1, a2, a3, b0, b1);
            }
        }
    }

    float i0 = 1.f/l0, i1 = 1.f/l1;
    long o0 = ((long)(b*SEQ + qs0 + w*16 + g)*NHEAD + h)*HDIM;
    long o8 = o0 + 8L*NHEAD*HDIM;
#pragma unroll
    for (int nt = 0; nt < 16; nt++) {
        int c = nt*8 + 2*tg;
        og[o0+c]   = __float2half(oac[nt][0]*i0);
        og[o0+c+1] = __float2half(oac[nt][1]*i0);
        og[o8+c]   = __float2half(oac[nt][2]*i1);
        og[o8+c+1] = __float2half(oac[nt][3]*i1);
    }
}

// ---------------- fp16 mma.sync GEMM, 3-stage cp.async pipeline ----------------
// C[M,N] = A[M,K] @ B^T where B stored [N][K] fp16.
// CTA tile 128x128x32; 4 warps (2x2), warp tile 64x64; m16n8k16.
// EPI: 0=store f32, 1=resid add(extra), 2=Ch = silu(extra)*acc (fp16 out), 3=C += acc*extra[row]
#define HPITCH 40                      // halves per smem row
#define TBUF_H (128*HPITCH)            // halves per tile buffer
#define STAGE_B (2*TBUF_H*2)           // bytes per stage (A+B)
#define NSTAGE 3
#define MMH_SMEM_BYTES (NSTAGE*STAGE_B)

template<int EPI, bool AIDX, bool EXPERT>
__global__ void __launch_bounds__(128)
mmh_k(int M, int N, int Kd,
      const __half* __restrict__ A, int lda,
      const __half* __restrict__ B, long strideB,
      float* __restrict__ C, __half* __restrict__ Ch, int ldc,
      const int* __restrict__ offs, const int* __restrict__ aidx,
      const float* __restrict__ extra)
{
    extern __shared__ __align__(16) char smh[];
    __half* st = reinterpret_cast<__half*>(smh);
    uint32_t sb = smem_u32(smh);

    int rbase = 0, mrows = M;
    const __half* Bp = B;
    if (EXPERT) {
        int e = blockIdx.z;
        rbase = offs[e];
        mrows = offs[e+1] - rbase;
        Bp = B + (long)e * strideB;
    }
    int bm0 = blockIdx.y * 128;
    if (bm0 >= mrows) return;
    int bn0 = blockIdx.x * 128;

    int tid = threadIdx.x, lane = tid & 31, wid = tid >> 5;
    int g = lane >> 2, tg = lane & 3;
    int warp_m = wid & 1, warp_n = wid >> 1;

    // one A row + one B row per thread, 4x16B segments per chunk
    const char* aptr;
    uint32_t aok;
    {
        int lr = bm0 + tid;
        if (lr < mrows) {
            long gr = AIDX ? (long)aidx[rbase + lr] : (long)(rbase + lr);
            aptr = (const char*)(A + gr*(long)lda);
            aok = 16;
        } else { aptr = (const char*)A; aok = 0; }
    }
    const char* bptr = (const char*)(Bp + (long)(bn0 + tid)*Kd);
    uint32_t aoff = (uint32_t)(tid*HPITCH)*2;           // smem byte offset of this thread's A row
    uint32_t boff = (uint32_t)(TBUF_H + tid*HPITCH)*2;  // ... B row

    float acc[4][8][4];
#pragma unroll
    for (int mt = 0; mt < 4; mt++)
#pragma unroll
        for (int nt = 0; nt < 8; nt++)
#pragma unroll
            for (int r = 0; r < 4; r++) acc[mt][nt][r] = 0.f;

    int nc = Kd >> 5;   // 32-k chunks

    // prologue: stage chunks 0 and 1
#pragma unroll
    for (int pc = 0; pc < 2; pc++) {
        if (pc < nc) {
            uint32_t s0 = sb + pc*STAGE_B;
            long kadv = (long)pc*64;   // bytes (32 halves)
#pragma unroll
            for (int seg = 0; seg < 4; seg++) {
                cp_async16(s0 + aoff + seg*16, aptr + kadv + seg*16, aok);
                cp_async16(s0 + boff + seg*16, bptr + kadv + seg*16, 16);
            }
        }
        cp_commit();
    }

    for (int c = 0; c < nc; c++) {
        int p = c % NSTAGE;
        __syncthreads();                     // buffer (c+2)%3 free from iter c-1
        if (c + 2 < nc) {
            int q = (c+2) % NSTAGE;
            uint32_t s0 = sb + q*STAGE_B;
            long kadv = (long)(c+2)*64;
#pragma unroll
            for (int seg = 0; seg < 4; seg++) {
                cp_async16(s0 + aoff + seg*16, aptr + kadv + seg*16, aok);
                cp_async16(s0 + boff + seg*16, bptr + kadv + seg*16, 16);
            }
            cp_commit();
            cp_wait<2>();
        } else if (c + 1 < nc) {
            cp_wait<1>();
        } else {
            cp_wait<0>();
        }
        __syncthreads();

        const __half* As = st + p*2*TBUF_H;
        const __half* Bs = As + TBUF_H;
#pragma unroll
        for (int ks = 0; ks < 2; ks++) {
            int kb = ks*16 + 2*tg;
            uint32_t a0[4], a1[4], a2[4], a3[4];
#pragma unroll
            for (int mt = 0; mt < 4; mt++) {
                int ra = warp_m*64 + mt*16 + g;
                a0[mt] = *reinterpret_cast<const uint32_t*>(As + ra*HPITCH + kb);
                a1[mt] = *reinterpret_cast<const uint32_t*>(As + (ra+8)*HPITCH + kb);
                a2[mt] = *reinterpret_cast<const uint32_t*>(As + ra*HPITCH + kb + 8);
                a3[mt] = *reinterpret_cast<const uint32_t*>(As + (ra+8)*HPITCH + kb + 8);
            }
            uint32_t b0[8], b1[8];
#pragma unroll
            for (int nt = 0; nt < 8; nt++) {
                int n = warp_n*64 + nt*8 + g;
                b0[nt] = *reinterpret_cast<const uint32_t*>(Bs + n*HPITCH + kb);
                b1[nt] = *reinterpret_cast<const uint32_t*>(Bs + n*HPITCH + kb + 8);
            }
#pragma unroll
            for (int mt = 0; mt < 4; mt++)
#pragma unroll
                for (int nt = 0; nt < 8; nt++)
                    mma_f16(acc[mt][nt], a0[mt], a1[mt], a2[mt], a3[mt], b0[nt], b1[nt]);
        }
    }

    // epilogue: c0=(g,2tg), c1=(g,2tg+1), c2=(g+8,2tg), c3=(g+8,2tg+1)
#pragma unroll
    for (int mt = 0; mt < 4; mt++) {
#pragma unroll
        for (int nt = 0; nt < 8; nt++) {
            int col = bn0 + warp_n*64 + nt*8 + 2*tg;
#pragma unroll
            for (int half = 0; half < 2; half++) {
                int lr = warp_m*64 + mt*16 + g + half*8;
                int grow = bm0 + lr;
                if (grow >= mrows) continue;
                long cr = rbase + grow;
                float v0 = acc[mt][nt][half*2+0];
                float v1 = acc[mt][nt][half*2+1];
                long o0 = cr*(long)ldc + col;
                if (EPI == 0) {
                    C[o0] = v0; C[o0+1] = v1;
                } else if (EPI == 1) {
                    C[o0]   = extra[o0]   + v0;
                    C[o0+1] = extra[o0+1] + v1;
                } else if (EPI == 2) {
                    float g0 = extra[o0], g1 = extra[o0+1];
                    Ch[o0]   = __float2half(g0 / (1.f + expf(-g0)) * v0);
                    Ch[o0+1] = __float2half(g1 / (1.f + expf(-g1)) * v1);
                } else if (EPI == 3) {
                    float s = extra[grow];
                    C[o0]   += v0 * s;
                    C[o0+1] += v1 * s;
                }
            }
        }
    }
}

// ---------------- router ----------------
__global__ void router_k(const float* __restrict__ x2, const float* __restrict__ Wr,
                         int* __restrict__ topi, float* __restrict__ topw)
{
    int t = blockIdx.x;
    __shared__ float xs[HID];
    __shared__ float pr[NEXP];
    for (int i = threadIdx.x; i < HID; i += blockDim.x) xs[i] = x2[(long)t*HID + i];
    __syncthreads();
    if (threadIdx.x < NEXP) {
        int e = threadIdx.x;
        float d = 0.f;
        for (int i = 0; i < HID; i++) d += xs[i] * Wr[i*NEXP + e];
        pr[e] = d;
    }
    __syncthreads();
    if (threadIdx.x == 0) {
        float mx = -1e30f;
        for (int e = 0; e < NEXP; e++) mx = fmaxf(mx, pr[e]);
        float p[NEXP]; float sm2 = 0.f;
        for (int e = 0; e < NEXP; e++) { p[e] = expf(pr[e]-mx); sm2 += p[e]; }
        for (int e = 0; e < NEXP; e++) p[e] /= sm2;
        float tw = 0.f;
        int   idx[TOPK]; float val[TOPK];
        for (int kk = 0; kk < TOPK; kk++) {
            int bi = 0; float bv = -1.f;
            for (int e = 0; e < NEXP; e++) if (p[e] > bv) { bv = p[e]; bi = e; }
            idx[kk] = bi; val[kk] = bv; p[bi] = -2.f; tw += bv;
        }
        for (int kk = 0; kk < TOPK; kk++) {
            topi[t*TOPK+kk] = idx[kk];
            topw[t*TOPK+kk] = val[kk] / tw;
        }
    }
}

// ---------------- routing build ----------------
__global__ void zero32_k(int* cnt) { if (threadIdx.x < NEXP) cnt[threadIdx.x] = 0; }
__global__ void count_k(const int* __restrict__ topi, int* __restrict__ cnt)
{
    int i = blockIdx.x*256 + threadIdx.x;
    if (i < T_TOK*TOPK) atomicAdd(&cnt[topi[i]], 1);
}
__global__ void scan_k(const int* __restrict__ cnt, int* __restrict__ off, int* __restrict__ cur)
{
    if (threadIdx.x == 0) {
        int a = 0;
        for (int e = 0; e < NEXP; e++) { off[e] = a; cur[e] = a; a += cnt[e]; }
        off[NEXP] = a;
    }
}
__global__ void fill_k(const int* __restrict__ topi, int* __restrict__ cur,
                       int* __restrict__ ptok, int* __restrict__ ppos)
{
    int i = blockIdx.x*256 + threadIdx.x;
    if (i < T_TOK*TOPK) {
        int e = topi[i];
        int p = atomicAdd(&cur[e], 1);
        ptok[p] = i / TOPK;
        ppos[i] = p;
    }
}

// ---------------- MoE reduction ----------------
__global__ void moe_reduce_k(const float* __restrict__ down, const int* __restrict__ ppos,
                             const float* __restrict__ topw, const float* __restrict__ h,
                             float* __restrict__ out)
{
    int t = blockIdx.x;
    int pos[TOPK]; float w[TOPK];
#pragma unroll
    for (int kk = 0; kk < TOPK; kk++) { pos[kk] = ppos[t*TOPK+kk]; w[kk] = topw[t*TOPK+kk]; }
    for (int c = threadIdx.x; c < HID; c += blockDim.x) {
        float s = h[(long)t*HID + c];
#pragma unroll
        for (int kk = 0; kk < TOPK; kk++) s += down[(long)pos[kk]*HID + c] * w[kk];
        out[(long)t*HID + c] = s;
    }
}

// ---------------- shared-expert sigmoid gate ----------------
__global__ void shgate_k(const float* __restrict__ x2, const float* __restrict__ w,
                         float* __restrict__ sig)
{
    int t = blockIdx.x;
    float s = 0.f;
    for (int i = threadIdx.x; i < HID; i += blockDim.x) s += x2[(long)t*HID + i] * w[i];
    __shared__ float red[32];
    for (int o = 16; o > 0; o >>= 1) s += __shfl_xor_sync(0xffffffffu, s, o);
    int warp = threadIdx.x >> 5, lane = threadIdx.x & 31;
    if (lane == 0) red[warp] = s;
    __syncthreads();
    if (warp == 0) {
        s = (lane < (blockDim.x >> 5)) ? red[lane] : 0.f;
        for (int o = 16; o > 0; o >>= 1) s += __shfl_xor_sync(0xffffffffu, s, o);
        if (lane == 0) sig[t] = 1.f / (1.f + expf(-s));
    }
}

// ---------------- host launch ----------------
extern "C" void kernel_launch(void* const* d_in, const int* in_sizes, int n_in,
                              void* d_out, int out_size)
{
    (void)in_sizes; (void)out_size;
    if (n_in < 17) return;
    const float* hidden = (const float*)d_in[0];
    const float* ln1    = (const float*)d_in[1];
    const float* ln2    = (const float*)d_in[2];
    const float* qnw    = (const float*)d_in[3];
    const float* knw    = (const float*)d_in[4];
    const float* Wq     = (const float*)d_in[5];
    const float* Wk     = (const float*)d_in[6];
    const float* Wv     = (const float*)d_in[7];
    const float* Wo     = (const float*)d_in[8];
    const float* Wr     = (const float*)d_in[9];
    const float* Weg    = (const float*)d_in[10];
    const float* Weu    = (const float*)d_in[11];
    const float* Wed    = (const float*)d_in[12];
    const float* Wsg    = (const float*)d_in[13];
    const float* Wsu    = (const float*)d_in[14];
    const float* Wsd    = (const float*)d_in[15];
    const float* Wshg   = (const float*)d_in[16];
    float* out = (float*)d_out;

    float *xn, *qkvb, *hb, *actg, *shg, *down, *cosT, *sinT, *topw, *sig;
    int *topi, *cnt, *off, *cur, *ptok, *ppos;
    __half *xh, *atth, *acth, *shh;
    __half *WqkvT, *WoT, *WegT, *WeuT, *WedT, *WsgT, *WsuT, *WsdT;
    cudaGetSymbolAddress((void**)&xn,    g_xn);
    cudaGetSymbolAddress((void**)&qkvb,  g_qkv);
    cudaGetSymbolAddress((void**)&hb,    g_h);
    cudaGetSymbolAddress((void**)&actg,  g_actg);
    cudaGetSymbolAddress((void**)&shg,   g_shg);
    cudaGetSymbolAddress((void**)&down,  g_down);
    cudaGetSymbolAddress((void**)&cosT,  g_cos);
    cudaGetSymbolAddress((void**)&sinT,  g_sin);
    cudaGetSymbolAddress((void**)&topi,  g_topi);
    cudaGetSymbolAddress((void**)&topw,  g_topw);
    cudaGetSymbolAddress((void**)&cnt,   g_cnt);
    cudaGetSymbolAddress((void**)&off,   g_off);
    cudaGetSymbolAddress((void**)&cur,   g_cur);
    cudaGetSymbolAddress((void**)&ptok,  g_ptok);
    cudaGetSymbolAddress((void**)&ppos,  g_ppos);
    cudaGetSymbolAddress((void**)&sig,   g_sig);
    cudaGetSymbolAddress((void**)&xh,    g_xh);
    cudaGetSymbolAddress((void**)&atth,  g_atth);
    cudaGetSymbolAddress((void**)&acth,  g_acth);
    cudaGetSymbolAddress((void**)&shh,   g_shh);
    cudaGetSymbolAddress((void**)&WqkvT, g_Wqkv);
    cudaGetSymbolAddress((void**)&WoT,   g_WoT);
    cudaGetSymbolAddress((void**)&WegT,  g_WegT);
    cudaGetSymbolAddress((void**)&WeuT,  g_WeuT);
    cudaGetSymbolAddress((void**)&WedT,  g_WedT);
    cudaGetSymbolAddress((void**)&WsgT,  g_WsgT);
    cudaGetSymbolAddress((void**)&WsuT,  g_WsuT);
    cudaGetSymbolAddress((void**)&WsdT,  g_WsdT);

    cudaFuncSetAttribute(flash_tc_k, cudaFuncAttributeMaxDynamicSharedMemorySize, FLASH2_SMEM_BYTES);
    cudaFuncSetAttribute(mmh_k<0,false,false>, cudaFuncAttributeMaxDynamicSharedMemorySize, MMH_SMEM_BYTES);
    cudaFuncSetAttribute(mmh_k<1,false,false>, cudaFuncAttributeMaxDynamicSharedMemorySize, MMH_SMEM_BYTES);
    cudaFuncSetAttribute(mmh_k<2,false,false>, cudaFuncAttributeMaxDynamicSharedMemorySize, MMH_SMEM_BYTES);
    cudaFuncSetAttribute(mmh_k<3,false,false>, cudaFuncAttributeMaxDynamicSharedMemorySize, MMH_SMEM_BYTES);
    cudaFuncSetAttribute(mmh_k<0,true,true>,   cudaFuncAttributeMaxDynamicSharedMemorySize, MMH_SMEM_BYTES);
    cudaFuncSetAttribute(mmh_k<2,true,true>,   cudaFuncAttributeMaxDynamicSharedMemorySize, MMH_SMEM_BYTES);
    cudaFuncSetAttribute(mmh_k<0,false,true>,  cudaFuncAttributeMaxDynamicSharedMemorySize, MMH_SMEM_BYTES);

    dim3 tb(32, 8);
    // --- weight transpose+fp16 conversion (once per launch) ---
    tcvt_k<<<dim3(4096/32, 2048/32), tb>>>(Wq,  WqkvT, HID, 4096);
    tcvt_k<<<dim3( 512/32, 2048/32), tb>>>(Wk,  WqkvT + (long)4096*HID, HID, 512);
    tcvt_k<<<dim3( 512/32, 2048/32), tb>>>(Wv,  WqkvT + (long)4608*HID, HID, 512);
    tcvt_k<<<dim3(2048/32, 4096/32), tb>>>(Wo,  WoT,  4096, 2048);
    tcvt_k<<<dim3( 768/32, 2048/32, NEXP), tb>>>(Weg, WegT, HID, EI);
    tcvt_k<<<dim3( 768/32, 2048/32, NEXP), tb>>>(Weu, WeuT, HID, EI);
    tcvt_k<<<dim3(2048/32,  768/32, NEXP), tb>>>(Wed, WedT, EI, HID);
    tcvt_k<<<dim3(4096/32, 2048/32), tb>>>(Wsg, WsgT, HID, SI);
    tcvt_k<<<dim3(4096/32, 2048/32), tb>>>(Wsu, WsuT, HID, SI);
    tcvt_k<<<dim3(2048/32, 4096/32), tb>>>(Wsd, WsdT, SI, HID);

    // --- attention block ---
    rmsnorm_k<<<T_TOK, 256>>>(hidden, ln1, xn, xh);

    mmh_k<0,false,false><<<dim3(QKVN/128, 32), 128, MMH_SMEM_BYTES>>>(
        T_TOK, QKVN, HID, xh, HID, WqkvT, 0, qkvb, nullptr, QKVN, nullptr, nullptr, nullptr);

    rope_tab_k<<<SEQ, HDIM/2>>>(cosT, sinT);
    qknr_k<<<T_TOK*NHEAD, HDIM>>>(qkvb, qnw, NHEAD, 0, 0, cosT, sinT);
    qknr_k<<<T_TOK*NKVH,  HDIM>>>(qkvb, knw, NKVH, NHEAD*HDIM, 1, cosT, sinT);
    vround_k<<<T_TOK, 128>>>(qkvb);

    flash_tc_k<<<dim3(SEQ/64, NHEAD, BATCH), 128, FLASH2_SMEM_BYTES>>>(qkvb, atth);

    // h = hidden + att @ Wo
    mmh_k<1,false,false><<<dim3(16, 32), 128, MMH_SMEM_BYTES>>>(
        T_TOK, HID, NHEAD*HDIM, atth, NHEAD*HDIM, WoT, 0, hb, nullptr, HID, nullptr, nullptr, hidden);

    // --- MoE block ---
    rmsnorm_k<<<T_TOK, 256>>>(hb, ln2, xn, xh);

    router_k<<<T_TOK, 128>>>(xn, Wr, topi, topw);
    zero32_k<<<1, 32>>>(cnt);
    count_k<<<(T_TOK*TOPK+255)/256, 256>>>(topi, cnt);
    scan_k<<<1, 32>>>(cnt, off, cur);
    fill_k<<<(T_TOK*TOPK+255)/256, 256>>>(topi, cur, ptok, ppos);

    // experts: gate -> actg (f32); up -> acth = silu(actg)*up (fp16); down -> down (f32)
    mmh_k<0,true,true><<<dim3(EI/128, 32, NEXP), 128, MMH_SMEM_BYTES>>>(
        0, EI, HID, xh, HID, WegT, (long)EI*HID, actg, nullptr, EI, off, ptok, nullptr);
    mmh_k<2,true,true><<<dim3(EI/128, 32, NEXP), 128, MMH_SMEM_BYTES>>>(
        0, EI, HID, xh, HID, WeuT, (long)EI*HID, nullptr, acth, EI, off, ptok, actg);
    mmh_k<0,false,true><<<dim3(HID/128, 32, NEXP), 128, MMH_SMEM_BYTES>>>(
        0, HID, EI, acth, EI, WedT, (long)HID*EI, down, nullptr, HID, off, nullptr, nullptr);

    moe_reduce_k<<<T_TOK, 256>>>(down, ppos, topw, hb, out);

    // --- shared expert ---
    mmh_k<0,false,false><<<dim3(SI/128, 32), 128, MMH_SMEM_BYTES>>>(
        T_TOK, SI, HID, xh, HID, WsgT, 0, shg, nullptr, SI, nullptr, nullptr, nullptr);
    mmh_k<2,false,false><<<dim3(SI/128, 32), 128, MMH_SMEM_BYTES>>>(
        T_TOK, SI, HID, xh, HID, WsuT, 0, nullptr, shh, SI, nullptr, nullptr, shg);
    shgate_k<<<T_TOK, 256>>>(xn, Wshg, sig);
    mmh_k<3,false,false><<<dim3(HID/128, 32), 128, MMH_SMEM_BYTES>>>(
        T_TOK, HID, SI, shh, SI, WsdT, 0, out, nullptr, HID, nullptr, nullptr, sig);
}

// round 9
// speedup vs baseline: 5.4463x; 1.4615x over previous
#include <cuda_runtime.h>
#include <cuda_fp16.h>
#include <math.h>
#include <stdint.h>

// ---------------- problem constants ----------------
#define T_TOK 4096
#define HID   2048
#define SEQ   1024
#define BATCH 4
#define NHEAD 32
#define NKVH  4
#define HDIM  128
#define NEXP  32
#define TOPK  8
#define EI    768
#define SI    4096
#define GQA   8
#define EPSV  1e-6f
#define QKVN  (NHEAD*HDIM + 2*NKVH*HDIM)   // 5120

// ---------------- scratch (fp32) ----------------
__device__ float g_xn  [T_TOK*HID];
__device__ float g_qkv [T_TOK*QKVN];
__device__ float g_h   [T_TOK*HID];
__device__ float g_actg[T_TOK*TOPK*EI];
__device__ float g_shg [T_TOK*SI];
__device__ float g_down[T_TOK*TOPK*HID];
__device__ float g_cos[SEQ*(HDIM/2)];
__device__ float g_sin[SEQ*(HDIM/2)];
__device__ int   g_topi[T_TOK*TOPK];
__device__ float g_topw[T_TOK*TOPK];
__device__ int   g_cnt[NEXP];
__device__ int   g_off[NEXP+1];
__device__ int   g_cur[NEXP];
__device__ int   g_ptok[T_TOK*TOPK];
__device__ int   g_ppos[T_TOK*TOPK];
__device__ float g_sig[T_TOK];
// ---------------- scratch (fp16) ----------------
__device__ __half g_xh  [T_TOK*HID];
__device__ __half g_atth[T_TOK*NHEAD*HDIM];
__device__ __half g_acth[T_TOK*TOPK*EI];
__device__ __half g_shh [T_TOK*SI];
// fp16 transposed weights [N][K]
__device__ __half g_Wqkv[QKVN*HID];
__device__ __half g_WoT [HID*NHEAD*HDIM];
__device__ __half g_WegT[(long)NEXP*EI*HID];
__device__ __half g_WeuT[(long)NEXP*EI*HID];
__device__ __half g_WedT[(long)NEXP*HID*EI];
__device__ __half g_WsgT[SI*HID];
__device__ __half g_WsuT[SI*HID];
__device__ __half g_WsdT[HID*SI];

// ---------------- helpers ----------------
__device__ __forceinline__ float tf32r(float x)
{
    uint32_t u;
    asm("cvt.rna.tf32.f32 %0, %1;" : "=r"(u) : "f"(x));
    return __uint_as_float(u);
}
__device__ __forceinline__ uint32_t smem_u32(const void* p){
    uint32_t a;
    asm("{ .reg .u64 t; cvta.to.shared.u64 t, %1; cvt.u32.u64 %0, t; }" : "=r"(a) : "l"(p));
    return a;
}
__device__ __forceinline__ void cp_async16(uint32_t saddr, const void* gaddr, uint32_t sz){
    asm volatile("cp.async.cg.shared.global [%0], [%1], 16, %2;"
        :: "r"(saddr), "l"(gaddr), "r"(sz) : "memory");
}
__device__ __forceinline__ void cp_commit(){
    asm volatile("cp.async.commit_group;" ::: "memory");
}
template<int N>
__device__ __forceinline__ void cp_wait(){
    asm volatile("cp.async.wait_group %0;" :: "n"(N) : "memory");
}
__device__ __forceinline__ void mma_tf32(float* c, float a0, float a1, float a2, float a3,
                                         float b0, float b1)
{
    uint32_t ua0 = __float_as_uint(a0), ua1 = __float_as_uint(a1);
    uint32_t ua2 = __float_as_uint(a2), ua3 = __float_as_uint(a3);
    uint32_t ub0 = __float_as_uint(b0), ub1 = __float_as_uint(b1);
    asm volatile("mma.sync.aligned.m16n8k8.row.col.f32.tf32.tf32.f32 "
        "{%0,%1,%2,%3}, {%4,%5,%6,%7}, {%8,%9}, {%0,%1,%2,%3};"
        : "+f"(c[0]), "+f"(c[1]), "+f"(c[2]), "+f"(c[3])
        : "r"(ua0), "r"(ua1), "r"(ua2), "r"(ua3), "r"(ub0), "r"(ub1));
}
__device__ __forceinline__ void mma_f16(float* c, uint32_t a0, uint32_t a1, uint32_t a2, uint32_t a3,
                                        uint32_t b0, uint32_t b1)
{
    asm volatile("mma.sync.aligned.m16n8k16.row.col.f32.f16.f16.f32 "
        "{%0,%1,%2,%3}, {%4,%5,%6,%7}, {%8,%9}, {%0,%1,%2,%3};"
        : "+f"(c[0]), "+f"(c[1]), "+f"(c[2]), "+f"(c[3])
        : "r"(a0), "r"(a1), "r"(a2), "r"(a3), "r"(b0), "r"(b1));
}
#define LDSM_X4(r0, r1, r2, r3, addr) \
    asm volatile("ldmatrix.sync.aligned.m8n8.x4.shared.b16 {%0,%1,%2,%3}, [%4];" \
        : "=r"(r0), "=r"(r1), "=r"(r2), "=r"(r3) : "r"(addr))

// ---------------- weight transpose + fp16 convert: src[K][N] -> dst[N][K] ----------------
__global__ void tcvt_k(const float* __restrict__ src, __half* __restrict__ dst, int K, int N)
{
    __shared__ float t[32][33];
    long z = blockIdx.z;
    src += z * (long)K * N;
    dst += z * (long)K * N;
    int n0 = blockIdx.x*32, k0 = blockIdx.y*32;
    int tx = threadIdx.x, ty = threadIdx.y;
#pragma unroll
    for (int i = 0; i < 32; i += 8)
        t[tx][ty+i] = src[(long)(k0+ty+i)*N + n0+tx];
    __syncthreads();
#pragma unroll
    for (int i = 0; i < 32; i += 8)
        dst[(long)(n0+ty+i)*K + k0+tx] = __float2half(t[ty+i][tx]);
}

// ---------------- rmsnorm over HID (writes fp32 + fp16) ----------------
__global__ void rmsnorm_k(const float* __restrict__ x, const float* __restrict__ w,
                          float* __restrict__ y, __half* __restrict__ yh)
{
    int row = blockIdx.x;
    const float* xr = x + (long)row*HID;
    float ss = 0.f;
    for (int i = threadIdx.x; i < HID; i += blockDim.x) { float v = xr[i]; ss += v*v; }
    __shared__ float red[32];
    for (int o = 16; o > 0; o >>= 1) ss += __shfl_xor_sync(0xffffffffu, ss, o);
    int warp = threadIdx.x >> 5, lane = threadIdx.x & 31;
    if (lane == 0) red[warp] = ss;
    __syncthreads();
    if (warp == 0) {
        ss = (lane < (blockDim.x >> 5)) ? red[lane] : 0.f;
        for (int o = 16; o > 0; o >>= 1) ss += __shfl_xor_sync(0xffffffffu, ss, o);
        if (lane == 0) red[0] = ss;
    }
    __syncthreads();
    float r = rsqrtf(red[0] / (float)HID + EPSV);
    for (int i = threadIdx.x; i < HID; i += blockDim.x) {
        float v = xr[i] * r * w[i];
        y [(long)row*HID + i] = v;
        yh[(long)row*HID + i] = __float2half(v);
    }
}

// ---------------- rope tables ----------------
__global__ void rope_tab_k(float* __restrict__ cosT, float* __restrict__ sinT)
{
    int s = blockIdx.x;
    int i = threadIdx.x;
    float inv = expf(-((float)(2*i) / (float)HDIM) * logf(1000000.0f));
    float ang = (float)s * inv;
    cosT[s*(HDIM/2)+i] = cosf(ang);
    sinT[s*(HDIM/2)+i] = sinf(ang);
}

// ---------------- per-head rmsnorm + rope on packed qkv ----------------
__global__ void qknr_k(float* __restrict__ qkv, const float* __restrict__ nw, int nh, int colOff,
                       int doRound,
                       const float* __restrict__ cosT, const float* __restrict__ sinT)
{
    long bh = blockIdx.x;
    int t = (int)(bh / nh);
    int head = (int)(bh % nh);
    int s = t & (SEQ-1);
    int d = threadIdx.x;
    float* xp = qkv + (long)t*QKVN + colOff + head*HDIM;
    float v = xp[d];
    float ss = v*v;
    for (int o = 16; o > 0; o >>= 1) ss += __shfl_xor_sync(0xffffffffu, ss, o);
    __shared__ float red[4];
    if ((threadIdx.x & 31) == 0) red[threadIdx.x >> 5] = ss;
    __syncthreads();
    float tot = red[0]+red[1]+red[2]+red[3];
    float r = rsqrtf(tot / (float)HDIM + EPSV);
    float xn = v * r * nw[d];
    __shared__ float xsh[HDIM];
    xsh[d] = xn;
    __syncthreads();
    float c, sn, oth;
    if (d < HDIM/2) { c = cosT[s*(HDIM/2)+d];          sn = sinT[s*(HDIM/2)+d];          oth = -xsh[d+HDIM/2]; }
    else            { c = cosT[s*(HDIM/2)+d-HDIM/2];   sn = sinT[s*(HDIM/2)+d-HDIM/2];   oth =  xsh[d-HDIM/2]; }
    float val = xn*c + oth*sn;
    xp[d] = doRound ? tf32r(val) : val;
}

// ---------------- round V slice in place (tf32) ----------------
__global__ void vround_k(float* __restrict__ qkv)
{
    long t = blockIdx.x;
    float4* p = reinterpret_cast<float4*>(qkv + t*QKVN + NHEAD*HDIM + NKVH*HDIM);
    for (int i = threadIdx.x; i < NKVH*HDIM/4; i += blockDim.x) {
        float4 v = p[i];
        v.x = tf32r(v.x); v.y = tf32r(v.y); v.z = tf32r(v.z); v.w = tf32r(v.w);
        p[i] = v;
    }
}

// ---------------- tensor-core flash attention (tf32 mma, online softmax), fp16 output ----------------
#define FLASH2_SMEM_BYTES ((8448 + 8704 + 4352)*4)

__global__ void __launch_bounds__(128)
flash_tc_k(const float* __restrict__ qkv, __half* __restrict__ og)
{
    extern __shared__ float fs[];
    float* Ks = fs;
    float* Vs = fs + 8448;
    float* Ps = fs + 17152;
    uint32_t sb = smem_u32(fs);
    uint32_t KsU = sb;
    uint32_t VsU = sb + 8448u*4;

    int qt = blockIdx.x, h = blockIdx.y, b = blockIdx.z;
    int kvh = h / GQA;
    int qs0 = qt*64;
    int tid = threadIdx.x, w = tid >> 5, lane = tid & 31;
    int g = lane >> 2, tg = lane & 3;
    float scale = rsqrtf((float)HDIM);

    float qa[16][4];
    {
        const float* q0 = qkv + (long)(b*SEQ + qs0 + w*16 + g)*QKVN + h*HDIM;
        const float* q8 = q0 + 8L*QKVN;
#pragma unroll
        for (int ks = 0; ks < 16; ks++) {
            int kb = ks*8;
            qa[ks][0] = tf32r(q0[kb+tg]*scale);
            qa[ks][1] = tf32r(q8[kb+tg]*scale);
            qa[ks][2] = tf32r(q0[kb+tg+4]*scale);
            qa[ks][3] = tf32r(q8[kb+tg+4]*scale);
        }
    }

    float m0 = -1e30f, m1 = -1e30f, l0 = 0.f, l1 = 0.f;
    float oac[16][4];
#pragma unroll
    for (int nt = 0; nt < 16; nt++)
#pragma unroll
        for (int r = 0; r < 4; r++) oac[nt][r] = 0.f;

    long kbase = (long)(b*SEQ)*QKVN + NHEAD*HDIM + kvh*HDIM;
    long vbase = kbase + (long)NKVH*HDIM;
    int pr0 = (w*16+g)*68, pr1 = (w*16+g+8)*68;

    for (int jt = 0; jt <= qt; jt++) {
        __syncthreads();
        {
            long kr = kbase + (long)(jt*64)*QKVN;
#pragma unroll
            for (int i = 0; i < 16; i++) {
                int idx = i*128 + tid;
                int r = idx >> 5, c = idx & 31;
                cp_async16(KsU + (uint32_t)(r*132 + c*4)*4, qkv + kr + (long)r*QKVN + c*4, 16);
            }
            cp_commit();
            long vr = vbase + (long)(jt*64)*QKVN;
#pragma unroll
            for (int i = 0; i < 16; i++) {
                int idx = i*128 + tid;
                int r = idx >> 5, c = idx & 31;
                cp_async16(VsU + (uint32_t)(r*136 + c*4)*4, qkv + vr + (long)r*QKVN + c*4, 16);
            }
            cp_commit();
        }
        cp_wait<1>(); __syncthreads();

        float sacc[8][4];
#pragma unroll
        for (int nt = 0; nt < 8; nt++)
#pragma unroll
            for (int r = 0; r < 4; r++) sacc[nt][r] = 0.f;
#pragma unroll
        for (int ks = 0; ks < 16; ks++) {
            int kb = ks*8;
#pragma unroll
            for (int nt = 0; nt < 8; nt++) {
                float b0 = Ks[(nt*8+g)*132 + kb+tg];
                float b1 = Ks[(nt*8+g)*132 + kb+tg+4];
                mma_tf32(sacc[nt], qa[ks][0], qa[ks][1], qa[ks][2], qa[ks][3], b0, b1);
            }
        }
        int row0 = qs0 + w*16 + g, row1 = row0 + 8;
        if (jt == qt) {
            int cb = jt*64;
#pragma unroll
            for (int nt = 0; nt < 8; nt++) {
                int c0 = cb + nt*8 + 2*tg;
                if (c0   > row0) sacc[nt][0] = -1e30f;
                if (c0+1 > row0) sacc[nt][1] = -1e30f;
                if (c0   > row1) sacc[nt][2] = -1e30f;
                if (c0+1 > row1) sacc[nt][3] = -1e30f;
            }
        }
        float mx0 = m0, mx1 = m1;
#pragma unroll
        for (int nt = 0; nt < 8; nt++) {
            mx0 = fmaxf(mx0, fmaxf(sacc[nt][0], sacc[nt][1]));
            mx1 = fmaxf(mx1, fmaxf(sacc[nt][2], sacc[nt][3]));
        }
        mx0 = fmaxf(mx0, __shfl_xor_sync(0xffffffffu, mx0, 1));
        mx0 = fmaxf(mx0, __shfl_xor_sync(0xffffffffu, mx0, 2));
        mx1 = fmaxf(mx1, __shfl_xor_sync(0xffffffffu, mx1, 1));
        mx1 = fmaxf(mx1, __shfl_xor_sync(0xffffffffu, mx1, 2));
        float c0 = expf(m0 - mx0), c1 = expf(m1 - mx1);
        float s0 = 0.f, s1 = 0.f;
#pragma unroll
        for (int nt = 0; nt < 8; nt++) {
            sacc[nt][0] = expf(sacc[nt][0] - mx0);
            sacc[nt][1] = expf(sacc[nt][1] - mx0);
            sacc[nt][2] = expf(sacc[nt][2] - mx1);
            sacc[nt][3] = expf(sacc[nt][3] - mx1);
            s0 += sacc[nt][0] + sacc[nt][1];
            s1 += sacc[nt][2] + sacc[nt][3];
        }
        s0 += __shfl_xor_sync(0xffffffffu, s0, 1);
        s0 += __shfl_xor_sync(0xffffffffu, s0, 2);
        s1 += __shfl_xor_sync(0xffffffffu, s1, 1);
        s1 += __shfl_xor_sync(0xffffffffu, s1, 2);
        l0 = l0*c0 + s0;  l1 = l1*c1 + s1;  m0 = mx0;  m1 = mx1;
#pragma unroll
        for (int nt = 0; nt < 16; nt++) {
            oac[nt][0] *= c0; oac[nt][1] *= c0;
            oac[nt][2] *= c1; oac[nt][3] *= c1;
        }
#pragma unroll
        for (int nt = 0; nt < 8; nt++) {
            int pc = nt*8 + 2*tg;
            Ps[pr0+pc]   = tf32r(sacc[nt][0]);
            Ps[pr0+pc+1] = tf32r(sacc[nt][1]);
            Ps[pr1+pc]   = tf32r(sacc[nt][2]);
            Ps[pr1+pc+1] = tf32r(sacc[nt][3]);
        }
        cp_wait<0>(); __syncthreads();

#pragma unroll
        for (int ks = 0; ks < 8; ks++) {
            int kb = ks*8;
            float a0 = Ps[pr0 + kb+tg];
            float a1 = Ps[pr1 + kb+tg];
            float a2 = Ps[pr0 + kb+tg+4];
            float a3 = Ps[pr1 + kb+tg+4];
#pragma unroll
            for (int nt = 0; nt < 16; nt++) {
                float b0 = Vs[(kb+tg)*136 + nt*8+g];
                float b1 = Vs[(kb+tg+4)*136 + nt*8+g];
                mma_tf32(oac[nt], a0, a1, a2, a3, b0, b1);
            }
        }
    }

    float i0 = 1.f/l0, i1 = 1.f/l1;
    long o0 = ((long)(b*SEQ + qs0 + w*16 + g)*NHEAD + h)*HDIM;
    long o8 = o0 + 8L*NHEAD*HDIM;
#pragma unroll
    for (int nt = 0; nt < 16; nt++) {
        int c = nt*8 + 2*tg;
        og[o0+c]   = __float2half(oac[nt][0]*i0);
        og[o0+c+1] = __float2half(oac[nt][1]*i0);
        og[o8+c]   = __float2half(oac[nt][2]*i1);
        og[o8+c+1] = __float2half(oac[nt][3]*i1);
    }
}

// ---------------- fp16 mma GEMM: 128x128x32, 256 thr (2x4 warps, 64x32 tiles), ldmatrix ----------------
// C[M,N] = A[M,K] @ B^T, B stored [N][K] fp16.
// EPI: 0=store f32, 1=resid add(extra), 2=Ch = silu(extra)*acc (fp16 out), 3=C += acc*extra[row]
#define HPITCH 40
#define TBUF_H (128*HPITCH)
#define STAGE_B (2*TBUF_H*2)
#define NSTAGE 3
#define MMH_SMEM_BYTES (NSTAGE*STAGE_B)

template<int EPI, bool AIDX, bool EXPERT>
__global__ void __launch_bounds__(256, 2)
mmh_k(int M, int N, int Kd,
      const __half* __restrict__ A, int lda,
      const __half* __restrict__ B, long strideB,
      float* __restrict__ C, __half* __restrict__ Ch, int ldc,
      const int* __restrict__ offs, const int* __restrict__ aidx,
      const float* __restrict__ extra)
{
    extern __shared__ __align__(16) char smh[];
    uint32_t sb = smem_u32(smh);

    int rbase = 0, mrows = M;
    const __half* Bp = B;
    if (EXPERT) {
        int e = blockIdx.z;
        rbase = offs[e];
        mrows = offs[e+1] - rbase;
        Bp = B + (long)e * strideB;
    }
    int bm0 = blockIdx.y * 128;
    if (bm0 >= mrows) return;
    int bn0 = blockIdx.x * 128;

    int tid = threadIdx.x, lane = tid & 31, wid = tid >> 5;
    int g = lane >> 2, tg = lane & 3;
    int warp_m = wid & 1, warp_n = wid >> 1;   // 2x4 warps

    // staging: thread covers row tid>>1 (A and B), 32 contiguous bytes at half-offset (tid&1)*16
    const char* aptr;
    uint32_t aok;
    {
        int lr = bm0 + (tid >> 1);
        if (lr < mrows) {
            long gr = AIDX ? (long)aidx[rbase + lr] : (long)(rbase + lr);
            aptr = (const char*)(A + gr*(long)lda + (tid & 1)*16);
            aok = 16;
        } else { aptr = (const char*)A; aok = 0; }
    }
    const char* bptr = (const char*)(Bp + (long)(bn0 + (tid >> 1))*Kd + (tid & 1)*16);
    uint32_t aoff = (uint32_t)((tid >> 1)*HPITCH + (tid & 1)*16)*2;
    uint32_t boff = (uint32_t)(TBUF_H + (tid >> 1)*HPITCH + (tid & 1)*16)*2;

    // ldmatrix lane bases (byte offsets within a stage)
    uint32_t aFragB = (uint32_t)((warp_m*64 + (lane & 15))*HPITCH + ((lane >> 4) & 1)*8)*2;
    uint32_t bFragB = (uint32_t)(TBUF_H + (warp_n*32 + ((lane >> 4) << 3) + (lane & 7))*HPITCH
                                 + ((lane >> 3) & 1)*8)*2;

    float acc[4][4][4];
#pragma unroll
    for (int mt = 0; mt < 4; mt++)
#pragma unroll
        for (int nt = 0; nt < 4; nt++)
#pragma unroll
            for (int r = 0; r < 4; r++) acc[mt][nt][r] = 0.f;

    int nc = Kd >> 5;

    // prologue: stage chunks 0,1
#pragma unroll
    for (int pc = 0; pc < 2; pc++) {
        if (pc < nc) {
            uint32_t s0 = sb + pc*STAGE_B;
            long kadv = (long)pc*64;
            cp_async16(s0 + aoff,      aptr + kadv,      aok);
            cp_async16(s0 + aoff + 16, aptr + kadv + 16, aok);
            cp_async16(s0 + boff,      bptr + kadv,      16);
            cp_async16(s0 + boff + 16, bptr + kadv + 16, 16);
        }
        cp_commit();
    }

    for (int c = 0; c < nc; c++) {
        int p = c % NSTAGE;
        cp_wait<1>();          // stage c complete (only group c+1 may pend)
        __syncthreads();       // all threads past iter c-1 compute -> buffer (c+2)%3 free
        if (c + 2 < nc) {
            int q = (c + 2) % NSTAGE;
            uint32_t s0 = sb + q*STAGE_B;
            long kadv = (long)(c + 2)*64;
            cp_async16(s0 + aoff,      aptr + kadv,      aok);
            cp_async16(s0 + aoff + 16, aptr + kadv + 16, aok);
            cp_async16(s0 + boff,      bptr + kadv,      16);
            cp_async16(s0 + boff + 16, bptr + kadv + 16, 16);
        }
        cp_commit();           // always commit (possibly empty) to keep group count regular

        uint32_t aB = sb + p*STAGE_B + aFragB;
        uint32_t bB = sb + p*STAGE_B + bFragB;
#pragma unroll
        for (int ks = 0; ks < 2; ks++) {
            uint32_t a[4][4];
#pragma unroll
            for (int mt = 0; mt < 4; mt++)
                LDSM_X4(a[mt][0], a[mt][1], a[mt][2], a[mt][3],
                        aB + (uint32_t)(mt*16*HPITCH)*2 + ks*32);
            uint32_t bq[2][4];
#pragma unroll
            for (int ntp = 0; ntp < 2; ntp++)
                LDSM_X4(bq[ntp][0], bq[ntp][1], bq[ntp][2], bq[ntp][3],
                        bB + (uint32_t)(ntp*16*HPITCH)*2 + ks*32);
#pragma unroll
            for (int mt = 0; mt < 4; mt++)
#pragma unroll
                for (int nt = 0; nt < 4; nt++)
                    mma_f16(acc[mt][nt], a[mt][0], a[mt][1], a[mt][2], a[mt][3],
                            bq[nt >> 1][(nt & 1)*2], bq[nt >> 1][(nt & 1)*2 + 1]);
        }
    }

    // epilogue: c0=(g,2tg), c1=(g,2tg+1), c2=(g+8,2tg), c3=(g+8,2tg+1)
#pragma unroll
    for (int mt = 0; mt < 4; mt++) {
#pragma unroll
        for (int nt = 0; nt < 4; nt++) {
            int col = bn0 + warp_n*32 + nt*8 + 2*tg;
#pragma unroll
            for (int half = 0; half < 2; half++) {
                int lr = warp_m*64 + mt*16 + g + half*8;
                int grow = bm0 + lr;
                if (grow >= mrows) continue;
                long cr = rbase + grow;
                float v0 = acc[mt][nt][half*2+0];
                float v1 = acc[mt][nt][half*2+1];
                long o0 = cr*(long)ldc + col;
                if (EPI == 0) {
                    C[o0] = v0; C[o0+1] = v1;
                } else if (EPI == 1) {
                    C[o0]   = extra[o0]   + v0;
                    C[o0+1] = extra[o0+1] + v1;
                } else if (EPI == 2) {
                    float g0 = extra[o0], g1 = extra[o0+1];
                    Ch[o0]   = __float2half(g0 / (1.f + expf(-g0)) * v0);
                    Ch[o0+1] = __float2half(g1 / (1.f + expf(-g1)) * v1);
                } else if (EPI == 3) {
                    float s = extra[grow];
                    C[o0]   += v0 * s;
                    C[o0+1] += v1 * s;
                }
            }
        }
    }
}

// ---------------- router ----------------
__global__ void router_k(const float* __restrict__ x2, const float* __restrict__ Wr,
                         int* __restrict__ topi, float* __restrict__ topw)
{
    int t = blockIdx.x;
    __shared__ float xs[HID];
    __shared__ float pr[NEXP];
    for (int i = threadIdx.x; i < HID; i += blockDim.x) xs[i] = x2[(long)t*HID + i];
    __syncthreads();
    if (threadIdx.x < NEXP) {
        int e = threadIdx.x;
        float d = 0.f;
        for (int i = 0; i < HID; i++) d += xs[i] * Wr[i*NEXP + e];
        pr[e] = d;
    }
    __syncthreads();
    if (threadIdx.x == 0) {
        float mx = -1e30f;
        for (int e = 0; e < NEXP; e++) mx = fmaxf(mx, pr[e]);
        float p[NEXP]; float sm2 = 0.f;
        for (int e = 0; e < NEXP; e++) { p[e] = expf(pr[e]-mx); sm2 += p[e]; }
        for (int e = 0; e < NEXP; e++) p[e] /= sm2;
        float tw = 0.f;
        int   idx[TOPK]; float val[TOPK];
        for (int kk = 0; kk < TOPK; kk++) {
            int bi = 0; float bv = -1.f;
            for (int e = 0; e < NEXP; e++) if (p[e] > bv) { bv = p[e]; bi = e; }
            idx[kk] = bi; val[kk] = bv; p[bi] = -2.f; tw += bv;
        }
        for (int kk = 0; kk < TOPK; kk++) {
            topi[t*TOPK+kk] = idx[kk];
            topw[t*TOPK+kk] = val[kk] / tw;
        }
    }
}

// ---------------- routing build ----------------
__global__ void zero32_k(int* cnt) { if (threadIdx.x < NEXP) cnt[threadIdx.x] = 0; }
__global__ void count_k(const int* __restrict__ topi, int* __restrict__ cnt)
{
    int i = blockIdx.x*256 + threadIdx.x;
    if (i < T_TOK*TOPK) atomicAdd(&cnt[topi[i]], 1);
}
__global__ void scan_k(const int* __restrict__ cnt, int* __restrict__ off, int* __restrict__ cur)
{
    if (threadIdx.x == 0) {
        int a = 0;
        for (int e = 0; e < NEXP; e++) { off[e] = a; cur[e] = a; a += cnt[e]; }
        off[NEXP] = a;
    }
}
__global__ void fill_k(const int* __restrict__ topi, int* __restrict__ cur,
                       int* __restrict__ ptok, int* __restrict__ ppos)
{
    int i = blockIdx.x*256 + threadIdx.x;
    if (i < T_TOK*TOPK) {
        int e = topi[i];
        int p = atomicAdd(&cur[e], 1);
        ptok[p] = i / TOPK;
        ppos[i] = p;
    }
}

// ---------------- MoE reduction ----------------
__global__ void moe_reduce_k(const float* __restrict__ down, const int* __restrict__ ppos,
                             const float* __restrict__ topw, const float* __restrict__ h,
                             float* __restrict__ out)
{
    int t = blockIdx.x;
    int pos[TOPK]; float w[TOPK];
#pragma unroll
    for (int kk = 0; kk < TOPK; kk++) { pos[kk] = ppos[t*TOPK+kk]; w[kk] = topw[t*TOPK+kk]; }
    for (int c = threadIdx.x; c < HID; c += blockDim.x) {
        float s = h[(long)t*HID + c];
#pragma unroll
        for (int kk = 0; kk < TOPK; kk++) s += down[(long)pos[kk]*HID + c] * w[kk];
        out[(long)t*HID + c] = s;
    }
}

// ---------------- shared-expert sigmoid gate ----------------
__global__ void shgate_k(const float* __restrict__ x2, const float* __restrict__ w,
                         float* __restrict__ sig)
{
    int t = blockIdx.x;
    float s = 0.f;
    for (int i = threadIdx.x; i < HID; i += blockDim.x) s += x2[(long)t*HID + i] * w[i];
    __shared__ float red[32];
    for (int o = 16; o > 0; o >>= 1) s += __shfl_xor_sync(0xffffffffu, s, o);
    int warp = threadIdx.x >> 5, lane = threadIdx.x & 31;
    if (lane == 0) red[warp] = s;
    __syncthreads();
    if (warp == 0) {
        s = (lane < (blockDim.x >> 5)) ? red[lane] : 0.f;
        for (int o = 16; o > 0; o >>= 1) s += __shfl_xor_sync(0xffffffffu, s, o);
        if (lane == 0) sig[t] = 1.f / (1.f + expf(-s));
    }
}

// ---------------- host launch ----------------
extern "C" void kernel_launch(void* const* d_in, const int* in_sizes, int n_in,
                              void* d_out, int out_size)
{
    (void)in_sizes; (void)out_size;
    if (n_in < 17) return;
    const float* hidden = (const float*)d_in[0];
    const float* ln1    = (const float*)d_in[1];
    const float* ln2    = (const float*)d_in[2];
    const float* qnw    = (const float*)d_in[3];
    const float* knw    = (const float*)d_in[4];
    const float* Wq     = (const float*)d_in[5];
    const float* Wk     = (const float*)d_in[6];
    const float* Wv     = (const float*)d_in[7];
    const float* Wo     = (const float*)d_in[8];
    const float* Wr     = (const float*)d_in[9];
    const float* Weg    = (const float*)d_in[10];
    const float* Weu    = (const float*)d_in[11];
    const float* Wed    = (const float*)d_in[12];
    const float* Wsg    = (const float*)d_in[13];
    const float* Wsu    = (const float*)d_in[14];
    const float* Wsd    = (const float*)d_in[15];
    const float* Wshg   = (const float*)d_in[16];
    float* out = (float*)d_out;

    float *xn, *qkvb, *hb, *actg, *shg, *down, *cosT, *sinT, *topw, *sig;
    int *topi, *cnt, *off, *cur, *ptok, *ppos;
    __half *xh, *atth, *acth, *shh;
    __half *WqkvT, *WoT, *WegT, *WeuT, *WedT, *WsgT, *WsuT, *WsdT;
    cudaGetSymbolAddress((void**)&xn,    g_xn);
    cudaGetSymbolAddress((void**)&qkvb,  g_qkv);
    cudaGetSymbolAddress((void**)&hb,    g_h);
    cudaGetSymbolAddress((void**)&actg,  g_actg);
    cudaGetSymbolAddress((void**)&shg,   g_shg);
    cudaGetSymbolAddress((void**)&down,  g_down);
    cudaGetSymbolAddress((void**)&cosT,  g_cos);
    cudaGetSymbolAddress((void**)&sinT,  g_sin);
    cudaGetSymbolAddress((void**)&topi,  g_topi);
    cudaGetSymbolAddress((void**)&topw,  g_topw);
    cudaGetSymbolAddress((void**)&cnt,   g_cnt);
    cudaGetSymbolAddress((void**)&off,   g_off);
    cudaGetSymbolAddress((void**)&cur,   g_cur);
    cudaGetSymbolAddress((void**)&ptok,  g_ptok);
    cudaGetSymbolAddress((void**)&ppos,  g_ppos);
    cudaGetSymbolAddress((void**)&sig,   g_sig);
    cudaGetSymbolAddress((void**)&xh,    g_xh);
    cudaGetSymbolAddress((void**)&atth,  g_atth);
    cudaGetSymbolAddress((void**)&acth,  g_acth);
    cudaGetSymbolAddress((void**)&shh,   g_shh);
    cudaGetSymbolAddress((void**)&WqkvT, g_Wqkv);
    cudaGetSymbolAddress((void**)&WoT,   g_WoT);
    cudaGetSymbolAddress((void**)&WegT,  g_WegT);
    cudaGetSymbolAddress((void**)&WeuT,  g_WeuT);
    cudaGetSymbolAddress((void**)&WedT,  g_WedT);
    cudaGetSymbolAddress((void**)&WsgT,  g_WsgT);
    cudaGetSymbolAddress((void**)&WsuT,  g_WsuT);
    cudaGetSymbolAddress((void**)&WsdT,  g_WsdT);

    cudaFuncSetAttribute(flash_tc_k, cudaFuncAttributeMaxDynamicSharedMemorySize, FLASH2_SMEM_BYTES);
    cudaFuncSetAttribute(mmh_k<0,false,false>, cudaFuncAttributeMaxDynamicSharedMemorySize, MMH_SMEM_BYTES);
    cudaFuncSetAttribute(mmh_k<1,false,false>, cudaFuncAttributeMaxDynamicSharedMemorySize, MMH_SMEM_BYTES);
    cudaFuncSetAttribute(mmh_k<2,false,false>, cudaFuncAttributeMaxDynamicSharedMemorySize, MMH_SMEM_BYTES);
    cudaFuncSetAttribute(mmh_k<3,false,false>, cudaFuncAttributeMaxDynamicSharedMemorySize, MMH_SMEM_BYTES);
    cudaFuncSetAttribute(mmh_k<0,true,true>,   cudaFuncAttributeMaxDynamicSharedMemorySize, MMH_SMEM_BYTES);
    cudaFuncSetAttribute(mmh_k<2,true,true>,   cudaFuncAttributeMaxDynamicSharedMemorySize, MMH_SMEM_BYTES);
    cudaFuncSetAttribute(mmh_k<0,false,true>,  cudaFuncAttributeMaxDynamicSharedMemorySize, MMH_SMEM_BYTES);

    dim3 tb(32, 8);
    // --- weight transpose+fp16 conversion (once per launch) ---
    tcvt_k<<<dim3(4096/32, 2048/32), tb>>>(Wq,  WqkvT, HID, 4096);
    tcvt_k<<<dim3( 512/32, 2048/32), tb>>>(Wk,  WqkvT + (long)4096*HID, HID, 512);
    tcvt_k<<<dim3( 512/32, 2048/32), tb>>>(Wv,  WqkvT + (long)4608*HID, HID, 512);
    tcvt_k<<<dim3(2048/32, 4096/32), tb>>>(Wo,  WoT,  4096, 2048);
    tcvt_k<<<dim3( 768/32, 2048/32, NEXP), tb>>>(Weg, WegT, HID, EI);
    tcvt_k<<<dim3( 768/32, 2048/32, NEXP), tb>>>(Weu, WeuT, HID, EI);
    tcvt_k<<<dim3(2048/32,  768/32, NEXP), tb>>>(Wed, WedT, EI, HID);
    tcvt_k<<<dim3(4096/32, 2048/32), tb>>>(Wsg, WsgT, HID, SI);
    tcvt_k<<<dim3(4096/32, 2048/32), tb>>>(Wsu, WsuT, HID, SI);
    tcvt_k<<<dim3(2048/32, 4096/32), tb>>>(Wsd, WsdT, SI, HID);

    // --- attention block ---
    rmsnorm_k<<<T_TOK, 256>>>(hidden, ln1, xn, xh);

    mmh_k<0,false,false><<<dim3(QKVN/128, 32), 256, MMH_SMEM_BYTES>>>(
        T_TOK, QKVN, HID, xh, HID, WqkvT, 0, qkvb, nullptr, QKVN, nullptr, nullptr, nullptr);

    rope_tab_k<<<SEQ, HDIM/2>>>(cosT, sinT);
    qknr_k<<<T_TOK*NHEAD, HDIM>>>(qkvb, qnw, NHEAD, 0, 0, cosT, sinT);
    qknr_k<<<T_TOK*NKVH,  HDIM>>>(qkvb, knw, NKVH, NHEAD*HDIM, 1, cosT, sinT);
    vround_k<<<T_TOK, 128>>>(qkvb);

    flash_tc_k<<<dim3(SEQ/64, NHEAD, BATCH), 128, FLASH2_SMEM_BYTES>>>(qkvb, atth);

    // h = hidden + att @ Wo
    mmh_k<1,false,false><<<dim3(16, 32), 256, MMH_SMEM_BYTES>>>(
        T_TOK, HID, NHEAD*HDIM, atth, NHEAD*HDIM, WoT, 0, hb, nullptr, HID, nullptr, nullptr, hidden);

    // --- MoE block ---
    rmsnorm_k<<<T_TOK, 256>>>(hb, ln2, xn, xh);

    router_k<<<T_TOK, 128>>>(xn, Wr, topi, topw);
    zero32_k<<<1, 32>>>(cnt);
    count_k<<<(T_TOK*TOPK+255)/256, 256>>>(topi, cnt);
    scan_k<<<1, 32>>>(cnt, off, cur);
    fill_k<<<(T_TOK*TOPK+255)/256, 256>>>(topi, cur, ptok, ppos);

    // experts: gate -> actg (f32); up -> acth = silu(actg)*up (fp16); down -> down (f32)
    mmh_k<0,true,true><<<dim3(EI/128, 32, NEXP), 256, MMH_SMEM_BYTES>>>(
        0, EI, HID, xh, HID, WegT, (long)EI*HID, actg, nullptr, EI, off, ptok, nullptr);
    mmh_k<2,true,true><<<dim3(EI/128, 32, NEXP), 256, MMH_SMEM_BYTES>>>(
        0, EI, HID, xh, HID, WeuT, (long)EI*HID, nullptr, acth, EI, off, ptok, actg);
    mmh_k<0,false,true><<<dim3(HID/128, 32, NEXP), 256, MMH_SMEM_BYTES>>>(
        0, HID, EI, acth, EI, WedT, (long)HID*EI, down, nullptr, HID, off, nullptr, nullptr);

    moe_reduce_k<<<T_TOK, 256>>>(down, ppos, topw, hb, out);

    // --- shared expert ---
    mmh_k<0,false,false><<<dim3(SI/128, 32), 256, MMH_SMEM_BYTES>>>(
        T_TOK, SI, HID, xh, HID, WsgT, 0, shg, nullptr, SI, nullptr, nullptr, nullptr);
    mmh_k<2,false,false><<<dim3(SI/128, 32), 256, MMH_SMEM_BYTES>>>(
        T_TOK, SI, HID, xh, HID, WsuT, 0, nullptr, shh, SI, nullptr, nullptr, shg);
    shgate_k<<<T_TOK, 256>>>(xn, Wshg, sig);
    mmh_k<3,false,false><<<dim3(HID/128, 32), 256, MMH_SMEM_BYTES>>>(
        T_TOK, HID, SI, shh, SI, WsdT, 0, out, nullptr, HID, nullptr, nullptr, sig);
}

// round 10
// speedup vs baseline: 5.7829x; 1.0618x over previous
#include <cuda_runtime.h>
#include <cuda_fp16.h>
#include <math.h>
#include <stdint.h>

// ---------------- problem constants ----------------
#define T_TOK 4096
#define HID   2048
#define SEQ   1024
#define BATCH 4
#define NHEAD 32
#define NKVH  4
#define HDIM  128
#define NEXP  32
#define TOPK  8
#define EI    768
#define SI    4096
#define GQA   8
#define EPSV  1e-6f
#define QKVN  (NHEAD*HDIM + 2*NKVH*HDIM)   // 5120

// ---------------- scratch (fp32) ----------------
__device__ float g_xn  [T_TOK*HID];
__device__ float g_qkv [T_TOK*QKVN];
__device__ float g_h   [T_TOK*HID];
__device__ float g_cos[SEQ*(HDIM/2)];
__device__ float g_sin[SEQ*(HDIM/2)];
__device__ int   g_topi[T_TOK*TOPK];
__device__ float g_topw[T_TOK*TOPK];
__device__ int   g_cnt[NEXP];
__device__ int   g_off[NEXP+1];
__device__ int   g_cur[NEXP];
__device__ int   g_ptok[T_TOK*TOPK];
__device__ int   g_ppos[T_TOK*TOPK];
__device__ float g_sig[T_TOK];
// ---------------- scratch (fp16) ----------------
__device__ __half g_xh   [T_TOK*HID];
__device__ __half g_kh   [T_TOK*NKVH*HDIM];
__device__ __half g_vh   [T_TOK*NKVH*HDIM];
__device__ __half g_atth [T_TOK*NHEAD*HDIM];
__device__ __half g_gateh[(long)T_TOK*TOPK*EI];
__device__ __half g_acth [(long)T_TOK*TOPK*EI];
__device__ __half g_downh[(long)T_TOK*TOPK*HID];
__device__ __half g_shgh [T_TOK*SI];
__device__ __half g_shh  [T_TOK*SI];
// fp16 transposed weights [N][K]
__device__ __half g_Wqkv[QKVN*HID];
__device__ __half g_WoT [HID*NHEAD*HDIM];
__device__ __half g_WegT[(long)NEXP*EI*HID];
__device__ __half g_WeuT[(long)NEXP*EI*HID];
__device__ __half g_WedT[(long)NEXP*HID*EI];
__device__ __half g_WsgT[SI*HID];
__device__ __half g_WsuT[SI*HID];
__device__ __half g_WsdT[HID*SI];

// ---------------- helpers ----------------
__device__ __forceinline__ uint32_t smem_u32(const void* p){
    uint32_t a;
    asm("{ .reg .u64 t; cvta.to.shared.u64 t, %1; cvt.u32.u64 %0, t; }" : "=r"(a) : "l"(p));
    return a;
}
__device__ __forceinline__ void cp_async16(uint32_t saddr, const void* gaddr, uint32_t sz){
    asm volatile("cp.async.cg.shared.global [%0], [%1], 16, %2;"
        :: "r"(saddr), "l"(gaddr), "r"(sz) : "memory");
}
__device__ __forceinline__ void cp_commit(){
    asm volatile("cp.async.commit_group;" ::: "memory");
}
template<int N>
__device__ __forceinline__ void cp_wait(){
    asm volatile("cp.async.wait_group %0;" :: "n"(N) : "memory");
}
__device__ __forceinline__ void mma_f16(float* c, uint32_t a0, uint32_t a1, uint32_t a2, uint32_t a3,
                                        uint32_t b0, uint32_t b1)
{
    asm volatile("mma.sync.aligned.m16n8k16.row.col.f32.f16.f16.f32 "
        "{%0,%1,%2,%3}, {%4,%5,%6,%7}, {%8,%9}, {%0,%1,%2,%3};"
        : "+f"(c[0]), "+f"(c[1]), "+f"(c[2]), "+f"(c[3])
        : "r"(a0), "r"(a1), "r"(a2), "r"(a3), "r"(b0), "r"(b1));
}
#define LDSM_X4(r0, r1, r2, r3, addr) \
    asm volatile("ldmatrix.sync.aligned.m8n8.x4.shared.b16 {%0,%1,%2,%3}, [%4];" \
        : "=r"(r0), "=r"(r1), "=r"(r2), "=r"(r3) : "r"(addr))
#define LDSM_X4_T(r0, r1, r2, r3, addr) \
    asm volatile("ldmatrix.sync.aligned.m8n8.x4.trans.shared.b16 {%0,%1,%2,%3}, [%4];" \
        : "=r"(r0), "=r"(r1), "=r"(r2), "=r"(r3) : "r"(addr))
__device__ __forceinline__ uint32_t packh2(float a, float b){
    __half2 h = __floats2half2_rn(a, b);
    return *reinterpret_cast<uint32_t*>(&h);
}

// ---------------- weight transpose + fp16 convert: src[K][N] -> dst[N][K] ----------------
__global__ void tcvt_k(const float* __restrict__ src, __half* __restrict__ dst, int K, int N)
{
    __shared__ float t[32][33];
    long z = blockIdx.z;
    src += z * (long)K * N;
    dst += z * (long)K * N;
    int n0 = blockIdx.x*32, k0 = blockIdx.y*32;
    int tx = threadIdx.x, ty = threadIdx.y;
#pragma unroll
    for (int i = 0; i < 32; i += 8)
        t[tx][ty+i] = src[(long)(k0+ty+i)*N + n0+tx];
    __syncthreads();
#pragma unroll
    for (int i = 0; i < 32; i += 8)
        dst[(long)(n0+ty+i)*K + k0+tx] = __float2half(t[ty+i][tx]);
}

// ---------------- rmsnorm over HID (writes fp32 + fp16) ----------------
__global__ void rmsnorm_k(const float* __restrict__ x, const float* __restrict__ w,
                          float* __restrict__ y, __half* __restrict__ yh)
{
    int row = blockIdx.x;
    const float* xr = x + (long)row*HID;
    float ss = 0.f;
    for (int i = threadIdx.x; i < HID; i += blockDim.x) { float v = xr[i]; ss += v*v; }
    __shared__ float red[32];
    for (int o = 16; o > 0; o >>= 1) ss += __shfl_xor_sync(0xffffffffu, ss, o);
    int warp = threadIdx.x >> 5, lane = threadIdx.x & 31;
    if (lane == 0) red[warp] = ss;
    __syncthreads();
    if (warp == 0) {
        ss = (lane < (blockDim.x >> 5)) ? red[lane] : 0.f;
        for (int o = 16; o > 0; o >>= 1) ss += __shfl_xor_sync(0xffffffffu, ss, o);
        if (lane == 0) red[0] = ss;
    }
    __syncthreads();
    float r = rsqrtf(red[0] / (float)HID + EPSV);
    for (int i = threadIdx.x; i < HID; i += blockDim.x) {
        float v = xr[i] * r * w[i];
        y [(long)row*HID + i] = v;
        yh[(long)row*HID + i] = __float2half(v);
    }
}

// ---------------- rope tables ----------------
__global__ void rope_tab_k(float* __restrict__ cosT, float* __restrict__ sinT)
{
    int s = blockIdx.x;
    int i = threadIdx.x;
    float inv = expf(-((float)(2*i) / (float)HDIM) * logf(1000000.0f));
    float ang = (float)s * inv;
    cosT[s*(HDIM/2)+i] = cosf(ang);
    sinT[s*(HDIM/2)+i] = sinf(ang);
}

// ---------------- per-head rmsnorm + rope; optional fp16 out buffer ----------------
__global__ void qknr_k(float* __restrict__ qkv, __half* __restrict__ hout,
                       const float* __restrict__ nw, int nh, int colOff,
                       const float* __restrict__ cosT, const float* __restrict__ sinT)
{
    long bh = blockIdx.x;
    int t = (int)(bh / nh);
    int head = (int)(bh % nh);
    int s = t & (SEQ-1);
    int d = threadIdx.x;
    float* xp = qkv + (long)t*QKVN + colOff + head*HDIM;
    float v = xp[d];
    float ss = v*v;
    for (int o = 16; o > 0; o >>= 1) ss += __shfl_xor_sync(0xffffffffu, ss, o);
    __shared__ float red[4];
    if ((threadIdx.x & 31) == 0) red[threadIdx.x >> 5] = ss;
    __syncthreads();
    float tot = red[0]+red[1]+red[2]+red[3];
    float r = rsqrtf(tot / (float)HDIM + EPSV);
    float xn = v * r * nw[d];
    __shared__ float xsh[HDIM];
    xsh[d] = xn;
    __syncthreads();
    float c, sn, oth;
    if (d < HDIM/2) { c = cosT[s*(HDIM/2)+d];          sn = sinT[s*(HDIM/2)+d];          oth = -xsh[d+HDIM/2]; }
    else            { c = cosT[s*(HDIM/2)+d-HDIM/2];   sn = sinT[s*(HDIM/2)+d-HDIM/2];   oth =  xsh[d-HDIM/2]; }
    float val = xn*c + oth*sn;
    if (hout) hout[((long)t*nh + head)*HDIM + d] = __float2half(val);
    else      xp[d] = val;
}

// ---------------- V slice f32 -> fp16 ----------------
__global__ void vcvt_k(const float* __restrict__ qkv, __half* __restrict__ vh)
{
    long t = blockIdx.x;
    const float* src = qkv + t*QKVN + NHEAD*HDIM + NKVH*HDIM;
    __half* dst = vh + t*(NKVH*HDIM);
    for (int i = threadIdx.x; i < NKVH*HDIM; i += blockDim.x)
        dst[i] = __float2half(src[i]);
}

// ---------------- fp16 tensor-core flash attention (online softmax fp32) ----------------
// 64x64 tiles, 4 warps x 16 q-rows. K/V fp16 via cp.async; P fp16 through smem.
#define KPITCH 136
#define VPITCH 136
#define PPITCH 72
#define FLASHH_SMEM_BYTES ((64*KPITCH + 64*VPITCH + 64*PPITCH)*2)

__global__ void __launch_bounds__(128)
flash_h_k(const float* __restrict__ qkv, const __half* __restrict__ kh,
          const __half* __restrict__ vh, __half* __restrict__ og)
{
    extern __shared__ __half fsh[];
    uint32_t sb = smem_u32(fsh);
    uint32_t KsU = sb;
    uint32_t VsU = sb + (uint32_t)(64*KPITCH)*2;
    uint32_t PsU = VsU + (uint32_t)(64*VPITCH)*2;
    __half* Ps = fsh + 64*KPITCH + 64*VPITCH;

    int qt = blockIdx.x, h = blockIdx.y, b = blockIdx.z;
    int kvh = h / GQA;
    int qs0 = qt*64;
    int tid = threadIdx.x, w = tid >> 5, lane = tid & 31;
    int g = lane >> 2, tg = lane & 3;
    float scale = rsqrtf((float)HDIM);

    // Q fragments (fp16 packed), rows w*16+g and +8
    uint32_t qa[8][4];
    {
        const float* q0 = qkv + (long)(b*SEQ + qs0 + w*16 + g)*QKVN + h*HDIM;
        const float* q8 = q0 + 8L*QKVN;
#pragma unroll
        for (int ks = 0; ks < 8; ks++) {
            int kb = ks*16;
            qa[ks][0] = packh2(q0[kb+2*tg]*scale,   q0[kb+2*tg+1]*scale);
            qa[ks][1] = packh2(q8[kb+2*tg]*scale,   q8[kb+2*tg+1]*scale);
            qa[ks][2] = packh2(q0[kb+8+2*tg]*scale, q0[kb+8+2*tg+1]*scale);
            qa[ks][3] = packh2(q8[kb+8+2*tg]*scale, q8[kb+8+2*tg+1]*scale);
        }
    }

    float m0 = -1e30f, m1 = -1e30f, l0 = 0.f, l1 = 0.f;
    float oac[16][4];
#pragma unroll
    for (int nt = 0; nt < 16; nt++)
#pragma unroll
        for (int r = 0; r < 4; r++) oac[nt][r] = 0.f;

    long kbase = (long)(b*SEQ)*(NKVH*HDIM) + kvh*HDIM;
    int pr0 = (w*16+g)*PPITCH, pr1 = (w*16+g+8)*PPITCH;

    // ldmatrix lane bases
    uint32_t kFrag = KsU + (uint32_t)(((((lane>>4)<<3) + (lane&7))*KPITCH + ((lane>>3)&1)*8)*2);
    uint32_t pFrag = PsU + (uint32_t)(((w*16 + (lane&15))*PPITCH + ((lane>>4)&1)*8)*2);
    uint32_t vFrag = VsU + (uint32_t)(((lane&15)*VPITCH + ((lane>>4)<<3))*2);

    for (int jt = 0; jt <= qt; jt++) {
        __syncthreads();                 // Ks/Vs/Ps free for reuse
        {
            const __half* kr = kh + kbase + (long)(jt*64)*(NKVH*HDIM);
#pragma unroll
            for (int i = 0; i < 8; i++) {
                int idx = i*128 + tid;
                int r = idx >> 4, c = idx & 15;
                cp_async16(KsU + (uint32_t)(r*KPITCH + c*8)*2, kr + (long)r*(NKVH*HDIM) + c*8, 16);
            }
            cp_commit();
            const __half* vr = vh + kbase + (long)(jt*64)*(NKVH*HDIM);
#pragma unroll
            for (int i = 0; i < 8; i++) {
                int idx = i*128 + tid;
                int r = idx >> 4, c = idx & 15;
                cp_async16(VsU + (uint32_t)(r*VPITCH + c*8)*2, vr + (long)r*(NKVH*HDIM) + c*8, 16);
            }
            cp_commit();
        }
        cp_wait<1>(); __syncthreads();   // K ready (V in flight)

        // S = Q K^T  (fp16 mma, 8 k16 steps, 4 n-groups of 16)
        float sacc[8][4];
#pragma unroll
        for (int nt = 0; nt < 8; nt++)
#pragma unroll
            for (int r = 0; r < 4; r++) sacc[nt][r] = 0.f;
#pragma unroll
        for (int ks = 0; ks < 8; ks++) {
#pragma unroll
            for (int ng = 0; ng < 4; ng++) {
                uint32_t r0, r1, r2, r3;
                LDSM_X4(r0, r1, r2, r3, kFrag + (uint32_t)(ng*16*KPITCH)*2 + ks*32);
                mma_f16(sacc[ng*2],   qa[ks][0], qa[ks][1], qa[ks][2], qa[ks][3], r0, r1);
                mma_f16(sacc[ng*2+1], qa[ks][0], qa[ks][1], qa[ks][2], qa[ks][3], r2, r3);
            }
        }
        // causal mask (diagonal tile)
        int row0 = qs0 + w*16 + g, row1 = row0 + 8;
        if (jt == qt) {
            int cb = jt*64;
#pragma unroll
            for (int nt = 0; nt < 8; nt++) {
                int c0 = cb + nt*8 + 2*tg;
                if (c0   > row0) sacc[nt][0] = -1e30f;
                if (c0+1 > row0) sacc[nt][1] = -1e30f;
                if (c0   > row1) sacc[nt][2] = -1e30f;
                if (c0+1 > row1) sacc[nt][3] = -1e30f;
            }
        }
        // online softmax (fp32)
        float mx0 = m0, mx1 = m1;
#pragma unroll
        for (int nt = 0; nt < 8; nt++) {
            mx0 = fmaxf(mx0, fmaxf(sacc[nt][0], sacc[nt][1]));
            mx1 = fmaxf(mx1, fmaxf(sacc[nt][2], sacc[nt][3]));
        }
        mx0 = fmaxf(mx0, __shfl_xor_sync(0xffffffffu, mx0, 1));
        mx0 = fmaxf(mx0, __shfl_xor_sync(0xffffffffu, mx0, 2));
        mx1 = fmaxf(mx1, __shfl_xor_sync(0xffffffffu, mx1, 1));
        mx1 = fmaxf(mx1, __shfl_xor_sync(0xffffffffu, mx1, 2));
        float c0 = expf(m0 - mx0), c1 = expf(m1 - mx1);
        float s0 = 0.f, s1 = 0.f;
#pragma unroll
        for (int nt = 0; nt < 8; nt++) {
            sacc[nt][0] = expf(sacc[nt][0] - mx0);
            sacc[nt][1] = expf(sacc[nt][1] - mx0);
            sacc[nt][2] = expf(sacc[nt][2] - mx1);
            sacc[nt][3] = expf(sacc[nt][3] - mx1);
            s0 += sacc[nt][0] + sacc[nt][1];
            s1 += sacc[nt][2] + sacc[nt][3];
        }
        s0 += __shfl_xor_sync(0xffffffffu, s0, 1);
        s0 += __shfl_xor_sync(0xffffffffu, s0, 2);
        s1 += __shfl_xor_sync(0xffffffffu, s1, 1);
        s1 += __shfl_xor_sync(0xffffffffu, s1, 2);
        l0 = l0*c0 + s0;  l1 = l1*c1 + s1;  m0 = mx0;  m1 = mx1;
#pragma unroll
        for (int nt = 0; nt < 16; nt++) {
            oac[nt][0] *= c0; oac[nt][1] *= c0;
            oac[nt][2] *= c1; oac[nt][3] *= c1;
        }
        // write P fp16
#pragma unroll
        for (int nt = 0; nt < 8; nt++) {
            int pc = nt*8 + 2*tg;
            *reinterpret_cast<__half2*>(Ps + pr0 + pc) = __floats2half2_rn(sacc[nt][0], sacc[nt][1]);
            *reinterpret_cast<__half2*>(Ps + pr1 + pc) = __floats2half2_rn(sacc[nt][2], sacc[nt][3]);
        }
        cp_wait<0>(); __syncthreads();   // V ready + Ps visible

        // O += P V  (4 k16 steps over kv64, 8 n-groups of 16 d-cols)
#pragma unroll
        for (int ks = 0; ks < 4; ks++) {
            uint32_t a0, a1, a2, a3;
            LDSM_X4(a0, a1, a2, a3, pFrag + ks*32);
#pragma unroll
            for (int ng = 0; ng < 8; ng++) {
                uint32_t r0, r1, r2, r3;
                LDSM_X4_T(r0, r1, r2, r3, vFrag + (uint32_t)(ks*16*VPITCH)*2 + ng*32);
                mma_f16(oac[ng*2],   a0, a1, a2, a3, r0, r1);
                mma_f16(oac[ng*2+1], a0, a1, a2, a3, r2, r3);
            }
        }
    }

    float i0 = 1.f/l0, i1 = 1.f/l1;
    long o0 = ((long)(b*SEQ + qs0 + w*16 + g)*NHEAD + h)*HDIM;
    long o8 = o0 + 8L*NHEAD*HDIM;
#pragma unroll
    for (int nt = 0; nt < 16; nt++) {
        int c = nt*8 + 2*tg;
        *reinterpret_cast<__half2*>(&og[o0+c]) = __floats2half2_rn(oac[nt][0]*i0, oac[nt][1]*i0);
        *reinterpret_cast<__half2*>(&og[o8+c]) = __floats2half2_rn(oac[nt][2]*i1, oac[nt][3]*i1);
    }
}

// ---------------- fp16 mma GEMM: 128x128x32, 256 thr (2x4 warps), ldmatrix, 3-stage ----------------
// C[M,N] = A[M,K] @ B^T, B stored [N][K] fp16.
// EPI: 0=store f32, 1=resid add(extra), 3=C += acc*extra[row],
//      4=Ch = half(acc), 5=Ch = half(silu(extraH)*acc)
#define HPITCH 40
#define TBUF_H (128*HPITCH)
#define STAGE_B (2*TBUF_H*2)
#define NSTAGE 3
#define MMH_SMEM_BYTES (NSTAGE*STAGE_B)

template<int EPI, bool AIDX, bool EXPERT>
__global__ void __launch_bounds__(256, 2)
mmh_k(int M, int N, int Kd,
      const __half* __restrict__ A, int lda,
      const __half* __restrict__ B, long strideB,
      float* __restrict__ C, __half* __restrict__ Ch, int ldc,
      const int* __restrict__ offs, const int* __restrict__ aidx,
      const float* __restrict__ extra, const __half* __restrict__ extraH)
{
    extern __shared__ __align__(16) char smh[];
    uint32_t sb = smem_u32(smh);

    int rbase = 0, mrows = M;
    const __half* Bp = B;
    if (EXPERT) {
        int e = blockIdx.z;
        rbase = offs[e];
        mrows = offs[e+1] - rbase;
        Bp = B + (long)e * strideB;
    }
    int bm0 = blockIdx.y * 128;
    if (bm0 >= mrows) return;
    int bn0 = blockIdx.x * 128;

    int tid = threadIdx.x, lane = tid & 31, wid = tid >> 5;
    int g = lane >> 2, tg = lane & 3;
    int warp_m = wid & 1, warp_n = wid >> 1;   // 2x4 warps

    // staging: thread covers row tid>>1, 32 contiguous bytes at half-offset (tid&1)*16
    const char* aptr;
    uint32_t aok;
    {
        int lr = bm0 + (tid >> 1);
        if (lr < mrows) {
            long gr = AIDX ? (long)aidx[rbase + lr] : (long)(rbase + lr);
            aptr = (const char*)(A + gr*(long)lda + (tid & 1)*16);
            aok = 16;
        } else { aptr = (const char*)A; aok = 0; }
    }
    const char* bptr = (const char*)(Bp + (long)(bn0 + (tid >> 1))*Kd + (tid & 1)*16);
    uint32_t aoff = (uint32_t)((tid >> 1)*HPITCH + (tid & 1)*16)*2;
    uint32_t boff = (uint32_t)(TBUF_H + (tid >> 1)*HPITCH + (tid & 1)*16)*2;

    uint32_t aFragB = (uint32_t)((warp_m*64 + (lane & 15))*HPITCH + ((lane >> 4) & 1)*8)*2;
    uint32_t bFragB = (uint32_t)(TBUF_H + (warp_n*32 + ((lane >> 4) << 3) + (lane & 7))*HPITCH
                                 + ((lane >> 3) & 1)*8)*2;

    float acc[4][4][4];
#pragma unroll
    for (int mt = 0; mt < 4; mt++)
#pragma unroll
        for (int nt = 0; nt < 4; nt++)
#pragma unroll
            for (int r = 0; r < 4; r++) acc[mt][nt][r] = 0.f;

    int nc = Kd >> 5;

#pragma unroll
    for (int pc = 0; pc < 2; pc++) {
        if (pc < nc) {
            uint32_t s0 = sb + pc*STAGE_B;
            long kadv = (long)pc*64;
            cp_async16(s0 + aoff,      aptr + kadv,      aok);
            cp_async16(s0 + aoff + 16, aptr + kadv + 16, aok);
            cp_async16(s0 + boff,      bptr + kadv,      16);
            cp_async16(s0 + boff + 16, bptr + kadv + 16, 16);
        }
        cp_commit();
    }

    for (int c = 0; c < nc; c++) {
        int p = c % NSTAGE;
        cp_wait<1>();
        __syncthreads();
        if (c + 2 < nc) {
            int q = (c + 2) % NSTAGE;
            uint32_t s0 = sb + q*STAGE_B;
            long kadv = (long)(c + 2)*64;
            cp_async16(s0 + aoff,      aptr + kadv,      aok);
            cp_async16(s0 + aoff + 16, aptr + kadv + 16, aok);
            cp_async16(s0 + boff,      bptr + kadv,      16);
            cp_async16(s0 + boff + 16, bptr + kadv + 16, 16);
        }
        cp_commit();

        uint32_t aB = sb + p*STAGE_B + aFragB;
        uint32_t bB = sb + p*STAGE_B + bFragB;
#pragma unroll
        for (int ks = 0; ks < 2; ks++) {
            uint32_t a[4][4];
#pragma unroll
            for (int mt = 0; mt < 4; mt++)
                LDSM_X4(a[mt][0], a[mt][1], a[mt][2], a[mt][3],
                        aB + (uint32_t)(mt*16*HPITCH)*2 + ks*32);
            uint32_t bq[2][4];
#pragma unroll
            for (int ntp = 0; ntp < 2; ntp++)
                LDSM_X4(bq[ntp][0], bq[ntp][1], bq[ntp][2], bq[ntp][3],
                        bB + (uint32_t)(ntp*16*HPITCH)*2 + ks*32);
#pragma unroll
            for (int mt = 0; mt < 4; mt++)
#pragma unroll
                for (int nt = 0; nt < 4; nt++)
                    mma_f16(acc[mt][nt], a[mt][0], a[mt][1], a[mt][2], a[mt][3],
                            bq[nt >> 1][(nt & 1)*2], bq[nt >> 1][(nt & 1)*2 + 1]);
        }
    }

#pragma unroll
    for (int mt = 0; mt < 4; mt++) {
#pragma unroll
        for (int nt = 0; nt < 4; nt++) {
            int col = bn0 + warp_n*32 + nt*8 + 2*tg;
#pragma unroll
            for (int half = 0; half < 2; half++) {
                int lr = warp_m*64 + mt*16 + g + half*8;
                int grow = bm0 + lr;
                if (grow >= mrows) continue;
                long cr = rbase + grow;
                float v0 = acc[mt][nt][half*2+0];
                float v1 = acc[mt][nt][half*2+1];
                long o0 = cr*(long)ldc + col;
                if (EPI == 0) {
                    C[o0] = v0; C[o0+1] = v1;
                } else if (EPI == 1) {
                    C[o0]   = extra[o0]   + v0;
                    C[o0+1] = extra[o0+1] + v1;
                } else if (EPI == 3) {
                    float s = extra[grow];
                    C[o0]   += v0 * s;
                    C[o0+1] += v1 * s;
                } else if (EPI == 4) {
                    *reinterpret_cast<__half2*>(&Ch[o0]) = __floats2half2_rn(v0, v1);
                } else if (EPI == 5) {
                    float g0 = __half2float(extraH[o0]);
                    float g1 = __half2float(extraH[o0+1]);
                    *reinterpret_cast<__half2*>(&Ch[o0]) = __floats2half2_rn(
                        g0 / (1.f + expf(-g0)) * v0,
                        g1 / (1.f + expf(-g1)) * v1);
                }
            }
        }
    }
}

// ---------------- router ----------------
__global__ void router_k(const float* __restrict__ x2, const float* __restrict__ Wr,
                         int* __restrict__ topi, float* __restrict__ topw)
{
    int t = blockIdx.x;
    __shared__ float xs[HID];
    __shared__ float pr[NEXP];
    for (int i = threadIdx.x; i < HID; i += blockDim.x) xs[i] = x2[(long)t*HID + i];
    __syncthreads();
    if (threadIdx.x < NEXP) {
        int e = threadIdx.x;
        float d = 0.f;
        for (int i = 0; i < HID; i++) d += xs[i] * Wr[i*NEXP + e];
        pr[e] = d;
    }
    __syncthreads();
    if (threadIdx.x == 0) {
        float mx = -1e30f;
        for (int e = 0; e < NEXP; e++) mx = fmaxf(mx, pr[e]);
        float p[NEXP]; float sm2 = 0.f;
        for (int e = 0; e < NEXP; e++) { p[e] = expf(pr[e]-mx); sm2 += p[e]; }
        for (int e = 0; e < NEXP; e++) p[e] /= sm2;
        float tw = 0.f;
        int   idx[TOPK]; float val[TOPK];
        for (int kk = 0; kk < TOPK; kk++) {
            int bi = 0; float bv = -1.f;
            for (int e = 0; e < NEXP; e++) if (p[e] > bv) { bv = p[e]; bi = e; }
            idx[kk] = bi; val[kk] = bv; p[bi] = -2.f; tw += bv;
        }
        for (int kk = 0; kk < TOPK; kk++) {
            topi[t*TOPK+kk] = idx[kk];
            topw[t*TOPK+kk] = val[kk] / tw;
        }
    }
}

// ---------------- routing build ----------------
__global__ void zero32_k(int* cnt) { if (threadIdx.x < NEXP) cnt[threadIdx.x] = 0; }
__global__ void count_k(const int* __restrict__ topi, int* __restrict__ cnt)
{
    int i = blockIdx.x*256 + threadIdx.x;
    if (i < T_TOK*TOPK) atomicAdd(&cnt[topi[i]], 1);
}
__global__ void scan_k(const int* __restrict__ cnt, int* __restrict__ off, int* __restrict__ cur)
{
    if (threadIdx.x == 0) {
        int a = 0;
        for (int e = 0; e < NEXP; e++) { off[e] = a; cur[e] = a; a += cnt[e]; }
        off[NEXP] = a;
    }
}
__global__ void fill_k(const int* __restrict__ topi, int* __restrict__ cur,
                       int* __restrict__ ptok, int* __restrict__ ppos)
{
    int i = blockIdx.x*256 + threadIdx.x;
    if (i < T_TOK*TOPK) {
        int e = topi[i];
        int p = atomicAdd(&cur[e], 1);
        ptok[p] = i / TOPK;
        ppos[i] = p;
    }
}

// ---------------- MoE reduction (fp16 down) ----------------
__global__ void moe_reduce_k(const __half* __restrict__ down, const int* __restrict__ ppos,
                             const float* __restrict__ topw, const float* __restrict__ h,
                             float* __restrict__ out)
{
    int t = blockIdx.x;
    long pos[TOPK]; float w[TOPK];
#pragma unroll
    for (int kk = 0; kk < TOPK; kk++) { pos[kk] = ppos[t*TOPK+kk]; w[kk] = topw[t*TOPK+kk]; }
    for (int c = threadIdx.x; c < HID; c += blockDim.x) {
        float s = h[(long)t*HID + c];
#pragma unroll
        for (int kk = 0; kk < TOPK; kk++) s += __half2float(down[pos[kk]*HID + c]) * w[kk];
        out[(long)t*HID + c] = s;
    }
}

// ---------------- shared-expert sigmoid gate ----------------
__global__ void shgate_k(const float* __restrict__ x2, const float* __restrict__ w,
                         float* __restrict__ sig)
{
    int t = blockIdx.x;
    float s = 0.f;
    for (int i = threadIdx.x; i < HID; i += blockDim.x) s += x2[(long)t*HID + i] * w[i];
    __shared__ float red[32];
    for (int o = 16; o > 0; o >>= 1) s += __shfl_xor_sync(0xffffffffu, s, o);
    int warp = threadIdx.x >> 5, lane = threadIdx.x & 31;
    if (lane == 0) red[warp] = s;
    __syncthreads();
    if (warp == 0) {
        s = (lane < (blockDim.x >> 5)) ? red[lane] : 0.f;
        for (int o = 16; o > 0; o >>= 1) s += __shfl_xor_sync(0xffffffffu, s, o);
        if (lane == 0) sig[t] = 1.f / (1.f + expf(-s));
    }
}

// ---------------- host launch ----------------
extern "C" void kernel_launch(void* const* d_in, const int* in_sizes, int n_in,
                              void* d_out, int out_size)
{
    (void)in_sizes; (void)out_size;
    if (n_in < 17) return;
    const float* hidden = (const float*)d_in[0];
    const float* ln1    = (const float*)d_in[1];
    const float* ln2    = (const float*)d_in[2];
    const float* qnw    = (const float*)d_in[3];
    const float* knw    = (const float*)d_in[4];
    const float* Wq     = (const float*)d_in[5];
    const float* Wk     = (const float*)d_in[6];
    const float* Wv     = (const float*)d_in[7];
    const float* Wo     = (const float*)d_in[8];
    const float* Wr     = (const float*)d_in[9];
    const float* Weg    = (const float*)d_in[10];
    const float* Weu    = (const float*)d_in[11];
    const float* Wed    = (const float*)d_in[12];
    const float* Wsg    = (const float*)d_in[13];
    const float* Wsu    = (const float*)d_in[14];
    const float* Wsd    = (const float*)d_in[15];
    const float* Wshg   = (const float*)d_in[16];
    float* out = (float*)d_out;

    float *xn, *qkvb, *hb, *cosT, *sinT, *topw, *sig;
    int *topi, *cnt, *off, *cur, *ptok, *ppos;
    __half *xh, *kh, *vh, *atth, *gateh, *acth, *downh, *shgh, *shh;
    __half *WqkvT, *WoT, *WegT, *WeuT, *WedT, *WsgT, *WsuT, *WsdT;
    cudaGetSymbolAddress((void**)&xn,    g_xn);
    cudaGetSymbolAddress((void**)&qkvb,  g_qkv);
    cudaGetSymbolAddress((void**)&hb,    g_h);
    cudaGetSymbolAddress((void**)&cosT,  g_cos);
    cudaGetSymbolAddress((void**)&sinT,  g_sin);
    cudaGetSymbolAddress((void**)&topi,  g_topi);
    cudaGetSymbolAddress((void**)&topw,  g_topw);
    cudaGetSymbolAddress((void**)&cnt,   g_cnt);
    cudaGetSymbolAddress((void**)&off,   g_off);
    cudaGetSymbolAddress((void**)&cur,   g_cur);
    cudaGetSymbolAddress((void**)&ptok,  g_ptok);
    cudaGetSymbolAddress((void**)&ppos,  g_ppos);
    cudaGetSymbolAddress((void**)&sig,   g_sig);
    cudaGetSymbolAddress((void**)&xh,    g_xh);
    cudaGetSymbolAddress((void**)&kh,    g_kh);
    cudaGetSymbolAddress((void**)&vh,    g_vh);
    cudaGetSymbolAddress((void**)&atth,  g_atth);
    cudaGetSymbolAddress((void**)&gateh, g_gateh);
    cudaGetSymbolAddress((void**)&acth,  g_acth);
    cudaGetSymbolAddress((void**)&downh, g_downh);
    cudaGetSymbolAddress((void**)&shgh,  g_shgh);
    cudaGetSymbolAddress((void**)&shh,   g_shh);
    cudaGetSymbolAddress((void**)&WqkvT, g_Wqkv);
    cudaGetSymbolAddress((void**)&WoT,   g_WoT);
    cudaGetSymbolAddress((void**)&WegT,  g_WegT);
    cudaGetSymbolAddress((void**)&WeuT,  g_WeuT);
    cudaGetSymbolAddress((void**)&WedT,  g_WedT);
    cudaGetSymbolAddress((void**)&WsgT,  g_WsgT);
    cudaGetSymbolAddress((void**)&WsuT,  g_WsuT);
    cudaGetSymbolAddress((void**)&WsdT,  g_WsdT);

    cudaFuncSetAttribute(flash_h_k, cudaFuncAttributeMaxDynamicSharedMemorySize, FLASHH_SMEM_BYTES);
    cudaFuncSetAttribute(mmh_k<0,false,false>, cudaFuncAttributeMaxDynamicSharedMemorySize, MMH_SMEM_BYTES);
    cudaFuncSetAttribute(mmh_k<1,false,false>, cudaFuncAttributeMaxDynamicSharedMemorySize, MMH_SMEM_BYTES);
    cudaFuncSetAttribute(mmh_k<3,false,false>, cudaFuncAttributeMaxDynamicSharedMemorySize, MMH_SMEM_BYTES);
    cudaFuncSetAttribute(mmh_k<4,false,false>, cudaFuncAttributeMaxDynamicSharedMemorySize, MMH_SMEM_BYTES);
    cudaFuncSetAttribute(mmh_k<5,false,false>, cudaFuncAttributeMaxDynamicSharedMemorySize, MMH_SMEM_BYTES);
    cudaFuncSetAttribute(mmh_k<4,true,true>,   cudaFuncAttributeMaxDynamicSharedMemorySize, MMH_SMEM_BYTES);
    cudaFuncSetAttribute(mmh_k<5,true,true>,   cudaFuncAttributeMaxDynamicSharedMemorySize, MMH_SMEM_BYTES);
    cudaFuncSetAttribute(mmh_k<4,false,true>,  cudaFuncAttributeMaxDynamicSharedMemorySize, MMH_SMEM_BYTES);

    dim3 tb(32, 8);
    // --- weight transpose+fp16 conversion (once per launch) ---
    tcvt_k<<<dim3(4096/32, 2048/32), tb>>>(Wq,  WqkvT, HID, 4096);
    tcvt_k<<<dim3( 512/32, 2048/32), tb>>>(Wk,  WqkvT + (long)4096*HID, HID, 512);
    tcvt_k<<<dim3( 512/32, 2048/32), tb>>>(Wv,  WqkvT + (long)4608*HID, HID, 512);
    tcvt_k<<<dim3(2048/32, 4096/32), tb>>>(Wo,  WoT,  4096, 2048);
    tcvt_k<<<dim3( 768/32, 2048/32, NEXP), tb>>>(Weg, WegT, HID, EI);
    tcvt_k<<<dim3( 768/32, 2048/32, NEXP), tb>>>(Weu, WeuT, HID, EI);
    tcvt_k<<<dim3(2048/32,  768/32, NEXP), tb>>>(Wed, WedT, EI, HID);
    tcvt_k<<<dim3(4096/32, 2048/32), tb>>>(Wsg, WsgT, HID, SI);
    tcvt_k<<<dim3(4096/32, 2048/32), tb>>>(Wsu, WsuT, HID, SI);
    tcvt_k<<<dim3(2048/32, 4096/32), tb>>>(Wsd, WsdT, SI, HID);

    // --- attention block ---
    rmsnorm_k<<<T_TOK, 256>>>(hidden, ln1, xn, xh);

    mmh_k<0,false,false><<<dim3(QKVN/128, 32), 256, MMH_SMEM_BYTES>>>(
        T_TOK, QKVN, HID, xh, HID, WqkvT, 0, qkvb, nullptr, QKVN, nullptr, nullptr, nullptr, nullptr);

    rope_tab_k<<<SEQ, HDIM/2>>>(cosT, sinT);
    qknr_k<<<T_TOK*NHEAD, HDIM>>>(qkvb, nullptr, qnw, NHEAD, 0, cosT, sinT);
    qknr_k<<<T_TOK*NKVH,  HDIM>>>(qkvb, kh, knw, NKVH, NHEAD*HDIM, cosT, sinT);
    vcvt_k<<<T_TOK, 128>>>(qkvb, vh);

    flash_h_k<<<dim3(SEQ/64, NHEAD, BATCH), 128, FLASHH_SMEM_BYTES>>>(qkvb, kh, vh, atth);

    // h = hidden + att @ Wo
    mmh_k<1,false,false><<<dim3(16, 32), 256, MMH_SMEM_BYTES>>>(
        T_TOK, HID, NHEAD*HDIM, atth, NHEAD*HDIM, WoT, 0, hb, nullptr, HID, nullptr, nullptr, hidden, nullptr);

    // --- MoE block ---
    rmsnorm_k<<<T_TOK, 256>>>(hb, ln2, xn, xh);

    router_k<<<T_TOK, 128>>>(xn, Wr, topi, topw);
    zero32_k<<<1, 32>>>(cnt);
    count_k<<<(T_TOK*TOPK+255)/256, 256>>>(topi, cnt);
    scan_k<<<1, 32>>>(cnt, off, cur);
    fill_k<<<(T_TOK*TOPK+255)/256, 256>>>(topi, cur, ptok, ppos);

    // experts: gate -> gateh (fp16); up -> acth = silu(gateh)*up (fp16); down -> downh (fp16)
    mmh_k<4,true,true><<<dim3(EI/128, 32, NEXP), 256, MMH_SMEM_BYTES>>>(
        0, EI, HID, xh, HID, WegT, (long)EI*HID, nullptr, gateh, EI, off, ptok, nullptr, nullptr);
    mmh_k<5,true,true><<<dim3(EI/128, 32, NEXP), 256, MMH_SMEM_BYTES>>>(
        0, EI, HID, xh, HID, WeuT, (long)EI*HID, nullptr, acth, EI, off, ptok, nullptr, gateh);
    mmh_k<4,false,true><<<dim3(HID/128, 32, NEXP), 256, MMH_SMEM_BYTES>>>(
        0, HID, EI, acth, EI, WedT, (long)HID*EI, nullptr, downh, HID, off, nullptr, nullptr, nullptr);

    moe_reduce_k<<<T_TOK, 256>>>(downh, ppos, topw, hb, out);

    // --- shared expert ---
    mmh_k<4,false,false><<<dim3(SI/128, 32), 256, MMH_SMEM_BYTES>>>(
        T_TOK, SI, HID, xh, HID, WsgT, 0, nullptr, shgh, SI, nullptr, nullptr, nullptr, nullptr);
    mmh_k<5,false,false><<<dim3(SI/128, 32), 256, MMH_SMEM_BYTES>>>(
        T_TOK, SI, HID, xh, HID, WsuT, 0, nullptr, shh, SI, nullptr, nullptr, nullptr, shgh);
    shgate_k<<<T_TOK, 256>>>(xn, Wshg, sig);
    mmh_k<3,false,false><<<dim3(HID/128, 32), 256, MMH_SMEM_BYTES>>>(
        T_TOK, HID, SI, shh, SI, WsdT, 0, out, nullptr, HID, nullptr, nullptr, sig, nullptr);
}